// round 1
// baseline (speedup 1.0000x reference)
#include <cuda_runtime.h>
#include <math.h>
#include <stdint.h>

#define BATCH 4
#define SL    1024
#define DM    768
#define NH    12
#define DHD   64
#define FF    3072
#define NVOC  50257
#define MT    (BATCH*SL)   /* 4096 rows */
#define NLAY  2

#define S_C   512
#define S_C2  256
#define S_Q   128
#define S_R   128

#define GF_RESID 1
#define GF_GELU  2
#define GF_WPE   4

// ---------------- scratch (static device globals; no allocation allowed) ----
__device__ float g_h[MT*DM];                 // residual stream
__device__ float g_x[MT*DM];                 // LN output / emb
__device__ float g_qkv[MT*3*DM];             // qkv
__device__ float g_att[MT*DM];               // attention output (concat heads)
__device__ float g_fc[MT*FF];                // MLP hidden
__device__ float g_sc[(size_t)BATCH*NH*SL*SL]; // attention scores (201 MB)
__device__ int   g_tok[MT];                  // token id or -1 (pad)

// ---------------- token build (ragged concat bookkeeping) -------------------
__global__ void k_build_tok(const int* __restrict__ ctx, const int* __restrict__ qry,
                            const int* __restrict__ rsp, const int* __restrict__ c2,
                            const int* __restrict__ cl, const int* __restrict__ ql,
                            const int* __restrict__ rl, const int* __restrict__ c2l)
{
    int idx = blockIdx.x*blockDim.x + threadIdx.x;
    if (idx >= MT) return;
    int b = idx / SL, p = idx % SL;
    int l0 = cl[b], l1 = c2l[b], l2 = ql[b], l3 = rl[b];
    int tok = -1;
    if (p < l0)                    tok = ctx[b*S_C + p];
    else if (p < l0+l1)            tok = c2 [b*S_C2 + (p-l0)];
    else if (p < l0+l1+l2)         tok = qry[b*S_Q + (p-l0-l1)];
    else if (p < l0+l1+l2+l3)      tok = rsp[b*S_R + (p-l0-l1-l2)];
    g_tok[idx] = tok;
}

// ---------------- embedding gather into g_x ---------------------------------
__global__ void k_gather(const float* __restrict__ wte)
{
    int idx = blockIdx.x*blockDim.x + threadIdx.x;   // over MT * DM/4
    if (idx >= MT*(DM/4)) return;
    int row = idx / (DM/4), c4 = idx % (DM/4);
    int tok = g_tok[row];
    float4 v = make_float4(0.f,0.f,0.f,0.f);
    if (tok >= 0) v = ((const float4*)(wte + (size_t)tok*DM))[c4];
    ((float4*)(g_x + (size_t)row*DM))[c4] = v;
}

// ---------------- generic tiled SGEMM: C[M,N] = A[M,K] @ B (+epilogues) -----
// TB=false: B is [K,N] row-major.  TB=true: B is [N,K] row-major (B^T GEMM).
template<bool TB>
__global__ void __launch_bounds__(256)
k_gemm(const float* __restrict__ A, const float* __restrict__ Bm,
       const float* __restrict__ bias, const float* __restrict__ wpe,
       float* __restrict__ C, int M, int N, int K, int flags)
{
    __shared__ float As[8][128];
    __shared__ float Bs[8][128];
    int tid = threadIdx.x;
    int bm = blockIdx.y * 128;
    int bn = blockIdx.x * 128;
    int tm = (tid >> 4) * 8;     // 16x16 thread grid, 8x8 per thread
    int tn = (tid & 15) * 8;
    float acc[8][8];
    #pragma unroll
    for (int i=0;i<8;i++)
        #pragma unroll
        for (int j=0;j<8;j++) acc[i][j]=0.f;

    int arow = tid >> 1, acol = (tid & 1)*4;
    for (int k0 = 0; k0 < K; k0 += 8) {
        // A tile 128x8 (transposed into smem)
        float4 av = *(const float4*)(A + (size_t)(bm+arow)*K + k0 + acol);
        As[acol+0][arow]=av.x; As[acol+1][arow]=av.y;
        As[acol+2][arow]=av.z; As[acol+3][arow]=av.w;
        if (!TB) {
            int brow = tid >> 5, bcol = (tid & 31)*4;
            int n = bn + bcol;
            float4 bv = make_float4(0.f,0.f,0.f,0.f);
            if (n + 3 < N) bv = *(const float4*)(Bm + (size_t)(k0+brow)*N + n);
            else {
                float t0 = (n+0<N)?Bm[(size_t)(k0+brow)*N+n+0]:0.f;
                float t1 = (n+1<N)?Bm[(size_t)(k0+brow)*N+n+1]:0.f;
                float t2 = (n+2<N)?Bm[(size_t)(k0+brow)*N+n+2]:0.f;
                float t3 = (n+3<N)?Bm[(size_t)(k0+brow)*N+n+3]:0.f;
                bv = make_float4(t0,t1,t2,t3);
            }
            Bs[brow][bcol+0]=bv.x; Bs[brow][bcol+1]=bv.y;
            Bs[brow][bcol+2]=bv.z; Bs[brow][bcol+3]=bv.w;
        } else {
            int n = tid >> 1, kc = (tid & 1)*4;
            float4 bv = make_float4(0.f,0.f,0.f,0.f);
            if (bn + n < N) bv = *(const float4*)(Bm + (size_t)(bn+n)*K + k0 + kc);
            Bs[kc+0][n]=bv.x; Bs[kc+1][n]=bv.y;
            Bs[kc+2][n]=bv.z; Bs[kc+3][n]=bv.w;
        }
        __syncthreads();
        #pragma unroll
        for (int kk=0; kk<8; kk++) {
            float4 a0 = *(const float4*)&As[kk][tm];
            float4 a1 = *(const float4*)&As[kk][tm+4];
            float4 b0 = *(const float4*)&Bs[kk][tn];
            float4 b1 = *(const float4*)&Bs[kk][tn+4];
            float a[8] = {a0.x,a0.y,a0.z,a0.w,a1.x,a1.y,a1.z,a1.w};
            float bb[8] = {b0.x,b0.y,b0.z,b0.w,b1.x,b1.y,b1.z,b1.w};
            #pragma unroll
            for (int i=0;i<8;i++)
                #pragma unroll
                for (int j=0;j<8;j++) acc[i][j] += a[i]*bb[j];
        }
        __syncthreads();
    }

    #pragma unroll
    for (int i=0;i<8;i++) {
        int r = bm + tm + i;
        #pragma unroll
        for (int j=0;j<8;j++) {
            int c = bn + tn + j;
            if (c < N) {
                float v = acc[i][j];
                if (bias) v += bias[c];
                if (flags & GF_WPE) v += wpe[(size_t)(r & (SL-1))*DM + c];
                if (flags & GF_GELU) {
                    float u = v;
                    v = 0.5f*u*(1.f + tanhf(0.7978845608028654f*(u + 0.044715f*u*u*u)));
                }
                size_t o = (size_t)r*N + c;
                if (flags & GF_RESID) C[o] += v; else C[o] = v;
            }
        }
    }
}

// ---------------- LayerNorm: out = (x-mean)*rsqrt(var+eps)*g + b ------------
__global__ void __launch_bounds__(256)
k_ln(const float* __restrict__ in, const float* __restrict__ gm,
     const float* __restrict__ bt, float* __restrict__ out)
{
    __shared__ float red[256];
    int row = blockIdx.x, tid = threadIdx.x;
    const float* x = in + (size_t)row*DM;
    float v0 = x[tid], v1 = x[tid+256], v2 = x[tid+512];
    red[tid] = v0+v1+v2; __syncthreads();
    for (int o=128;o>0;o>>=1){ if(tid<o) red[tid]+=red[tid+o]; __syncthreads(); }
    float mean = red[0] * (1.f/768.f); __syncthreads();
    float d0=v0-mean, d1=v1-mean, d2=v2-mean;
    red[tid] = d0*d0+d1*d1+d2*d2; __syncthreads();
    for (int o=128;o>0;o>>=1){ if(tid<o) red[tid]+=red[tid+o]; __syncthreads(); }
    float inv = rsqrtf(red[0]*(1.f/768.f) + 1e-5f);
    out[(size_t)row*DM + tid    ] = d0*inv*gm[tid    ] + bt[tid    ];
    out[(size_t)row*DM + tid+256] = d1*inv*gm[tid+256] + bt[tid+256];
    out[(size_t)row*DM + tid+512] = d2*inv*gm[tid+512] + bt[tid+512];
}

// ---------------- attention scores: S = Q K^T / 8  (masked) -----------------
__global__ void __launch_bounds__(256)
k_scores(const int* __restrict__ cl, const int* __restrict__ c2l,
         const int* __restrict__ ql, const int* __restrict__ rl)
{
    int bh = blockIdx.z; int b = bh / NH, hh = bh % NH;
    int q0 = blockIdx.x*64, k0 = blockIdx.y*64;
    int tid = threadIdx.x;
    int tq = (tid >> 4)*4, tk = (tid & 15)*4;

    if (k0 > q0 + 63) {  // whole tile causally masked
        #pragma unroll
        for (int i=0;i<4;i++)
            #pragma unroll
            for (int j=0;j<4;j++)
                g_sc[((size_t)bh*SL + (q0+tq+i))*SL + (k0+tk+j)] = -1e9f;
        return;
    }
    int total = cl[b] + c2l[b] + ql[b] + rl[b];

    __shared__ float Qs[64][64];  // [d][q]
    __shared__ float Ks[64][64];  // [d][k]
    #pragma unroll
    for (int t=0;t<4;t++) {
        int e = tid + 256*t;
        int row = e >> 4, c4 = e & 15;
        float4 qv = *(const float4*)(g_qkv + (size_t)(b*SL + q0 + row)*2304 + hh*64 + c4*4);
        Qs[c4*4+0][row]=qv.x; Qs[c4*4+1][row]=qv.y; Qs[c4*4+2][row]=qv.z; Qs[c4*4+3][row]=qv.w;
        float4 kv = *(const float4*)(g_qkv + (size_t)(b*SL + k0 + row)*2304 + 768 + hh*64 + c4*4);
        Ks[c4*4+0][row]=kv.x; Ks[c4*4+1][row]=kv.y; Ks[c4*4+2][row]=kv.z; Ks[c4*4+3][row]=kv.w;
    }
    __syncthreads();

    float acc[4][4];
    #pragma unroll
    for (int i=0;i<4;i++)
        #pragma unroll
        for (int j=0;j<4;j++) acc[i][j]=0.f;
    #pragma unroll 8
    for (int dd=0; dd<64; dd++) {
        float4 a = *(const float4*)&Qs[dd][tq];
        float4 bb = *(const float4*)&Ks[dd][tk];
        float av[4]={a.x,a.y,a.z,a.w}, bv[4]={bb.x,bb.y,bb.z,bb.w};
        #pragma unroll
        for (int i=0;i<4;i++)
            #pragma unroll
            for (int j=0;j<4;j++) acc[i][j] += av[i]*bv[j];
    }
    #pragma unroll
    for (int i=0;i<4;i++) {
        int qi = q0+tq+i;
        #pragma unroll
        for (int j=0;j<4;j++) {
            int kj = k0+tk+j;
            bool allowed = (kj <= qi) && (kj < total);
            g_sc[((size_t)bh*SL + qi)*SL + kj] = allowed ? acc[i][j]*0.125f : -1e9f;
        }
    }
}

// ---------------- row softmax over 1024 ------------------------------------
__global__ void __launch_bounds__(256) k_softmax()
{
    __shared__ float red[256];
    size_t row = blockIdx.x;
    int tid = threadIdx.x;
    float* S = g_sc + row*SL;
    float4 v = ((float4*)S)[tid];
    float m = fmaxf(fmaxf(v.x,v.y), fmaxf(v.z,v.w));
    red[tid]=m; __syncthreads();
    for (int o=128;o>0;o>>=1){ if(tid<o) red[tid]=fmaxf(red[tid],red[tid+o]); __syncthreads(); }
    float mx = red[0]; __syncthreads();
    v.x = expf(v.x-mx); v.y = expf(v.y-mx); v.z = expf(v.z-mx); v.w = expf(v.w-mx);
    red[tid]=v.x+v.y+v.z+v.w; __syncthreads();
    for (int o=128;o>0;o>>=1){ if(tid<o) red[tid]+=red[tid+o]; __syncthreads(); }
    float inv = 1.f/red[0];
    v.x*=inv; v.y*=inv; v.z*=inv; v.w*=inv;
    ((float4*)S)[tid]=v;
}

// ---------------- AV: O = softmax(S) @ V  -> g_att (heads concat) ----------
__global__ void __launch_bounds__(256) k_av()
{
    int bh = blockIdx.y; int b = bh / NH, hh = bh % NH;
    int q0 = blockIdx.x*64;
    int tid = threadIdx.x;
    int tq = (tid >> 4)*4, td = (tid & 15)*4;
    __shared__ float Ss[64][64];  // [q][k]
    __shared__ float Vs[64][64];  // [k][d]
    float acc[4][4];
    #pragma unroll
    for (int i=0;i<4;i++)
        #pragma unroll
        for (int j=0;j<4;j++) acc[i][j]=0.f;

    for (int k0 = 0; k0 <= q0; k0 += 64) {   // keys beyond q-tile are exactly 0 post-softmax
        #pragma unroll
        for (int t=0;t<4;t++) {
            int e = tid + 256*t;
            int row = e >> 4, c4 = e & 15;
            float4 sv = *(const float4*)(g_sc + ((size_t)bh*SL + q0+row)*SL + k0 + c4*4);
            *(float4*)&Ss[row][c4*4] = sv;
            float4 vv = *(const float4*)(g_qkv + (size_t)(b*SL + k0 + row)*2304 + 1536 + hh*64 + c4*4);
            *(float4*)&Vs[row][c4*4] = vv;
        }
        __syncthreads();
        #pragma unroll 8
        for (int kk=0; kk<64; kk++) {
            float a0=Ss[tq+0][kk], a1=Ss[tq+1][kk], a2=Ss[tq+2][kk], a3=Ss[tq+3][kk];
            float4 bb = *(const float4*)&Vs[kk][td];
            float bv[4]={bb.x,bb.y,bb.z,bb.w};
            #pragma unroll
            for (int j=0;j<4;j++) {
                acc[0][j] += a0*bv[j]; acc[1][j] += a1*bv[j];
                acc[2][j] += a2*bv[j]; acc[3][j] += a3*bv[j];
            }
        }
        __syncthreads();
    }
    #pragma unroll
    for (int i=0;i<4;i++)
        #pragma unroll
        for (int j=0;j<4;j++)
            g_att[(size_t)(b*SL + q0+tq+i)*DM + hh*64 + td + j] = acc[i][j];
}

// ---------------- launch ----------------------------------------------------
extern "C" void kernel_launch(void* const* d_in, const int* in_sizes, int n_in,
                              void* d_out, int out_size)
{
    const int*   ctx  = (const int*)  d_in[0];
    const int*   qry  = (const int*)  d_in[1];
    const int*   rsp  = (const int*)  d_in[2];
    const int*   c2   = (const int*)  d_in[3];
    const int*   cl   = (const int*)  d_in[4];
    const int*   ql   = (const int*)  d_in[5];
    const int*   rl   = (const int*)  d_in[6];
    const int*   c2l  = (const int*)  d_in[7];
    const float* wte  = (const float*)d_in[8];
    const float* wpe  = (const float*)d_in[9];
    const float* ln1g = (const float*)d_in[10];
    const float* ln1b = (const float*)d_in[11];
    const float* wqkv = (const float*)d_in[12];
    const float* bqkv = (const float*)d_in[13];
    const float* wo   = (const float*)d_in[14];
    const float* bo   = (const float*)d_in[15];
    const float* ln2g = (const float*)d_in[16];
    const float* ln2b = (const float*)d_in[17];
    const float* wfc  = (const float*)d_in[18];
    const float* bfc  = (const float*)d_in[19];
    const float* wpr  = (const float*)d_in[20];
    const float* bpr  = (const float*)d_in[21];
    const float* lnfg = (const float*)d_in[22];
    const float* lnfb = (const float*)d_in[23];
    const float* llw  = (const float*)d_in[24];
    const float* llb  = (const float*)d_in[25];
    float* out = (float*)d_out;

    float *ph, *px, *pqkv, *patt, *pfc;
    cudaGetSymbolAddress((void**)&ph,   g_h);
    cudaGetSymbolAddress((void**)&px,   g_x);
    cudaGetSymbolAddress((void**)&pqkv, g_qkv);
    cudaGetSymbolAddress((void**)&patt, g_att);
    cudaGetSymbolAddress((void**)&pfc,  g_fc);

    k_build_tok<<<(MT+255)/256, 256>>>(ctx, qry, rsp, c2, cl, ql, rl, c2l);
    k_gather<<<(MT*(DM/4)+255)/256, 256>>>(wte);

    // h = emb @ ll_w^T + ll_b + wpe
    k_gemm<true><<<dim3(DM/128, MT/128), 256>>>(px, llw, llb, wpe, ph, MT, DM, DM, GF_WPE);

    for (int l = 0; l < NLAY; l++) {
        k_ln<<<MT, 256>>>(ph, ln1g + l*DM, ln1b + l*DM, px);
        k_gemm<false><<<dim3((3*DM)/128, MT/128), 256>>>(px, wqkv + (size_t)l*DM*3*DM,
                                                         bqkv + l*3*DM, nullptr, pqkv,
                                                         MT, 3*DM, DM, 0);
        k_scores<<<dim3(SL/64, SL/64, BATCH*NH), 256>>>(cl, c2l, ql, rl);
        k_softmax<<<BATCH*NH*SL, 256>>>();
        k_av<<<dim3(SL/64, BATCH*NH), 256>>>();
        k_gemm<false><<<dim3(DM/128, MT/128), 256>>>(patt, wo + (size_t)l*DM*DM,
                                                     bo + l*DM, nullptr, ph,
                                                     MT, DM, DM, GF_RESID);
        k_ln<<<MT, 256>>>(ph, ln2g + l*DM, ln2b + l*DM, px);
        k_gemm<false><<<dim3(FF/128, MT/128), 256>>>(px, wfc + (size_t)l*DM*FF,
                                                     bfc + l*FF, nullptr, pfc,
                                                     MT, FF, DM, GF_GELU);
        k_gemm<false><<<dim3(DM/128, MT/128), 256>>>(pfc, wpr + (size_t)l*FF*DM,
                                                     bpr + l*DM, nullptr, ph,
                                                     MT, DM, FF, GF_RESID);
    }

    k_ln<<<MT, 256>>>(ph, lnfg, lnfb, px);

    // logits = x @ wte^T  [4096, 50257]
    k_gemm<true><<<dim3((NVOC+127)/128, MT/128), 256>>>(px, wte, nullptr, nullptr, out,
                                                        MT, NVOC, DM, 0);
}

// round 3
// speedup vs baseline: 1.6779x; 1.6779x over previous
#include <cuda_runtime.h>
#include <cuda_bf16.h>
#include <math.h>
#include <stdint.h>

#define BATCH 4
#define SL    1024
#define DM    768
#define NH    12
#define FF    3072
#define NVOC  50257
#define NVP   50432            /* padded vocab: 394*128 */
#define MT    (BATCH*SL)       /* 4096 */
#define NLAY  2

#define S_C   512
#define S_C2  256
#define S_Q   128
#define S_R   128

#define GF_RESID 1
#define GF_GELU  2
#define GF_WPE   4

typedef __nv_bfloat16 bf16;

// ---------------- scratch ---------------------------------------------------
__device__ float g_h[MT*DM];                    // residual stream fp32
__device__ float g_qkv[MT*3*DM];                // qkv fp32
__device__ float g_sc[(size_t)BATCH*NH*SL*SL];  // attention scores
__device__ int   g_tok[MT];

__device__ bf16 g_xh[MT*DM],  g_xl[MT*DM];      // LN / emb output split
__device__ bf16 g_ah[MT*DM],  g_al[MT*DM];      // attention output split
__device__ bf16 g_fh[(size_t)MT*FF], g_fl[(size_t)MT*FF];   // MLP hidden split
__device__ bf16 g_wth[(size_t)NVP*DM], g_wtl[(size_t)NVP*DM]; // wte split (padded)
__device__ bf16 g_qwh[NLAY*3*DM*DM], g_qwl[NLAY*3*DM*DM];   // wqkv^T split
__device__ bf16 g_owh[NLAY*DM*DM],   g_owl[NLAY*DM*DM];     // wo^T split
__device__ bf16 g_fwh[NLAY*FF*DM],   g_fwl[NLAY*FF*DM];     // wfc^T split
__device__ bf16 g_pwh[NLAY*DM*FF],   g_pwl[NLAY*DM*FF];     // wpr^T split
__device__ bf16 g_lwh[DM*DM],        g_lwl[DM*DM];          // ll_w split ([N,K] already)

// ---------------- asm helpers (base sm_103 ISA only) ------------------------
__device__ __forceinline__ uint32_t smem_u32(const void* p){
    uint32_t a;
    asm("{ .reg .u64 t; cvta.to.shared.u64 t, %1; cvt.u32.u64 %0, t; }" : "=r"(a) : "l"(p));
    return a;
}
__device__ __forceinline__ void cpa16(uint32_t d, const void* s){
    asm volatile("cp.async.cg.shared.global [%0], [%1], 16;" :: "r"(d), "l"(s));
}
#define CP_COMMIT() asm volatile("cp.async.commit_group;" ::: "memory")
#define CP_WAIT(n)  asm volatile("cp.async.wait_group %0;" :: "n"(n) : "memory")

#define LDSM4(r0,r1,r2,r3,a) \
    asm volatile("ldmatrix.sync.aligned.m8n8.x4.shared.b16 {%0,%1,%2,%3}, [%4];" \
        : "=r"(r0),"=r"(r1),"=r"(r2),"=r"(r3) : "r"(a))

#define MMA16816(d, a, b0, b1) \
    asm volatile("mma.sync.aligned.m16n8k16.row.col.f32.bf16.bf16.f32 " \
        "{%0,%1,%2,%3},{%4,%5,%6,%7},{%8,%9},{%0,%1,%2,%3};" \
        : "+f"((d)[0]),"+f"((d)[1]),"+f"((d)[2]),"+f"((d)[3]) \
        : "r"((a)[0]),"r"((a)[1]),"r"((a)[2]),"r"((a)[3]),"r"(b0),"r"(b1))

// ---------------- small kernels ---------------------------------------------
__global__ void k_build_tok(const int* __restrict__ ctx, const int* __restrict__ qry,
                            const int* __restrict__ rsp, const int* __restrict__ c2,
                            const int* __restrict__ cl, const int* __restrict__ ql,
                            const int* __restrict__ rl, const int* __restrict__ c2l)
{
    int idx = blockIdx.x*blockDim.x + threadIdx.x;
    if (idx >= MT) return;
    int b = idx / SL, p = idx % SL;
    int l0 = cl[b], l1 = c2l[b], l2 = ql[b], l3 = rl[b];
    int tok = -1;
    if (p < l0)               tok = ctx[b*S_C + p];
    else if (p < l0+l1)       tok = c2 [b*S_C2 + (p-l0)];
    else if (p < l0+l1+l2)    tok = qry[b*S_Q + (p-l0-l1)];
    else if (p < l0+l1+l2+l3) tok = rsp[b*S_R + (p-l0-l1-l2)];
    g_tok[idx] = tok;
}

__global__ void k_gather(const float* __restrict__ wte)
{
    int idx = blockIdx.x*blockDim.x + threadIdx.x;
    if (idx >= MT*(DM/4)) return;
    int row = idx / (DM/4), c4 = idx % (DM/4);
    int tok = g_tok[row];
    float4 v = make_float4(0.f,0.f,0.f,0.f);
    if (tok >= 0) v = ((const float4*)(wte + (size_t)tok*DM))[c4];
    float vv[4] = {v.x, v.y, v.z, v.w};
    size_t o = (size_t)row*DM + c4*4;
    #pragma unroll
    for (int t=0;t<4;t++){
        bf16 h = __float2bfloat16(vv[t]);
        g_xh[o+t] = h;
        g_xl[o+t] = __float2bfloat16(vv[t] - __bfloat162float(h));
    }
}

__global__ void k_cvt(const float* __restrict__ in, bf16* __restrict__ oh,
                      bf16* __restrict__ ol, int nin, int ntot)
{
    int i = blockIdx.x*blockDim.x + threadIdx.x;
    if (i >= ntot) return;
    float v = (i < nin) ? in[i] : 0.f;
    bf16 h = __float2bfloat16(v);
    oh[i] = h;
    ol[i] = __float2bfloat16(v - __bfloat162float(h));
}

// transpose fp32 [Kd, Nd] -> split bf16 [Nd, Kd]
__global__ void k_cvtT(const float* __restrict__ in, bf16* __restrict__ oh,
                       bf16* __restrict__ ol, int Kd, int Nd)
{
    __shared__ float t[32][33];
    int kb = blockIdx.y*32, nb = blockIdx.x*32;
    int tx = threadIdx.x, ty = threadIdx.y;  // 32 x 8
    #pragma unroll
    for (int i=0;i<32;i+=8)
        t[ty+i][tx] = in[(size_t)(kb+ty+i)*Nd + nb+tx];
    __syncthreads();
    #pragma unroll
    for (int i=0;i<32;i+=8){
        float v = t[tx][ty+i];
        bf16 h = __float2bfloat16(v);
        size_t o = (size_t)(nb+ty+i)*Kd + kb+tx;
        oh[o] = h;
        ol[o] = __float2bfloat16(v - __bfloat162float(h));
    }
}

// LayerNorm fp32 in -> split bf16 out
__global__ void __launch_bounds__(256)
k_ln(const float* __restrict__ in, const float* __restrict__ gm,
     const float* __restrict__ bt, bf16* __restrict__ oh, bf16* __restrict__ ol)
{
    __shared__ float red[256];
    int row = blockIdx.x, tid = threadIdx.x;
    const float* x = in + (size_t)row*DM;
    float v0 = x[tid], v1 = x[tid+256], v2 = x[tid+512];
    red[tid] = v0+v1+v2; __syncthreads();
    for (int o=128;o>0;o>>=1){ if(tid<o) red[tid]+=red[tid+o]; __syncthreads(); }
    float mean = red[0] * (1.f/768.f); __syncthreads();
    float d0=v0-mean, d1=v1-mean, d2=v2-mean;
    red[tid] = d0*d0+d1*d1+d2*d2; __syncthreads();
    for (int o=128;o>0;o>>=1){ if(tid<o) red[tid]+=red[tid+o]; __syncthreads(); }
    float inv = rsqrtf(red[0]*(1.f/768.f) + 1e-5f);
    #pragma unroll
    for (int t=0;t<3;t++){
        int c = tid + t*256;
        float d = (t==0)?d0:((t==1)?d1:d2);
        float y = d*inv*gm[c] + bt[c];
        bf16 h = __float2bfloat16(y);
        size_t o = (size_t)row*DM + c;
        oh[o] = h;
        ol[o] = __float2bfloat16(y - __bfloat162float(h));
    }
}

// ---------------- attention (fp32) ------------------------------------------
__global__ void __launch_bounds__(256)
k_scores(const int* __restrict__ cl, const int* __restrict__ c2l,
         const int* __restrict__ ql, const int* __restrict__ rl)
{
    int bh = blockIdx.z; int b = bh / NH, hh = bh % NH;
    int q0 = blockIdx.x*64, k0 = blockIdx.y*64;
    int tid = threadIdx.x;
    int tq = (tid >> 4)*4, tk = (tid & 15)*4;

    if (k0 > q0 + 63) {
        #pragma unroll
        for (int i=0;i<4;i++)
            #pragma unroll
            for (int j=0;j<4;j++)
                g_sc[((size_t)bh*SL + (q0+tq+i))*SL + (k0+tk+j)] = -1e9f;
        return;
    }
    int total = cl[b] + c2l[b] + ql[b] + rl[b];

    __shared__ float Qs[64][64];
    __shared__ float Ks[64][64];
    #pragma unroll
    for (int t=0;t<4;t++) {
        int e = tid + 256*t;
        int row = e >> 4, c4 = e & 15;
        float4 qv = *(const float4*)(g_qkv + (size_t)(b*SL + q0 + row)*2304 + hh*64 + c4*4);
        Qs[c4*4+0][row]=qv.x; Qs[c4*4+1][row]=qv.y; Qs[c4*4+2][row]=qv.z; Qs[c4*4+3][row]=qv.w;
        float4 kv = *(const float4*)(g_qkv + (size_t)(b*SL + k0 + row)*2304 + 768 + hh*64 + c4*4);
        Ks[c4*4+0][row]=kv.x; Ks[c4*4+1][row]=kv.y; Ks[c4*4+2][row]=kv.z; Ks[c4*4+3][row]=kv.w;
    }
    __syncthreads();

    float acc[4][4];
    #pragma unroll
    for (int i=0;i<4;i++)
        #pragma unroll
        for (int j=0;j<4;j++) acc[i][j]=0.f;
    #pragma unroll 8
    for (int dd=0; dd<64; dd++) {
        float4 a = *(const float4*)&Qs[dd][tq];
        float4 bb = *(const float4*)&Ks[dd][tk];
        float av[4]={a.x,a.y,a.z,a.w}, bv[4]={bb.x,bb.y,bb.z,bb.w};
        #pragma unroll
        for (int i=0;i<4;i++)
            #pragma unroll
            for (int j=0;j<4;j++) acc[i][j] += av[i]*bv[j];
    }
    #pragma unroll
    for (int i=0;i<4;i++) {
        int qi = q0+tq+i;
        #pragma unroll
        for (int j=0;j<4;j++) {
            int kj = k0+tk+j;
            bool allowed = (kj <= qi) && (kj < total);
            g_sc[((size_t)bh*SL + qi)*SL + kj] = allowed ? acc[i][j]*0.125f : -1e9f;
        }
    }
}

__global__ void __launch_bounds__(256) k_softmax()
{
    __shared__ float red[256];
    size_t row = blockIdx.x;
    int tid = threadIdx.x;
    float* S = g_sc + row*SL;
    float4 v = ((float4*)S)[tid];
    float m = fmaxf(fmaxf(v.x,v.y), fmaxf(v.z,v.w));
    red[tid]=m; __syncthreads();
    for (int o=128;o>0;o>>=1){ if(tid<o) red[tid]=fmaxf(red[tid],red[tid+o]); __syncthreads(); }
    float mx = red[0]; __syncthreads();
    v.x = expf(v.x-mx); v.y = expf(v.y-mx); v.z = expf(v.z-mx); v.w = expf(v.w-mx);
    red[tid]=v.x+v.y+v.z+v.w; __syncthreads();
    for (int o=128;o>0;o>>=1){ if(tid<o) red[tid]+=red[tid+o]; __syncthreads(); }
    float inv = 1.f/red[0];
    v.x*=inv; v.y*=inv; v.z*=inv; v.w*=inv;
    ((float4*)S)[tid]=v;
}

__global__ void __launch_bounds__(256) k_av()
{
    int bh = blockIdx.y; int b = bh / NH, hh = bh % NH;
    int q0 = blockIdx.x*64;
    int tid = threadIdx.x;
    int tq = (tid >> 4)*4, td = (tid & 15)*4;
    __shared__ float Ss[64][64];
    __shared__ float Vs[64][64];
    float acc[4][4];
    #pragma unroll
    for (int i=0;i<4;i++)
        #pragma unroll
        for (int j=0;j<4;j++) acc[i][j]=0.f;

    for (int k0 = 0; k0 <= q0; k0 += 64) {
        #pragma unroll
        for (int t=0;t<4;t++) {
            int e = tid + 256*t;
            int row = e >> 4, c4 = e & 15;
            float4 sv = *(const float4*)(g_sc + ((size_t)bh*SL + q0+row)*SL + k0 + c4*4);
            *(float4*)&Ss[row][c4*4] = sv;
            float4 vv = *(const float4*)(g_qkv + (size_t)(b*SL + k0 + row)*2304 + 1536 + hh*64 + c4*4);
            *(float4*)&Vs[row][c4*4] = vv;
        }
        __syncthreads();
        #pragma unroll 8
        for (int kk=0; kk<64; kk++) {
            float a0=Ss[tq+0][kk], a1=Ss[tq+1][kk], a2=Ss[tq+2][kk], a3=Ss[tq+3][kk];
            float4 bb = *(const float4*)&Vs[kk][td];
            float bv[4]={bb.x,bb.y,bb.z,bb.w};
            #pragma unroll
            for (int j=0;j<4;j++) {
                acc[0][j] += a0*bv[j]; acc[1][j] += a1*bv[j];
                acc[2][j] += a2*bv[j]; acc[3][j] += a3*bv[j];
            }
        }
        __syncthreads();
    }
    #pragma unroll
    for (int i=0;i<4;i++)
        #pragma unroll
        for (int j=0;j<4;j++){
            float v = acc[i][j];
            bf16 h = __float2bfloat16(v);
            size_t o = (size_t)(b*SL + q0+tq+i)*DM + hh*64 + td + j;
            g_ah[o] = h;
            g_al[o] = __float2bfloat16(v - __bfloat162float(h));
        }
}

// ---------------- split-bf16 mma.sync GEMM ----------------------------------
// D[M,N] = A[M,K] @ B[N,K]^T, 3 passes: Ah*Bh + Ah*Bl + Al*Bh (fp32 accum).
// 128x128 CTA tile, 8 warps (2x4), warp tile 64x32, m16n8k16 HMMA.
// K-chunk 16, double-buffered cp.async, 48KB static smem.
#define KC      16
#define ROWB    48              /* padded row stride bytes (16 bf16 + 8 pad) */
#define MATB    (128*ROWB)      /* 6144 bytes per matrix tile */
#define STG     (4*MATB)        /* Ah Al Bh Bl = 24576 */
// stage s at s*STG; Ah@0 Al@MATB Bh@2*MATB Bl@3*MATB

__global__ void __launch_bounds__(256,1)
k_tgemm(const bf16* __restrict__ aH, const bf16* __restrict__ aL,
        const bf16* __restrict__ bH, const bf16* __restrict__ bL,
        const float* __restrict__ bias, const float* __restrict__ wpe,
        float* __restrict__ C, bf16* __restrict__ cH, bf16* __restrict__ cL,
        int K, int Nvalid, int flags)
{
    __shared__ __align__(128) unsigned char smem_buf[2*STG];  // 49152 = 48KB
    uint32_t sb = smem_u32(smem_buf);
    int tid = threadIdx.x;
    int bm = blockIdx.x * 128;
    int bn = blockIdx.y * 128;

    int w = tid >> 5, lane = tid & 31;
    int wm = w >> 2, wn = w & 3;                 // 2 x 4 warp grid

    float acc[4][4][4];
    #pragma unroll
    for (int mt=0;mt<4;mt++)
        #pragma unroll
        for (int n8=0;n8<4;n8++)
            #pragma unroll
            for (int r=0;r<4;r++) acc[mt][n8][r]=0.f;

    // per-thread load slots: row = tid>>1, half = tid&1 (16B chunks)
    int lrow = tid >> 1, lhalf = tid & 1;
    uint32_t ldst = lrow*ROWB + lhalf*16;

    int nk = K / KC;

    // prologue: load stage 0
    {
        size_t ga = (size_t)(bm + lrow)*K + lhalf*8;
        size_t gb = (size_t)(bn + lrow)*K + lhalf*8;
        cpa16(sb + 0*MATB + ldst, aH + ga);
        cpa16(sb + 1*MATB + ldst, aL + ga);
        cpa16(sb + 2*MATB + ldst, bH + gb);
        cpa16(sb + 3*MATB + ldst, bL + gb);
        CP_COMMIT();
    }

    for (int i = 0; i < nk; i++) {
        uint32_t st = sb + (i & 1)*STG;
        if (i + 1 < nk) {
            uint32_t st2 = sb + ((i+1) & 1)*STG;
            int k0 = (i+1)*KC;
            size_t ga = (size_t)(bm + lrow)*K + k0 + lhalf*8;
            size_t gb = (size_t)(bn + lrow)*K + k0 + lhalf*8;
            cpa16(st2 + 0*MATB + ldst, aH + ga);
            cpa16(st2 + 1*MATB + ldst, aL + ga);
            cpa16(st2 + 2*MATB + ldst, bH + gb);
            cpa16(st2 + 3*MATB + ldst, bL + gb);
            CP_COMMIT();
            CP_WAIT(1);
        } else {
            CP_WAIT(0);
        }
        __syncthreads();

        // ldmatrix fragments
        uint32_t ah[4][4], al[4][4], bh[2][4], bl[2][4];
        int rr = lane & 15, hf = lane >> 4;
        #pragma unroll
        for (int mt=0;mt<4;mt++) {
            uint32_t ra = st + (wm*64 + mt*16 + rr)*ROWB + hf*16;
            LDSM4(ah[mt][0],ah[mt][1],ah[mt][2],ah[mt][3], ra);
            LDSM4(al[mt][0],al[mt][1],al[mt][2],al[mt][3], ra + MATB);
        }
        #pragma unroll
        for (int nt=0;nt<2;nt++) {
            uint32_t rb = st + 2*MATB + (wn*32 + nt*16 + rr)*ROWB + hf*16;
            LDSM4(bh[nt][0],bh[nt][1],bh[nt][2],bh[nt][3], rb);
            LDSM4(bl[nt][0],bl[nt][1],bl[nt][2],bl[nt][3], rb + MATB);
        }

        #pragma unroll
        for (int mt=0;mt<4;mt++) {
            #pragma unroll
            for (int n8=0;n8<4;n8++) {
                int nt = n8 >> 1, p = n8 & 1;
                MMA16816(acc[mt][n8], ah[mt], bh[nt][p], bh[nt][p+2]);
                MMA16816(acc[mt][n8], ah[mt], bl[nt][p], bl[nt][p+2]);
                MMA16816(acc[mt][n8], al[mt], bh[nt][p], bh[nt][p+2]);
            }
        }
        __syncthreads();
    }

    // epilogue: lane holds (row = mt*16 + lane/4 [+8], col = n8*8 + (lane%4)*2 [+1])
    int r0b = bm + wm*64 + (lane >> 2);
    int c0b = bn + wn*32 + (lane & 3)*2;
    #pragma unroll
    for (int mt=0;mt<4;mt++) {
        #pragma unroll
        for (int n8=0;n8<4;n8++) {
            #pragma unroll
            for (int half=0; half<2; half++) {
                int r = r0b + mt*16 + half*8;
                #pragma unroll
                for (int e=0; e<2; e++) {
                    int c = c0b + n8*8 + e;
                    if (c >= Nvalid) continue;
                    float v = acc[mt][n8][half*2 + e];
                    if (bias) v += bias[c];
                    if (flags & GF_WPE) v += wpe[(size_t)(r & (SL-1))*DM + c];
                    size_t o = (size_t)r*Nvalid + c;
                    if (flags & GF_GELU) {
                        float u = v;
                        v = 0.5f*u*(1.f + tanhf(0.7978845608028654f*(u + 0.044715f*u*u*u)));
                        bf16 h = __float2bfloat16(v);
                        cH[o] = h;
                        cL[o] = __float2bfloat16(v - __bfloat162float(h));
                    } else if (flags & GF_RESID) {
                        C[o] += v;
                    } else {
                        C[o] = v;
                    }
                }
            }
        }
    }
}

// ---------------- launch ----------------------------------------------------
extern "C" void kernel_launch(void* const* d_in, const int* in_sizes, int n_in,
                              void* d_out, int out_size)
{
    const int*   ctx  = (const int*)  d_in[0];
    const int*   qry  = (const int*)  d_in[1];
    const int*   rsp  = (const int*)  d_in[2];
    const int*   c2   = (const int*)  d_in[3];
    const int*   cl   = (const int*)  d_in[4];
    const int*   ql   = (const int*)  d_in[5];
    const int*   rl   = (const int*)  d_in[6];
    const int*   c2l  = (const int*)  d_in[7];
    const float* wte  = (const float*)d_in[8];
    const float* wpe  = (const float*)d_in[9];
    const float* ln1g = (const float*)d_in[10];
    const float* ln1b = (const float*)d_in[11];
    const float* wqkv = (const float*)d_in[12];
    const float* bqkv = (const float*)d_in[13];
    const float* wo   = (const float*)d_in[14];
    const float* bo   = (const float*)d_in[15];
    const float* ln2g = (const float*)d_in[16];
    const float* ln2b = (const float*)d_in[17];
    const float* wfc  = (const float*)d_in[18];
    const float* bfc  = (const float*)d_in[19];
    const float* wpr  = (const float*)d_in[20];
    const float* bpr  = (const float*)d_in[21];
    const float* lnfg = (const float*)d_in[22];
    const float* lnfb = (const float*)d_in[23];
    const float* llw  = (const float*)d_in[24];
    const float* llb  = (const float*)d_in[25];
    float* out = (float*)d_out;

    float *ph, *pqkv;
    bf16 *xh, *xl, *ah, *al, *fh, *fl, *wth, *wtl;
    bf16 *qwh, *qwl, *owh, *owl, *fwh, *fwl, *pwh, *pwl, *lwh, *lwl;
    cudaGetSymbolAddress((void**)&ph,   g_h);
    cudaGetSymbolAddress((void**)&pqkv, g_qkv);
    cudaGetSymbolAddress((void**)&xh,  g_xh);  cudaGetSymbolAddress((void**)&xl,  g_xl);
    cudaGetSymbolAddress((void**)&ah,  g_ah);  cudaGetSymbolAddress((void**)&al,  g_al);
    cudaGetSymbolAddress((void**)&fh,  g_fh);  cudaGetSymbolAddress((void**)&fl,  g_fl);
    cudaGetSymbolAddress((void**)&wth, g_wth); cudaGetSymbolAddress((void**)&wtl, g_wtl);
    cudaGetSymbolAddress((void**)&qwh, g_qwh); cudaGetSymbolAddress((void**)&qwl, g_qwl);
    cudaGetSymbolAddress((void**)&owh, g_owh); cudaGetSymbolAddress((void**)&owl, g_owl);
    cudaGetSymbolAddress((void**)&fwh, g_fwh); cudaGetSymbolAddress((void**)&fwl, g_fwl);
    cudaGetSymbolAddress((void**)&pwh, g_pwh); cudaGetSymbolAddress((void**)&pwl, g_pwl);
    cudaGetSymbolAddress((void**)&lwh, g_lwh); cudaGetSymbolAddress((void**)&lwl, g_lwl);

    // ---- weight conversions (split bf16; transpose where B is [K,N]) ----
    k_cvt<<<(NVP*DM+255)/256, 256>>>(wte, wth, wtl, NVOC*DM, NVP*DM);
    k_cvt<<<(DM*DM+255)/256, 256>>>(llw, lwh, lwl, DM*DM, DM*DM);
    for (int l = 0; l < NLAY; l++) {
        k_cvtT<<<dim3(3*DM/32, DM/32), dim3(32,8)>>>(wqkv + (size_t)l*DM*3*DM,
                                                     qwh + (size_t)l*3*DM*DM, qwl + (size_t)l*3*DM*DM, DM, 3*DM);
        k_cvtT<<<dim3(DM/32, DM/32), dim3(32,8)>>>(wo + (size_t)l*DM*DM,
                                                   owh + (size_t)l*DM*DM, owl + (size_t)l*DM*DM, DM, DM);
        k_cvtT<<<dim3(FF/32, DM/32), dim3(32,8)>>>(wfc + (size_t)l*DM*FF,
                                                   fwh + (size_t)l*FF*DM, fwl + (size_t)l*FF*DM, DM, FF);
        k_cvtT<<<dim3(DM/32, FF/32), dim3(32,8)>>>(wpr + (size_t)l*FF*DM,
                                                   pwh + (size_t)l*DM*FF, pwl + (size_t)l*DM*FF, FF, DM);
    }

    // ---- embeddings ----
    k_build_tok<<<(MT+255)/256, 256>>>(ctx, qry, rsp, c2, cl, ql, rl, c2l);
    k_gather<<<(MT*(DM/4)+255)/256, 256>>>(wte);

    // h = emb @ ll_w^T + ll_b + wpe
    k_tgemm<<<dim3(MT/128, DM/128), 256>>>(xh, xl, lwh, lwl, llb, wpe,
                                           ph, nullptr, nullptr, DM, DM, GF_WPE);

    for (int l = 0; l < NLAY; l++) {
        k_ln<<<MT, 256>>>(ph, ln1g + l*DM, ln1b + l*DM, xh, xl);
        k_tgemm<<<dim3(MT/128, 3*DM/128), 256>>>(xh, xl,
            qwh + (size_t)l*3*DM*DM, qwl + (size_t)l*3*DM*DM, bqkv + l*3*DM, nullptr,
            pqkv, nullptr, nullptr, DM, 3*DM, 0);
        k_scores<<<dim3(SL/64, SL/64, BATCH*NH), 256>>>(cl, c2l, ql, rl);
        k_softmax<<<BATCH*NH*SL, 256>>>();
        k_av<<<dim3(SL/64, BATCH*NH), 256>>>();
        k_tgemm<<<dim3(MT/128, DM/128), 256>>>(ah, al,
            owh + (size_t)l*DM*DM, owl + (size_t)l*DM*DM, bo + l*DM, nullptr,
            ph, nullptr, nullptr, DM, DM, GF_RESID);
        k_ln<<<MT, 256>>>(ph, ln2g + l*DM, ln2b + l*DM, xh, xl);
        k_tgemm<<<dim3(MT/128, FF/128), 256>>>(xh, xl,
            fwh + (size_t)l*FF*DM, fwl + (size_t)l*FF*DM, bfc + l*FF, nullptr,
            nullptr, fh, fl, DM, FF, GF_GELU);
        k_tgemm<<<dim3(MT/128, DM/128), 256>>>(fh, fl,
            pwh + (size_t)l*DM*FF, pwl + (size_t)l*DM*FF, bpr + l*DM, nullptr,
            ph, nullptr, nullptr, FF, DM, GF_RESID);
    }

    k_ln<<<MT, 256>>>(ph, lnfg, lnfb, xh, xl);

    // logits = x @ wte^T
    k_tgemm<<<dim3(MT/128, NVP/128), 256>>>(xh, xl, wth, wtl, nullptr, nullptr,
                                            out, nullptr, nullptr, DM, NVOC, 0);
}

// round 4
// speedup vs baseline: 2.0538x; 1.2241x over previous
#include <cuda_runtime.h>
#include <cuda_bf16.h>
#include <math.h>
#include <stdint.h>

#define BATCH 4
#define SL    1024
#define DM    768
#define NH    12
#define FF    3072
#define NVOC  50257
#define NVP   50432            /* padded vocab: 197*256 */
#define MT    (BATCH*SL)       /* 4096 */
#define NLAY  2

#define S_C   512
#define S_C2  256
#define S_Q   128
#define S_R   128

#define GF_RESID 1
#define GF_GELU  2
#define GF_WPE   4

typedef __nv_bfloat16 bf16;

// ---------------- scratch ---------------------------------------------------
__device__ float g_h[MT*DM];
__device__ float g_qkv[MT*3*DM];
__device__ float g_sc[(size_t)BATCH*NH*SL*SL];
__device__ int   g_tok[MT];

__device__ bf16 g_xh[MT*DM],  g_xl[MT*DM];
__device__ bf16 g_ah[MT*DM],  g_al[MT*DM];
__device__ bf16 g_fh[(size_t)MT*FF], g_fl[(size_t)MT*FF];
__device__ bf16 g_wth[(size_t)NVP*DM], g_wtl[(size_t)NVP*DM];
__device__ bf16 g_qwh[NLAY*3*DM*DM], g_qwl[NLAY*3*DM*DM];
__device__ bf16 g_owh[NLAY*DM*DM],   g_owl[NLAY*DM*DM];
__device__ bf16 g_fwh[NLAY*FF*DM],   g_fwl[NLAY*FF*DM];
__device__ bf16 g_pwh[NLAY*DM*FF],   g_pwl[NLAY*DM*FF];
__device__ bf16 g_lwh[DM*DM],        g_lwl[DM*DM];

// ---------------- asm helpers -----------------------------------------------
__device__ __forceinline__ uint32_t smem_u32(const void* p){
    uint32_t a;
    asm("{ .reg .u64 t; cvta.to.shared.u64 t, %1; cvt.u32.u64 %0, t; }" : "=r"(a) : "l"(p));
    return a;
}
__device__ __forceinline__ void cpa16(uint32_t d, const void* s){
    asm volatile("cp.async.cg.shared.global [%0], [%1], 16;" :: "r"(d), "l"(s));
}
#define CP_COMMIT() asm volatile("cp.async.commit_group;" ::: "memory")
#define CP_WAIT(n)  asm volatile("cp.async.wait_group %0;" :: "n"(n) : "memory")

#define LDSM4(r0,r1,r2,r3,a) \
    asm volatile("ldmatrix.sync.aligned.m8n8.x4.shared.b16 {%0,%1,%2,%3}, [%4];" \
        : "=r"(r0),"=r"(r1),"=r"(r2),"=r"(r3) : "r"(a))

#define MMA16816(d, a, b0, b1) \
    asm volatile("mma.sync.aligned.m16n8k16.row.col.f32.bf16.bf16.f32 " \
        "{%0,%1,%2,%3},{%4,%5,%6,%7},{%8,%9},{%0,%1,%2,%3};" \
        : "+f"((d)[0]),"+f"((d)[1]),"+f"((d)[2]),"+f"((d)[3]) \
        : "r"((a)[0]),"r"((a)[1]),"r"((a)[2]),"r"((a)[3]),"r"(b0),"r"(b1))

// ---------------- small kernels ---------------------------------------------
__global__ void k_build_tok(const int* __restrict__ ctx, const int* __restrict__ qry,
                            const int* __restrict__ rsp, const int* __restrict__ c2,
                            const int* __restrict__ cl, const int* __restrict__ ql,
                            const int* __restrict__ rl, const int* __restrict__ c2l)
{
    int idx = blockIdx.x*blockDim.x + threadIdx.x;
    if (idx >= MT) return;
    int b = idx / SL, p = idx % SL;
    int l0 = cl[b], l1 = c2l[b], l2 = ql[b], l3 = rl[b];
    int tok = -1;
    if (p < l0)               tok = ctx[b*S_C + p];
    else if (p < l0+l1)       tok = c2 [b*S_C2 + (p-l0)];
    else if (p < l0+l1+l2)    tok = qry[b*S_Q + (p-l0-l1)];
    else if (p < l0+l1+l2+l3) tok = rsp[b*S_R + (p-l0-l1-l2)];
    g_tok[idx] = tok;
}

__global__ void k_gather(const float* __restrict__ wte)
{
    int idx = blockIdx.x*blockDim.x + threadIdx.x;
    if (idx >= MT*(DM/4)) return;
    int row = idx / (DM/4), c4 = idx % (DM/4);
    int tok = g_tok[row];
    float4 v = make_float4(0.f,0.f,0.f,0.f);
    if (tok >= 0) v = ((const float4*)(wte + (size_t)tok*DM))[c4];
    float vv[4] = {v.x, v.y, v.z, v.w};
    size_t o = (size_t)row*DM + c4*4;
    #pragma unroll
    for (int t=0;t<4;t++){
        bf16 h = __float2bfloat16(vv[t]);
        g_xh[o+t] = h;
        g_xl[o+t] = __float2bfloat16(vv[t] - __bfloat162float(h));
    }
}

__global__ void k_cvt(const float* __restrict__ in, bf16* __restrict__ oh,
                      bf16* __restrict__ ol, int nin, int ntot)
{
    int i = blockIdx.x*blockDim.x + threadIdx.x;
    if (i >= ntot) return;
    float v = (i < nin) ? in[i] : 0.f;
    bf16 h = __float2bfloat16(v);
    oh[i] = h;
    ol[i] = __float2bfloat16(v - __bfloat162float(h));
}

// transpose fp32 [Kd, Nd] -> split bf16 [Nd, Kd]
__global__ void k_cvtT(const float* __restrict__ in, bf16* __restrict__ oh,
                       bf16* __restrict__ ol, int Kd, int Nd)
{
    __shared__ float t[32][33];
    int kb = blockIdx.y*32, nb = blockIdx.x*32;
    int tx = threadIdx.x, ty = threadIdx.y;
    #pragma unroll
    for (int i=0;i<32;i+=8)
        t[ty+i][tx] = in[(size_t)(kb+ty+i)*Nd + nb+tx];
    __syncthreads();
    #pragma unroll
    for (int i=0;i<32;i+=8){
        float v = t[tx][ty+i];
        bf16 h = __float2bfloat16(v);
        size_t o = (size_t)(nb+ty+i)*Kd + kb+tx;
        oh[o] = h;
        ol[o] = __float2bfloat16(v - __bfloat162float(h));
    }
}

__global__ void __launch_bounds__(256)
k_ln(const float* __restrict__ in, const float* __restrict__ gm,
     const float* __restrict__ bt, bf16* __restrict__ oh, bf16* __restrict__ ol)
{
    __shared__ float red[256];
    int row = blockIdx.x, tid = threadIdx.x;
    const float* x = in + (size_t)row*DM;
    float v0 = x[tid], v1 = x[tid+256], v2 = x[tid+512];
    red[tid] = v0+v1+v2; __syncthreads();
    for (int o=128;o>0;o>>=1){ if(tid<o) red[tid]+=red[tid+o]; __syncthreads(); }
    float mean = red[0] * (1.f/768.f); __syncthreads();
    float d0=v0-mean, d1=v1-mean, d2=v2-mean;
    red[tid] = d0*d0+d1*d1+d2*d2; __syncthreads();
    for (int o=128;o>0;o>>=1){ if(tid<o) red[tid]+=red[tid+o]; __syncthreads(); }
    float inv = rsqrtf(red[0]*(1.f/768.f) + 1e-5f);
    #pragma unroll
    for (int t=0;t<3;t++){
        int c = tid + t*256;
        float d = (t==0)?d0:((t==1)?d1:d2);
        float y = d*inv*gm[c] + bt[c];
        bf16 h = __float2bfloat16(y);
        size_t o = (size_t)row*DM + c;
        oh[o] = h;
        ol[o] = __float2bfloat16(y - __bfloat162float(h));
    }
}

// ---------------- attention (fp32, unchanged) -------------------------------
__global__ void __launch_bounds__(256)
k_scores(const int* __restrict__ cl, const int* __restrict__ c2l,
         const int* __restrict__ ql, const int* __restrict__ rl)
{
    int bh = blockIdx.z; int b = bh / NH, hh = bh % NH;
    int q0 = blockIdx.x*64, k0 = blockIdx.y*64;
    int tid = threadIdx.x;
    int tq = (tid >> 4)*4, tk = (tid & 15)*4;

    if (k0 > q0 + 63) {
        #pragma unroll
        for (int i=0;i<4;i++)
            #pragma unroll
            for (int j=0;j<4;j++)
                g_sc[((size_t)bh*SL + (q0+tq+i))*SL + (k0+tk+j)] = -1e9f;
        return;
    }
    int total = cl[b] + c2l[b] + ql[b] + rl[b];

    __shared__ float Qs[64][64];
    __shared__ float Ks[64][64];
    #pragma unroll
    for (int t=0;t<4;t++) {
        int e = tid + 256*t;
        int row = e >> 4, c4 = e & 15;
        float4 qv = *(const float4*)(g_qkv + (size_t)(b*SL + q0 + row)*2304 + hh*64 + c4*4);
        Qs[c4*4+0][row]=qv.x; Qs[c4*4+1][row]=qv.y; Qs[c4*4+2][row]=qv.z; Qs[c4*4+3][row]=qv.w;
        float4 kv = *(const float4*)(g_qkv + (size_t)(b*SL + k0 + row)*2304 + 768 + hh*64 + c4*4);
        Ks[c4*4+0][row]=kv.x; Ks[c4*4+1][row]=kv.y; Ks[c4*4+2][row]=kv.z; Ks[c4*4+3][row]=kv.w;
    }
    __syncthreads();

    float acc[4][4];
    #pragma unroll
    for (int i=0;i<4;i++)
        #pragma unroll
        for (int j=0;j<4;j++) acc[i][j]=0.f;
    #pragma unroll 8
    for (int dd=0; dd<64; dd++) {
        float4 a = *(const float4*)&Qs[dd][tq];
        float4 bb = *(const float4*)&Ks[dd][tk];
        float av[4]={a.x,a.y,a.z,a.w}, bv[4]={bb.x,bb.y,bb.z,bb.w};
        #pragma unroll
        for (int i=0;i<4;i++)
            #pragma unroll
            for (int j=0;j<4;j++) acc[i][j] += av[i]*bv[j];
    }
    #pragma unroll
    for (int i=0;i<4;i++) {
        int qi = q0+tq+i;
        #pragma unroll
        for (int j=0;j<4;j++) {
            int kj = k0+tk+j;
            bool allowed = (kj <= qi) && (kj < total);
            g_sc[((size_t)bh*SL + qi)*SL + kj] = allowed ? acc[i][j]*0.125f : -1e9f;
        }
    }
}

__global__ void __launch_bounds__(256) k_softmax()
{
    __shared__ float red[256];
    size_t row = blockIdx.x;
    int tid = threadIdx.x;
    float* S = g_sc + row*SL;
    float4 v = ((float4*)S)[tid];
    float m = fmaxf(fmaxf(v.x,v.y), fmaxf(v.z,v.w));
    red[tid]=m; __syncthreads();
    for (int o=128;o>0;o>>=1){ if(tid<o) red[tid]=fmaxf(red[tid],red[tid+o]); __syncthreads(); }
    float mx = red[0]; __syncthreads();
    v.x = expf(v.x-mx); v.y = expf(v.y-mx); v.z = expf(v.z-mx); v.w = expf(v.w-mx);
    red[tid]=v.x+v.y+v.z+v.w; __syncthreads();
    for (int o=128;o>0;o>>=1){ if(tid<o) red[tid]+=red[tid+o]; __syncthreads(); }
    float inv = 1.f/red[0];
    v.x*=inv; v.y*=inv; v.z*=inv; v.w*=inv;
    ((float4*)S)[tid]=v;
}

__global__ void __launch_bounds__(256) k_av()
{
    int bh = blockIdx.y; int b = bh / NH, hh = bh % NH;
    int q0 = blockIdx.x*64;
    int tid = threadIdx.x;
    int tq = (tid >> 4)*4, td = (tid & 15)*4;
    __shared__ float Ss[64][64];
    __shared__ float Vs[64][64];
    float acc[4][4];
    #pragma unroll
    for (int i=0;i<4;i++)
        #pragma unroll
        for (int j=0;j<4;j++) acc[i][j]=0.f;

    for (int k0 = 0; k0 <= q0; k0 += 64) {
        #pragma unroll
        for (int t=0;t<4;t++) {
            int e = tid + 256*t;
            int row = e >> 4, c4 = e & 15;
            float4 sv = *(const float4*)(g_sc + ((size_t)bh*SL + q0+row)*SL + k0 + c4*4);
            *(float4*)&Ss[row][c4*4] = sv;
            float4 vv = *(const float4*)(g_qkv + (size_t)(b*SL + k0 + row)*2304 + 1536 + hh*64 + c4*4);
            *(float4*)&Vs[row][c4*4] = vv;
        }
        __syncthreads();
        #pragma unroll 8
        for (int kk=0; kk<64; kk++) {
            float a0=Ss[tq+0][kk], a1=Ss[tq+1][kk], a2=Ss[tq+2][kk], a3=Ss[tq+3][kk];
            float4 bb = *(const float4*)&Vs[kk][td];
            float bv[4]={bb.x,bb.y,bb.z,bb.w};
            #pragma unroll
            for (int j=0;j<4;j++) {
                acc[0][j] += a0*bv[j]; acc[1][j] += a1*bv[j];
                acc[2][j] += a2*bv[j]; acc[3][j] += a3*bv[j];
            }
        }
        __syncthreads();
    }
    #pragma unroll
    for (int i=0;i<4;i++)
        #pragma unroll
        for (int j=0;j<4;j++){
            float v = acc[i][j];
            bf16 h = __float2bfloat16(v);
            size_t o = (size_t)(b*SL + q0+tq+i)*DM + hh*64 + td + j;
            g_ah[o] = h;
            g_al[o] = __float2bfloat16(v - __bfloat162float(h));
        }
}

// ---------------- split-bf16 mma.sync GEMM (v2) ------------------------------
// D[M,N] = A[M,K] @ B[N,K]^T, 3 passes (Ah*Bh + Ah*Bl + Al*Bh), fp32 accum.
// CTA tile 128 x BN (BN = 128 or 256), 8 warps, warp tile 64 x BN/4.
// KC = 64, XOR-swizzled 128B smem rows, double-buffered cp.async (dyn smem).
#define KC 64
#define AB (128*128)   /* bytes per A matrix tile (128 rows x 128B) */

template<int BN>
__global__ void __launch_bounds__(256,1)
k_tgemm(const bf16* __restrict__ aH, const bf16* __restrict__ aL,
        const bf16* __restrict__ bH, const bf16* __restrict__ bL,
        const float* __restrict__ bias, const float* __restrict__ wpe,
        float* __restrict__ C, bf16* __restrict__ cH, bf16* __restrict__ cL,
        int K, int Nvalid, int flags)
{
    constexpr int WN  = BN/4;        // warp n-tile
    constexpr int NT  = WN/16;       // 16-row B subtiles per warp
    constexpr int N8  = WN/8;        // 8-col accum tiles per warp
    constexpr int BB  = BN*128;      // bytes per B matrix tile
    constexpr int STG = 2*AB + 2*BB; // Ah Al Bh Bl

    extern __shared__ __align__(128) unsigned char smem_buf[];
    uint32_t sb = smem_u32(smem_buf);
    int tid = threadIdx.x;
    int bm = blockIdx.x * 128;
    int bn = blockIdx.y * BN;

    int w = tid >> 5, lane = tid & 31;
    int wm = w >> 2, wn = w & 3;

    float acc[4][N8][4];
    #pragma unroll
    for (int mt=0;mt<4;mt++)
        #pragma unroll
        for (int n8=0;n8<N8;n8++)
            #pragma unroll
            for (int r=0;r<4;r++) acc[mt][n8][r]=0.f;

    int nk = K / KC;

    // ---- stage loader (all threads) ----
    auto load_stage = [&](int stage, int k0){
        uint32_t st = sb + stage*STG;
        #pragma unroll 4
        for (int u = tid; u < 128*8; u += 256) {
            int r = u >> 3, c = u & 7;
            uint32_t d = r*128 + ((c ^ (r&7))*16);
            size_t g = (size_t)(bm+r)*K + k0 + c*8;
            cpa16(st + d,      aH + g);
            cpa16(st + AB + d, aL + g);
        }
        #pragma unroll 4
        for (int u = tid; u < BN*8; u += 256) {
            int r = u >> 3, c = u & 7;
            uint32_t d = r*128 + ((c ^ (r&7))*16);
            size_t g = (size_t)(bn+r)*K + k0 + c*8;
            cpa16(st + 2*AB + d,      bH + g);
            cpa16(st + 2*AB + BB + d, bL + g);
        }
        CP_COMMIT();
    };

    load_stage(0, 0);

    int rr = lane & 15, hf = lane >> 4;
    for (int i = 0; i < nk; i++) {
        uint32_t st = sb + (i & 1)*STG;
        if (i + 1 < nk) { load_stage((i+1)&1, (i+1)*KC); CP_WAIT(1); }
        else            { CP_WAIT(0); }
        __syncthreads();

        #pragma unroll
        for (int ks = 0; ks < 4; ks++) {
            uint32_t ah[4][4], al[4][4], bh[NT][4], bl[NT][4];
            int ch = ks*2 + hf;
            #pragma unroll
            for (int mt=0;mt<4;mt++) {
                int r = wm*64 + mt*16 + rr;
                uint32_t ra = st + r*128 + ((ch ^ (r&7))*16);
                LDSM4(ah[mt][0],ah[mt][1],ah[mt][2],ah[mt][3], ra);
                LDSM4(al[mt][0],al[mt][1],al[mt][2],al[mt][3], ra + AB);
            }
            #pragma unroll
            for (int nt=0;nt<NT;nt++) {
                int r = wn*WN + nt*16 + rr;
                uint32_t rb = st + 2*AB + r*128 + ((ch ^ (r&7))*16);
                LDSM4(bh[nt][0],bh[nt][1],bh[nt][2],bh[nt][3], rb);
                LDSM4(bl[nt][0],bl[nt][1],bl[nt][2],bl[nt][3], rb + BB);
            }
            #pragma unroll
            for (int mt=0;mt<4;mt++) {
                #pragma unroll
                for (int n8=0;n8<N8;n8++) {
                    int nt = n8 >> 1, p = n8 & 1;
                    MMA16816(acc[mt][n8], ah[mt], bh[nt][p], bh[nt][p+2]);
                    MMA16816(acc[mt][n8], ah[mt], bl[nt][p], bl[nt][p+2]);
                    MMA16816(acc[mt][n8], al[mt], bh[nt][p], bh[nt][p+2]);
                }
            }
        }
        __syncthreads();
    }

    // ---- epilogue ----
    int r0b = bm + wm*64 + (lane >> 2);
    int c0b = bn + wn*WN + (lane & 3)*2;
    #pragma unroll
    for (int mt=0;mt<4;mt++) {
        #pragma unroll
        for (int n8=0;n8<N8;n8++) {
            #pragma unroll
            for (int half=0; half<2; half++) {
                int r = r0b + mt*16 + half*8;
                int c = c0b + n8*8;
                float v0 = acc[mt][n8][half*2+0];
                float v1 = acc[mt][n8][half*2+1];
                if (c + 1 < Nvalid) {
                    if (bias) { v0 += bias[c]; v1 += bias[c+1]; }
                    if (flags & GF_WPE) {
                        const float* wp = wpe + (size_t)(r & (SL-1))*DM + c;
                        v0 += wp[0]; v1 += wp[1];
                    }
                    size_t o = (size_t)r*Nvalid + c;
                    if (flags & GF_GELU) {
                        float u0=v0, u1=v1;
                        v0 = 0.5f*u0*(1.f + tanhf(0.7978845608028654f*(u0 + 0.044715f*u0*u0*u0)));
                        v1 = 0.5f*u1*(1.f + tanhf(0.7978845608028654f*(u1 + 0.044715f*u1*u1*u1)));
                        bf16 h0 = __float2bfloat16(v0), h1 = __float2bfloat16(v1);
                        cH[o] = h0; cH[o+1] = h1;
                        cL[o]   = __float2bfloat16(v0 - __bfloat162float(h0));
                        cL[o+1] = __float2bfloat16(v1 - __bfloat162float(h1));
                    } else if (flags & GF_RESID) {
                        float2 old = *(float2*)(C + o);
                        old.x += v0; old.y += v1;
                        *(float2*)(C + o) = old;
                    } else {
                        C[o] = v0; C[o+1] = v1;
                    }
                } else if (c < Nvalid) {
                    if (bias) v0 += bias[c];
                    if (flags & GF_WPE) v0 += wpe[(size_t)(r & (SL-1))*DM + c];
                    size_t o = (size_t)r*Nvalid + c;
                    if (flags & GF_GELU) {
                        float u = v0;
                        v0 = 0.5f*u*(1.f + tanhf(0.7978845608028654f*(u + 0.044715f*u*u*u)));
                        bf16 h = __float2bfloat16(v0);
                        cH[o] = h; cL[o] = __float2bfloat16(v0 - __bfloat162float(h));
                    } else if (flags & GF_RESID) {
                        C[o] += v0;
                    } else {
                        C[o] = v0;
                    }
                }
            }
        }
    }
}

#define SMEM256 (2*(2*AB + 2*256*128))   /* 196608 */
#define SMEM128 (2*(2*AB + 2*128*128))   /* 131072 */

// ---------------- launch ----------------------------------------------------
extern "C" void kernel_launch(void* const* d_in, const int* in_sizes, int n_in,
                              void* d_out, int out_size)
{
    const int*   ctx  = (const int*)  d_in[0];
    const int*   qry  = (const int*)  d_in[1];
    const int*   rsp  = (const int*)  d_in[2];
    const int*   c2   = (const int*)  d_in[3];
    const int*   cl   = (const int*)  d_in[4];
    const int*   ql   = (const int*)  d_in[5];
    const int*   rl   = (const int*)  d_in[6];
    const int*   c2l  = (const int*)  d_in[7];
    const float* wte  = (const float*)d_in[8];
    const float* wpe  = (const float*)d_in[9];
    const float* ln1g = (const float*)d_in[10];
    const float* ln1b = (const float*)d_in[11];
    const float* wqkv = (const float*)d_in[12];
    const float* bqkv = (const float*)d_in[13];
    const float* wo   = (const float*)d_in[14];
    const float* bo   = (const float*)d_in[15];
    const float* ln2g = (const float*)d_in[16];
    const float* ln2b = (const float*)d_in[17];
    const float* wfc  = (const float*)d_in[18];
    const float* bfc  = (const float*)d_in[19];
    const float* wpr  = (const float*)d_in[20];
    const float* bpr  = (const float*)d_in[21];
    const float* lnfg = (const float*)d_in[22];
    const float* lnfb = (const float*)d_in[23];
    const float* llw  = (const float*)d_in[24];
    const float* llb  = (const float*)d_in[25];
    float* out = (float*)d_out;

    cudaFuncSetAttribute(k_tgemm<256>, cudaFuncAttributeMaxDynamicSharedMemorySize, SMEM256);
    cudaFuncSetAttribute(k_tgemm<128>, cudaFuncAttributeMaxDynamicSharedMemorySize, SMEM128);

    float *ph, *pqkv;
    bf16 *xh, *xl, *ah, *al, *fh, *fl, *wth, *wtl;
    bf16 *qwh, *qwl, *owh, *owl, *fwh, *fwl, *pwh, *pwl, *lwh, *lwl;
    cudaGetSymbolAddress((void**)&ph,   g_h);
    cudaGetSymbolAddress((void**)&pqkv, g_qkv);
    cudaGetSymbolAddress((void**)&xh,  g_xh);  cudaGetSymbolAddress((void**)&xl,  g_xl);
    cudaGetSymbolAddress((void**)&ah,  g_ah);  cudaGetSymbolAddress((void**)&al,  g_al);
    cudaGetSymbolAddress((void**)&fh,  g_fh);  cudaGetSymbolAddress((void**)&fl,  g_fl);
    cudaGetSymbolAddress((void**)&wth, g_wth); cudaGetSymbolAddress((void**)&wtl, g_wtl);
    cudaGetSymbolAddress((void**)&qwh, g_qwh); cudaGetSymbolAddress((void**)&qwl, g_qwl);
    cudaGetSymbolAddress((void**)&owh, g_owh); cudaGetSymbolAddress((void**)&owl, g_owl);
    cudaGetSymbolAddress((void**)&fwh, g_fwh); cudaGetSymbolAddress((void**)&fwl, g_fwl);
    cudaGetSymbolAddress((void**)&pwh, g_pwh); cudaGetSymbolAddress((void**)&pwl, g_pwl);
    cudaGetSymbolAddress((void**)&lwh, g_lwh); cudaGetSymbolAddress((void**)&lwl, g_lwl);

    // ---- weight conversions ----
    k_cvt<<<(NVP*DM+255)/256, 256>>>(wte, wth, wtl, NVOC*DM, NVP*DM);
    k_cvt<<<(DM*DM+255)/256, 256>>>(llw, lwh, lwl, DM*DM, DM*DM);
    for (int l = 0; l < NLAY; l++) {
        k_cvtT<<<dim3(3*DM/32, DM/32), dim3(32,8)>>>(wqkv + (size_t)l*DM*3*DM,
                                                     qwh + (size_t)l*3*DM*DM, qwl + (size_t)l*3*DM*DM, DM, 3*DM);
        k_cvtT<<<dim3(DM/32, DM/32), dim3(32,8)>>>(wo + (size_t)l*DM*DM,
                                                   owh + (size_t)l*DM*DM, owl + (size_t)l*DM*DM, DM, DM);
        k_cvtT<<<dim3(FF/32, DM/32), dim3(32,8)>>>(wfc + (size_t)l*DM*FF,
                                                   fwh + (size_t)l*FF*DM, fwl + (size_t)l*FF*DM, DM, FF);
        k_cvtT<<<dim3(DM/32, FF/32), dim3(32,8)>>>(wpr + (size_t)l*FF*DM,
                                                   pwh + (size_t)l*DM*FF, pwl + (size_t)l*DM*FF, FF, DM);
    }

    // ---- embeddings ----
    k_build_tok<<<(MT+255)/256, 256>>>(ctx, qry, rsp, c2, cl, ql, rl, c2l);
    k_gather<<<(MT*(DM/4)+255)/256, 256>>>(wte);

    // h = emb @ ll_w^T + ll_b + wpe
    k_tgemm<128><<<dim3(MT/128, DM/128), 256, SMEM128>>>(xh, xl, lwh, lwl, llb, wpe,
                                                         ph, nullptr, nullptr, DM, DM, GF_WPE);

    for (int l = 0; l < NLAY; l++) {
        k_ln<<<MT, 256>>>(ph, ln1g + l*DM, ln1b + l*DM, xh, xl);
        k_tgemm<256><<<dim3(MT/128, 3*DM/256), 256, SMEM256>>>(xh, xl,
            qwh + (size_t)l*3*DM*DM, qwl + (size_t)l*3*DM*DM, bqkv + l*3*DM, nullptr,
            pqkv, nullptr, nullptr, DM, 3*DM, 0);
        k_scores<<<dim3(SL/64, SL/64, BATCH*NH), 256>>>(cl, c2l, ql, rl);
        k_softmax<<<BATCH*NH*SL, 256>>>();
        k_av<<<dim3(SL/64, BATCH*NH), 256>>>();
        k_tgemm<128><<<dim3(MT/128, DM/128), 256, SMEM128>>>(ah, al,
            owh + (size_t)l*DM*DM, owl + (size_t)l*DM*DM, bo + l*DM, nullptr,
            ph, nullptr, nullptr, DM, DM, GF_RESID);
        k_ln<<<MT, 256>>>(ph, ln2g + l*DM, ln2b + l*DM, xh, xl);
        k_tgemm<256><<<dim3(MT/128, FF/256), 256, SMEM256>>>(xh, xl,
            fwh + (size_t)l*FF*DM, fwl + (size_t)l*FF*DM, bfc + l*FF, nullptr,
            nullptr, fh, fl, DM, FF, GF_GELU);
        k_tgemm<128><<<dim3(MT/128, DM/128), 256, SMEM128>>>(fh, fl,
            pwh + (size_t)l*DM*FF, pwl + (size_t)l*DM*FF, bpr + l*DM, nullptr,
            ph, nullptr, nullptr, FF, DM, GF_RESID);
    }

    k_ln<<<MT, 256>>>(ph, lnfg, lnfb, xh, xl);

    // logits = x @ wte^T
    k_tgemm<256><<<dim3(MT/128, NVP/256), 256, SMEM256>>>(xh, xl, wth, wtl, nullptr, nullptr,
                                                          out, nullptr, nullptr, DM, NVOC, 0);
}

// round 7
// speedup vs baseline: 3.3005x; 1.6070x over previous
#include <cuda_runtime.h>
#include <cuda_bf16.h>
#include <cuda_fp16.h>
#include <math.h>
#include <stdint.h>

#define BATCH 4
#define SL    1024
#define DM    768
#define NH    12
#define FF    3072
#define NVOC  50257
#define NVP   50432            /* padded vocab: 197*256 */
#define MT    (BATCH*SL)       /* 4096 */
#define NLAY  2

#define S_C   512
#define S_C2  256
#define S_Q   128
#define S_R   128

#define GF_RESID 1
#define GF_GELU  2
#define GF_WPE   4

typedef __nv_bfloat16 bf16;

// ---------------- scratch ---------------------------------------------------
__device__ float g_h[MT*DM];
__device__ float g_qkv[MT*3*DM];
__device__ float g_sc[(size_t)BATCH*NH*SL*SL];
__device__ int   g_tok[MT];

__device__ bf16 g_xh[MT*DM],  g_xl[MT*DM];
__device__ bf16 g_ah[MT*DM],  g_al[MT*DM];
__device__ bf16 g_fh[(size_t)MT*FF], g_fl[(size_t)MT*FF];
__device__ bf16 g_qwh[NLAY*3*DM*DM], g_qwl[NLAY*3*DM*DM];
__device__ bf16 g_owh[NLAY*DM*DM],   g_owl[NLAY*DM*DM];
__device__ bf16 g_fwh[NLAY*FF*DM],   g_fwl[NLAY*FF*DM];
__device__ bf16 g_pwh[NLAY*DM*FF],   g_pwl[NLAY*DM*FF];
__device__ bf16 g_lwh[DM*DM],        g_lwl[DM*DM];

__device__ __half g_xf[MT*DM];                 // final LN output, fp16
__device__ __half g_wtf[(size_t)NVP*DM];       // wte fp16 (padded)

// ---------------- asm helpers -----------------------------------------------
__device__ __forceinline__ uint32_t smem_u32(const void* p){
    uint32_t a;
    asm("{ .reg .u64 t; cvta.to.shared.u64 t, %1; cvt.u32.u64 %0, t; }" : "=r"(a) : "l"(p));
    return a;
}
__device__ __forceinline__ void cpa16(uint32_t d, const void* s){
    asm volatile("cp.async.cg.shared.global [%0], [%1], 16;" :: "r"(d), "l"(s));
}
#define CP_COMMIT() asm volatile("cp.async.commit_group;" ::: "memory")
#define CP_WAIT(n)  asm volatile("cp.async.wait_group %0;" :: "n"(n) : "memory")

#define LDSM4(r0,r1,r2,r3,a) \
    asm volatile("ldmatrix.sync.aligned.m8n8.x4.shared.b16 {%0,%1,%2,%3}, [%4];" \
        : "=r"(r0),"=r"(r1),"=r"(r2),"=r"(r3) : "r"(a))

#define MMA16816(d, a, b0, b1) \
    asm volatile("mma.sync.aligned.m16n8k16.row.col.f32.bf16.bf16.f32 " \
        "{%0,%1,%2,%3},{%4,%5,%6,%7},{%8,%9},{%0,%1,%2,%3};" \
        : "+f"((d)[0]),"+f"((d)[1]),"+f"((d)[2]),"+f"((d)[3]) \
        : "r"((a)[0]),"r"((a)[1]),"r"((a)[2]),"r"((a)[3]),"r"(b0),"r"(b1))

#define MMA16816H(d, a, b0, b1) \
    asm volatile("mma.sync.aligned.m16n8k16.row.col.f32.f16.f16.f32 " \
        "{%0,%1,%2,%3},{%4,%5,%6,%7},{%8,%9},{%0,%1,%2,%3};" \
        : "+f"((d)[0]),"+f"((d)[1]),"+f"((d)[2]),"+f"((d)[3]) \
        : "r"((a)[0]),"r"((a)[1]),"r"((a)[2]),"r"((a)[3]),"r"(b0),"r"(b1))

// ---------------- small kernels ---------------------------------------------
__global__ void k_build_tok(const int* __restrict__ ctx, const int* __restrict__ qry,
                            const int* __restrict__ rsp, const int* __restrict__ c2,
                            const int* __restrict__ cl, const int* __restrict__ ql,
                            const int* __restrict__ rl, const int* __restrict__ c2l)
{
    int idx = blockIdx.x*blockDim.x + threadIdx.x;
    if (idx >= MT) return;
    int b = idx / SL, p = idx % SL;
    int l0 = cl[b], l1 = c2l[b], l2 = ql[b], l3 = rl[b];
    int tok = -1;
    if (p < l0)               tok = ctx[b*S_C + p];
    else if (p < l0+l1)       tok = c2 [b*S_C2 + (p-l0)];
    else if (p < l0+l1+l2)    tok = qry[b*S_Q + (p-l0-l1)];
    else if (p < l0+l1+l2+l3) tok = rsp[b*S_R + (p-l0-l1-l2)];
    g_tok[idx] = tok;
}

__global__ void k_gather(const float* __restrict__ wte)
{
    int idx = blockIdx.x*blockDim.x + threadIdx.x;
    if (idx >= MT*(DM/4)) return;
    int row = idx / (DM/4), c4 = idx % (DM/4);
    int tok = g_tok[row];
    float4 v = make_float4(0.f,0.f,0.f,0.f);
    if (tok >= 0) v = ((const float4*)(wte + (size_t)tok*DM))[c4];
    float vv[4] = {v.x, v.y, v.z, v.w};
    size_t o = (size_t)row*DM + c4*4;
    #pragma unroll
    for (int t=0;t<4;t++){
        bf16 h = __float2bfloat16(vv[t]);
        g_xh[o+t] = h;
        g_xl[o+t] = __float2bfloat16(vv[t] - __bfloat162float(h));
    }
}

__global__ void k_cvt_f16(const float* __restrict__ in, __half* __restrict__ o,
                          int nin, int ntot)
{
    int i = blockIdx.x*blockDim.x + threadIdx.x;
    if (i >= ntot) return;
    float v = (i < nin) ? in[i] : 0.f;
    o[i] = __float2half(v);
}

__global__ void k_cvt(const float* __restrict__ in, bf16* __restrict__ oh,
                      bf16* __restrict__ ol, int nin, int ntot)
{
    int i = blockIdx.x*blockDim.x + threadIdx.x;
    if (i >= ntot) return;
    float v = (i < nin) ? in[i] : 0.f;
    bf16 h = __float2bfloat16(v);
    oh[i] = h;
    ol[i] = __float2bfloat16(v - __bfloat162float(h));
}

// transpose fp32 [Kd, Nd] -> split bf16 [Nd, Kd]
__global__ void k_cvtT(const float* __restrict__ in, bf16* __restrict__ oh,
                       bf16* __restrict__ ol, int Kd, int Nd)
{
    __shared__ float t[32][33];
    int kb = blockIdx.y*32, nb = blockIdx.x*32;
    int tx = threadIdx.x, ty = threadIdx.y;
    #pragma unroll
    for (int i=0;i<32;i+=8)
        t[ty+i][tx] = in[(size_t)(kb+ty+i)*Nd + nb+tx];
    __syncthreads();
    #pragma unroll
    for (int i=0;i<32;i+=8){
        float v = t[tx][ty+i];
        bf16 h = __float2bfloat16(v);
        size_t o = (size_t)(nb+ty+i)*Kd + kb+tx;
        oh[o] = h;
        ol[o] = __float2bfloat16(v - __bfloat162float(h));
    }
}

__global__ void __launch_bounds__(256)
k_ln(const float* __restrict__ in, const float* __restrict__ gm,
     const float* __restrict__ bt, bf16* __restrict__ oh, bf16* __restrict__ ol)
{
    __shared__ float red[256];
    int row = blockIdx.x, tid = threadIdx.x;
    const float* x = in + (size_t)row*DM;
    float v0 = x[tid], v1 = x[tid+256], v2 = x[tid+512];
    red[tid] = v0+v1+v2; __syncthreads();
    for (int o=128;o>0;o>>=1){ if(tid<o) red[tid]+=red[tid+o]; __syncthreads(); }
    float mean = red[0] * (1.f/768.f); __syncthreads();
    float d0=v0-mean, d1=v1-mean, d2=v2-mean;
    red[tid] = d0*d0+d1*d1+d2*d2; __syncthreads();
    for (int o=128;o>0;o>>=1){ if(tid<o) red[tid]+=red[tid+o]; __syncthreads(); }
    float inv = rsqrtf(red[0]*(1.f/768.f) + 1e-5f);
    #pragma unroll
    for (int t=0;t<3;t++){
        int c = tid + t*256;
        float d = (t==0)?d0:((t==1)?d1:d2);
        float y = d*inv*gm[c] + bt[c];
        bf16 h = __float2bfloat16(y);
        size_t o = (size_t)row*DM + c;
        oh[o] = h;
        ol[o] = __float2bfloat16(y - __bfloat162float(h));
    }
}

// final LayerNorm -> fp16 (feeds LM head only)
__global__ void __launch_bounds__(256)
k_ln_f16(const float* __restrict__ in, const float* __restrict__ gm,
         const float* __restrict__ bt, __half* __restrict__ o16)
{
    __shared__ float red[256];
    int row = blockIdx.x, tid = threadIdx.x;
    const float* x = in + (size_t)row*DM;
    float v0 = x[tid], v1 = x[tid+256], v2 = x[tid+512];
    red[tid] = v0+v1+v2; __syncthreads();
    for (int o=128;o>0;o>>=1){ if(tid<o) red[tid]+=red[tid+o]; __syncthreads(); }
    float mean = red[0] * (1.f/768.f); __syncthreads();
    float d0=v0-mean, d1=v1-mean, d2=v2-mean;
    red[tid] = d0*d0+d1*d1+d2*d2; __syncthreads();
    for (int o=128;o>0;o>>=1){ if(tid<o) red[tid]+=red[tid+o]; __syncthreads(); }
    float inv = rsqrtf(red[0]*(1.f/768.f) + 1e-5f);
    #pragma unroll
    for (int t=0;t<3;t++){
        int c = tid + t*256;
        float d = (t==0)?d0:((t==1)?d1:d2);
        o16[(size_t)row*DM + c] = __float2half(d*inv*gm[c] + bt[c]);
    }
}

// ---------------- attention (fp32, unchanged) -------------------------------
__global__ void __launch_bounds__(256)
k_scores(const int* __restrict__ cl, const int* __restrict__ c2l,
         const int* __restrict__ ql, const int* __restrict__ rl)
{
    int bh = blockIdx.z; int b = bh / NH, hh = bh % NH;
    int q0 = blockIdx.x*64, k0 = blockIdx.y*64;
    int tid = threadIdx.x;
    int tq = (tid >> 4)*4, tk = (tid & 15)*4;

    if (k0 > q0 + 63) {
        #pragma unroll
        for (int i=0;i<4;i++)
            #pragma unroll
            for (int j=0;j<4;j++)
                g_sc[((size_t)bh*SL + (q0+tq+i))*SL + (k0+tk+j)] = -1e9f;
        return;
    }
    int total = cl[b] + c2l[b] + ql[b] + rl[b];

    __shared__ float Qs[64][64];
    __shared__ float Ks[64][64];
    #pragma unroll
    for (int t=0;t<4;t++) {
        int e = tid + 256*t;
        int row = e >> 4, c4 = e & 15;
        float4 qv = *(const float4*)(g_qkv + (size_t)(b*SL + q0 + row)*2304 + hh*64 + c4*4);
        Qs[c4*4+0][row]=qv.x; Qs[c4*4+1][row]=qv.y; Qs[c4*4+2][row]=qv.z; Qs[c4*4+3][row]=qv.w;
        float4 kv = *(const float4*)(g_qkv + (size_t)(b*SL + k0 + row)*2304 + 768 + hh*64 + c4*4);
        Ks[c4*4+0][row]=kv.x; Ks[c4*4+1][row]=kv.y; Ks[c4*4+2][row]=kv.z; Ks[c4*4+3][row]=kv.w;
    }
    __syncthreads();

    float acc[4][4];
    #pragma unroll
    for (int i=0;i<4;i++)
        #pragma unroll
        for (int j=0;j<4;j++) acc[i][j]=0.f;
    #pragma unroll 8
    for (int dd=0; dd<64; dd++) {
        float4 a = *(const float4*)&Qs[dd][tq];
        float4 bb = *(const float4*)&Ks[dd][tk];
        float av[4]={a.x,a.y,a.z,a.w}, bv[4]={bb.x,bb.y,bb.z,bb.w};
        #pragma unroll
        for (int i=0;i<4;i++)
            #pragma unroll
            for (int j=0;j<4;j++) acc[i][j] += av[i]*bv[j];
    }
    #pragma unroll
    for (int i=0;i<4;i++) {
        int qi = q0+tq+i;
        #pragma unroll
        for (int j=0;j<4;j++) {
            int kj = k0+tk+j;
            bool allowed = (kj <= qi) && (kj < total);
            g_sc[((size_t)bh*SL + qi)*SL + kj] = allowed ? acc[i][j]*0.125f : -1e9f;
        }
    }
}

__global__ void __launch_bounds__(256) k_softmax()
{
    __shared__ float red[256];
    size_t row = blockIdx.x;
    int tid = threadIdx.x;
    float* S = g_sc + row*SL;
    float4 v = ((float4*)S)[tid];
    float m = fmaxf(fmaxf(v.x,v.y), fmaxf(v.z,v.w));
    red[tid]=m; __syncthreads();
    for (int o=128;o>0;o>>=1){ if(tid<o) red[tid]=fmaxf(red[tid],red[tid+o]); __syncthreads(); }
    float mx = red[0]; __syncthreads();
    v.x = expf(v.x-mx); v.y = expf(v.y-mx); v.z = expf(v.z-mx); v.w = expf(v.w-mx);
    red[tid]=v.x+v.y+v.z+v.w; __syncthreads();
    for (int o=128;o>0;o>>=1){ if(tid<o) red[tid]+=red[tid+o]; __syncthreads(); }
    float inv = 1.f/red[0];
    v.x*=inv; v.y*=inv; v.z*=inv; v.w*=inv;
    ((float4*)S)[tid]=v;
}

__global__ void __launch_bounds__(256) k_av()
{
    int bh = blockIdx.y; int b = bh / NH, hh = bh % NH;
    int q0 = blockIdx.x*64;
    int tid = threadIdx.x;
    int tq = (tid >> 4)*4, td = (tid & 15)*4;
    __shared__ float Ss[64][64];
    __shared__ float Vs[64][64];
    float acc[4][4];
    #pragma unroll
    for (int i=0;i<4;i++)
        #pragma unroll
        for (int j=0;j<4;j++) acc[i][j]=0.f;

    for (int k0 = 0; k0 <= q0; k0 += 64) {
        #pragma unroll
        for (int t=0;t<4;t++) {
            int e = tid + 256*t;
            int row = e >> 4, c4 = e & 15;
            float4 sv = *(const float4*)(g_sc + ((size_t)bh*SL + q0+row)*SL + k0 + c4*4);
            *(float4*)&Ss[row][c4*4] = sv;
            float4 vv = *(const float4*)(g_qkv + (size_t)(b*SL + k0 + row)*2304 + 1536 + hh*64 + c4*4);
            *(float4*)&Vs[row][c4*4] = vv;
        }
        __syncthreads();
        #pragma unroll 8
        for (int kk=0; kk<64; kk++) {
            float a0=Ss[tq+0][kk], a1=Ss[tq+1][kk], a2=Ss[tq+2][kk], a3=Ss[tq+3][kk];
            float4 bb = *(const float4*)&Vs[kk][td];
            float bv[4]={bb.x,bb.y,bb.z,bb.w};
            #pragma unroll
            for (int j=0;j<4;j++) {
                acc[0][j] += a0*bv[j]; acc[1][j] += a1*bv[j];
                acc[2][j] += a2*bv[j]; acc[3][j] += a3*bv[j];
            }
        }
        __syncthreads();
    }
    #pragma unroll
    for (int i=0;i<4;i++)
        #pragma unroll
        for (int j=0;j<4;j++){
            float v = acc[i][j];
            bf16 h = __float2bfloat16(v);
            size_t o = (size_t)(b*SL + q0+tq+i)*DM + hh*64 + td + j;
            g_ah[o] = h;
            g_al[o] = __float2bfloat16(v - __bfloat162float(h));
        }
}

// ---------------- split-bf16 mma.sync GEMM (layer GEMMs) ---------------------
#define KC 64
#define AB (128*128)

template<int BN>
__global__ void __launch_bounds__(256,1)
k_tgemm(const bf16* __restrict__ aH, const bf16* __restrict__ aL,
        const bf16* __restrict__ bH, const bf16* __restrict__ bL,
        const float* __restrict__ bias, const float* __restrict__ wpe,
        float* __restrict__ C, bf16* __restrict__ cH, bf16* __restrict__ cL,
        int K, int Nvalid, int flags)
{
    constexpr int WN  = BN/4;
    constexpr int NT  = WN/16;
    constexpr int N8  = WN/8;
    constexpr int BB  = BN*128;
    constexpr int STG = 2*AB + 2*BB;

    extern __shared__ __align__(128) unsigned char smem_buf[];
    uint32_t sb = smem_u32(smem_buf);
    int tid = threadIdx.x;
    int bm = blockIdx.x * 128;
    int bn = blockIdx.y * BN;

    int w = tid >> 5, lane = tid & 31;
    int wm = w >> 2, wn = w & 3;

    float acc[4][N8][4];
    #pragma unroll
    for (int mt=0;mt<4;mt++)
        #pragma unroll
        for (int n8=0;n8<N8;n8++)
            #pragma unroll
            for (int r=0;r<4;r++) acc[mt][n8][r]=0.f;

    int nk = K / KC;

    auto load_stage = [&](int stage, int k0){
        uint32_t st = sb + stage*STG;
        #pragma unroll 4
        for (int u = tid; u < 128*8; u += 256) {
            int r = u >> 3, c = u & 7;
            uint32_t d = r*128 + ((c ^ (r&7))*16);
            size_t g = (size_t)(bm+r)*K + k0 + c*8;
            cpa16(st + d,      aH + g);
            cpa16(st + AB + d, aL + g);
        }
        #pragma unroll 4
        for (int u = tid; u < BN*8; u += 256) {
            int r = u >> 3, c = u & 7;
            uint32_t d = r*128 + ((c ^ (r&7))*16);
            size_t g = (size_t)(bn+r)*K + k0 + c*8;
            cpa16(st + 2*AB + d,      bH + g);
            cpa16(st + 2*AB + BB + d, bL + g);
        }
        CP_COMMIT();
    };

    load_stage(0, 0);

    int rr = lane & 15, hf = lane >> 4;
    for (int i = 0; i < nk; i++) {
        uint32_t st = sb + (i & 1)*STG;
        if (i + 1 < nk) { load_stage((i+1)&1, (i+1)*KC); CP_WAIT(1); }
        else            { CP_WAIT(0); }
        __syncthreads();

        #pragma unroll
        for (int ks = 0; ks < 4; ks++) {
            uint32_t ah[4][4], al[4][4], bh[NT][4], bl[NT][4];
            int ch = ks*2 + hf;
            #pragma unroll
            for (int mt=0;mt<4;mt++) {
                int r = wm*64 + mt*16 + rr;
                uint32_t ra = st + r*128 + ((ch ^ (r&7))*16);
                LDSM4(ah[mt][0],ah[mt][1],ah[mt][2],ah[mt][3], ra);
                LDSM4(al[mt][0],al[mt][1],al[mt][2],al[mt][3], ra + AB);
            }
            #pragma unroll
            for (int nt=0;nt<NT;nt++) {
                int r = wn*WN + nt*16 + rr;
                uint32_t rb = st + 2*AB + r*128 + ((ch ^ (r&7))*16);
                LDSM4(bh[nt][0],bh[nt][1],bh[nt][2],bh[nt][3], rb);
                LDSM4(bl[nt][0],bl[nt][1],bl[nt][2],bl[nt][3], rb + BB);
            }
            #pragma unroll
            for (int mt=0;mt<4;mt++) {
                #pragma unroll
                for (int n8=0;n8<N8;n8++) {
                    int nt = n8 >> 1, p = n8 & 1;
                    MMA16816(acc[mt][n8], ah[mt], bh[nt][p], bh[nt][p+2]);
                    MMA16816(acc[mt][n8], ah[mt], bl[nt][p], bl[nt][p+2]);
                    MMA16816(acc[mt][n8], al[mt], bh[nt][p], bh[nt][p+2]);
                }
            }
        }
        __syncthreads();
    }

    int r0b = bm + wm*64 + (lane >> 2);
    int c0b = bn + wn*WN + (lane & 3)*2;
    #pragma unroll
    for (int mt=0;mt<4;mt++) {
        #pragma unroll
        for (int n8=0;n8<N8;n8++) {
            #pragma unroll
            for (int half=0; half<2; half++) {
                int r = r0b + mt*16 + half*8;
                int c = c0b + n8*8;
                float v0 = acc[mt][n8][half*2+0];
                float v1 = acc[mt][n8][half*2+1];
                if (bias) { v0 += bias[c]; v1 += bias[c+1]; }
                if (flags & GF_WPE) {
                    const float* wp = wpe + (size_t)(r & (SL-1))*DM + c;
                    v0 += wp[0]; v1 += wp[1];
                }
                size_t o = (size_t)r*Nvalid + c;
                if (flags & GF_GELU) {
                    float u0=v0, u1=v1;
                    v0 = 0.5f*u0*(1.f + tanhf(0.7978845608028654f*(u0 + 0.044715f*u0*u0*u0)));
                    v1 = 0.5f*u1*(1.f + tanhf(0.7978845608028654f*(u1 + 0.044715f*u1*u1*u1)));
                    bf16 h0 = __float2bfloat16(v0), h1 = __float2bfloat16(v1);
                    cH[o] = h0; cH[o+1] = h1;
                    cL[o]   = __float2bfloat16(v0 - __bfloat162float(h0));
                    cL[o+1] = __float2bfloat16(v1 - __bfloat162float(h1));
                } else if (flags & GF_RESID) {
                    float2 old = *(float2*)(C + o);
                    old.x += v0; old.y += v1;
                    *(float2*)(C + o) = old;
                } else {
                    C[o] = v0; C[o+1] = v1;
                }
            }
        }
    }
}

#define SMEM256 (2*(2*AB + 2*256*128))   /* 196608 */
#define SMEM128 (2*(2*AB + 2*128*128))   /* 131072 */

// ---------------- fp16 single-pass GEMM (LM head) ----------------------------
// C[M,NVOC] = A[M,768] @ B[NVP,768]^T, fp16 inputs, fp32 accum.
// CTA 128x256, 8 warps, warp 64x64. 3-stage cp.async pipeline.
#define HAB (128*128)      /* A stage bytes */
#define HBB (256*128)      /* B stage bytes */
#define HSTG (HAB+HBB)     /* 49152 */
#define SMEMH (3*HSTG)     /* 147456 */

__global__ void __launch_bounds__(256,1)
k_hgemm(const __half* __restrict__ Af, const __half* __restrict__ Bf,
        float* __restrict__ C, int K, int Nvalid)
{
    extern __shared__ __align__(128) unsigned char smem_buf[];
    uint32_t sb = smem_u32(smem_buf);
    int tid = threadIdx.x;
    int bm = blockIdx.x * 128;
    int bn = blockIdx.y * 256;

    int w = tid >> 5, lane = tid & 31;
    int wm = w >> 2, wn = w & 3;

    float acc[4][8][4];
    #pragma unroll
    for (int mt=0;mt<4;mt++)
        #pragma unroll
        for (int n8=0;n8<8;n8++)
            #pragma unroll
            for (int r=0;r<4;r++) acc[mt][n8][r]=0.f;

    int nk = K / KC;   // 12

    auto load_stage = [&](int stage, int k0){
        uint32_t st = sb + stage*HSTG;
        #pragma unroll 4
        for (int u = tid; u < 128*8; u += 256) {
            int r = u >> 3, c = u & 7;
            uint32_t d = r*128 + ((c ^ (r&7))*16);
            cpa16(st + d, Af + (size_t)(bm+r)*K + k0 + c*8);
        }
        #pragma unroll 8
        for (int u = tid; u < 256*8; u += 256) {
            int r = u >> 3, c = u & 7;
            uint32_t d = r*128 + ((c ^ (r&7))*16);
            cpa16(st + HAB + d, Bf + (size_t)(bn+r)*K + k0 + c*8);
        }
        CP_COMMIT();
    };

    load_stage(0, 0);
    if (nk > 1) load_stage(1, KC);

    int rr = lane & 15, hf = lane >> 4;
    int stage = 0;
    for (int i = 0; i < nk; i++) {
        if (i + 2 < nk) { load_stage((stage+2)%3, (i+2)*KC); CP_WAIT(2); }
        else if (i + 1 < nk) { CP_WAIT(1); }
        else { CP_WAIT(0); }
        __syncthreads();

        uint32_t st = sb + stage*HSTG;
        #pragma unroll
        for (int ks = 0; ks < 4; ks++) {
            uint32_t ah[4][4], bh[4][4];
            int ch = ks*2 + hf;
            #pragma unroll
            for (int mt=0;mt<4;mt++) {
                int r = wm*64 + mt*16 + rr;
                uint32_t ra = st + r*128 + ((ch ^ (r&7))*16);
                LDSM4(ah[mt][0],ah[mt][1],ah[mt][2],ah[mt][3], ra);
            }
            #pragma unroll
            for (int nt=0;nt<4;nt++) {
                int r = wn*64 + nt*16 + rr;
                uint32_t rb = st + HAB + r*128 + ((ch ^ (r&7))*16);
                LDSM4(bh[nt][0],bh[nt][1],bh[nt][2],bh[nt][3], rb);
            }
            #pragma unroll
            for (int mt=0;mt<4;mt++) {
                #pragma unroll
                for (int n8=0;n8<8;n8++) {
                    int nt = n8 >> 1, p = n8 & 1;
                    MMA16816H(acc[mt][n8], ah[mt], bh[nt][p], bh[nt][p+2]);
                }
            }
        }
        __syncthreads();
        stage = (stage + 1) % 3;
    }

    int r0b = bm + wm*64 + (lane >> 2);
    int c0b = bn + wn*64 + (lane & 3)*2;
    #pragma unroll
    for (int mt=0;mt<4;mt++) {
        #pragma unroll
        for (int n8=0;n8<8;n8++) {
            int c = c0b + n8*8;
            #pragma unroll
            for (int half=0; half<2; half++) {
                int r = r0b + mt*16 + half*8;
                size_t o = (size_t)r*Nvalid + c;
                if (c + 1 < Nvalid) {
                    C[o]   = acc[mt][n8][half*2+0];
                    C[o+1] = acc[mt][n8][half*2+1];
                } else if (c < Nvalid) {
                    C[o]   = acc[mt][n8][half*2+0];
                }
            }
        }
    }
}

// ---------------- launch ----------------------------------------------------
extern "C" void kernel_launch(void* const* d_in, const int* in_sizes, int n_in,
                              void* d_out, int out_size)
{
    const int*   ctx  = (const int*)  d_in[0];
    const int*   qry  = (const int*)  d_in[1];
    const int*   rsp  = (const int*)  d_in[2];
    const int*   c2   = (const int*)  d_in[3];
    const int*   cl   = (const int*)  d_in[4];
    const int*   ql   = (const int*)  d_in[5];
    const int*   rl   = (const int*)  d_in[6];
    const int*   c2l  = (const int*)  d_in[7];
    const float* wte  = (const float*)d_in[8];
    const float* wpe  = (const float*)d_in[9];
    const float* ln1g = (const float*)d_in[10];
    const float* ln1b = (const float*)d_in[11];
    const float* wqkv = (const float*)d_in[12];
    const float* bqkv = (const float*)d_in[13];
    const float* wo   = (const float*)d_in[14];
    const float* bo   = (const float*)d_in[15];
    const float* ln2g = (const float*)d_in[16];
    const float* ln2b = (const float*)d_in[17];
    const float* wfc  = (const float*)d_in[18];
    const float* bfc  = (const float*)d_in[19];
    const float* wpr  = (const float*)d_in[20];
    const float* bpr  = (const float*)d_in[21];
    const float* lnfg = (const float*)d_in[22];
    const float* lnfb = (const float*)d_in[23];
    const float* llw  = (const float*)d_in[24];
    const float* llb  = (const float*)d_in[25];
    float* out = (float*)d_out;

    cudaFuncSetAttribute(k_tgemm<256>, cudaFuncAttributeMaxDynamicSharedMemorySize, SMEM256);
    cudaFuncSetAttribute(k_tgemm<128>, cudaFuncAttributeMaxDynamicSharedMemorySize, SMEM128);
    cudaFuncSetAttribute(k_hgemm,      cudaFuncAttributeMaxDynamicSharedMemorySize, SMEMH);

    float *ph, *pqkv;
    bf16 *xh, *xl, *ah, *al, *fh, *fl;
    bf16 *qwh, *qwl, *owh, *owl, *fwh, *fwl, *pwh, *pwl, *lwh, *lwl;
    __half *xf, *wtf;
    cudaGetSymbolAddress((void**)&ph,   g_h);
    cudaGetSymbolAddress((void**)&pqkv, g_qkv);
    cudaGetSymbolAddress((void**)&xh,  g_xh);  cudaGetSymbolAddress((void**)&xl,  g_xl);
    cudaGetSymbolAddress((void**)&ah,  g_ah);  cudaGetSymbolAddress((void**)&al,  g_al);
    cudaGetSymbolAddress((void**)&fh,  g_fh);  cudaGetSymbolAddress((void**)&fl,  g_fl);
    cudaGetSymbolAddress((void**)&qwh, g_qwh); cudaGetSymbolAddress((void**)&qwl, g_qwl);
    cudaGetSymbolAddress((void**)&owh, g_owh); cudaGetSymbolAddress((void**)&owl, g_owl);
    cudaGetSymbolAddress((void**)&fwh, g_fwh); cudaGetSymbolAddress((void**)&fwl, g_fwl);
    cudaGetSymbolAddress((void**)&pwh, g_pwh); cudaGetSymbolAddress((void**)&pwl, g_pwl);
    cudaGetSymbolAddress((void**)&lwh, g_lwh); cudaGetSymbolAddress((void**)&lwl, g_lwl);
    cudaGetSymbolAddress((void**)&xf,  g_xf);  cudaGetSymbolAddress((void**)&wtf, g_wtf);

    // ---- weight conversions ----
    k_cvt_f16<<<(NVP*DM+255)/256, 256>>>(wte, wtf, NVOC*DM, NVP*DM);
    k_cvt<<<(DM*DM+255)/256, 256>>>(llw, lwh, lwl, DM*DM, DM*DM);
    for (int l = 0; l < NLAY; l++) {
        k_cvtT<<<dim3(3*DM/32, DM/32), dim3(32,8)>>>(wqkv + (size_t)l*DM*3*DM,
                                                     qwh + (size_t)l*3*DM*DM, qwl + (size_t)l*3*DM*DM, DM, 3*DM);
        k_cvtT<<<dim3(DM/32, DM/32), dim3(32,8)>>>(wo + (size_t)l*DM*DM,
                                                   owh + (size_t)l*DM*DM, owl + (size_t)l*DM*DM, DM, DM);
        k_cvtT<<<dim3(FF/32, DM/32), dim3(32,8)>>>(wfc + (size_t)l*DM*FF,
                                                   fwh + (size_t)l*FF*DM, fwl + (size_t)l*FF*DM, DM, FF);
        k_cvtT<<<dim3(DM/32, FF/32), dim3(32,8)>>>(wpr + (size_t)l*FF*DM,
                                                   pwh + (size_t)l*DM*FF, pwl + (size_t)l*DM*FF, FF, DM);
    }

    // ---- embeddings ----
    k_build_tok<<<(MT+255)/256, 256>>>(ctx, qry, rsp, c2, cl, ql, rl, c2l);
    k_gather<<<(MT*(DM/4)+255)/256, 256>>>(wte);

    // h = emb @ ll_w^T + ll_b + wpe
    k_tgemm<128><<<dim3(MT/128, DM/128), 256, SMEM128>>>(xh, xl, lwh, lwl, llb, wpe,
                                                         ph, nullptr, nullptr, DM, DM, GF_WPE);

    for (int l = 0; l < NLAY; l++) {
        k_ln<<<MT, 256>>>(ph, ln1g + l*DM, ln1b + l*DM, xh, xl);
        k_tgemm<256><<<dim3(MT/128, 3*DM/256), 256, SMEM256>>>(xh, xl,
            qwh + (size_t)l*3*DM*DM, qwl + (size_t)l*3*DM*DM, bqkv + l*3*DM, nullptr,
            pqkv, nullptr, nullptr, DM, 3*DM, 0);
        k_scores<<<dim3(SL/64, SL/64, BATCH*NH), 256>>>(cl, c2l, ql, rl);
        k_softmax<<<BATCH*NH*SL, 256>>>();
        k_av<<<dim3(SL/64, BATCH*NH), 256>>>();
        k_tgemm<128><<<dim3(MT/128, DM/128), 256, SMEM128>>>(ah, al,
            owh + (size_t)l*DM*DM, owl + (size_t)l*DM*DM, bo + l*DM, nullptr,
            ph, nullptr, nullptr, DM, DM, GF_RESID);
        k_ln<<<MT, 256>>>(ph, ln2g + l*DM, ln2b + l*DM, xh, xl);
        k_tgemm<256><<<dim3(MT/128, FF/256), 256, SMEM256>>>(xh, xl,
            fwh + (size_t)l*FF*DM, fwl + (size_t)l*FF*DM, bfc + l*FF, nullptr,
            nullptr, fh, fl, DM, FF, GF_GELU);
        k_tgemm<128><<<dim3(MT/128, DM/128), 256, SMEM128>>>(fh, fl,
            pwh + (size_t)l*DM*FF, pwl + (size_t)l*DM*FF, bpr + l*DM, nullptr,
            ph, nullptr, nullptr, FF, DM, GF_RESID);
    }

    k_ln_f16<<<MT, 256>>>(ph, lnfg, lnfb, xf);

    // logits = x @ wte^T  (fp16 single-pass)
    k_hgemm<<<dim3(MT/128, NVP/256), 256, SMEMH>>>(xf, wtf, out, DM, NVOC);
}

// round 9
// speedup vs baseline: 3.9041x; 1.1829x over previous
#include <cuda_runtime.h>
#include <cuda_bf16.h>
#include <cuda_fp16.h>
#include <math.h>
#include <stdint.h>

#define BATCH 4
#define SL    1024
#define DM    768
#define NH    12
#define FF    3072
#define NVOC  50257
#define NVP   50432            /* padded vocab: 197*256 */
#define MT    (BATCH*SL)       /* 4096 */
#define NLAY  2

#define S_C   512
#define S_C2  256
#define S_Q   128
#define S_R   128

#define GF_RESID 1
#define GF_GELU  2
#define GF_WPE   4
#define GF_QKV   8

typedef __nv_bfloat16 bf16;

// ---------------- scratch ---------------------------------------------------
__device__ float g_h[MT*DM];
__device__ float g_sc[(size_t)BATCH*NH*SL*SL];
__device__ int   g_tok[MT];

__device__ bf16 g_xh[MT*DM],  g_xl[MT*DM];
__device__ bf16 g_ah[MT*DM],  g_al[MT*DM];
__device__ bf16 g_fh[(size_t)MT*FF], g_fl[(size_t)MT*FF];
__device__ bf16 g_qwh[NLAY*3*DM*DM], g_qwl[NLAY*3*DM*DM];
__device__ bf16 g_owh[NLAY*DM*DM],   g_owl[NLAY*DM*DM];
__device__ bf16 g_fwh[NLAY*FF*DM],   g_fwl[NLAY*FF*DM];
__device__ bf16 g_pwh[NLAY*DM*FF],   g_pwl[NLAY*DM*FF];
__device__ bf16 g_lwh[DM*DM],        g_lwl[DM*DM];

__device__ __half g_xf[MT*DM];                       // final LN output, fp16
__device__ __half g_wtf[(size_t)NVP*DM];             // wte fp16 (padded)
__device__ __half g_q16[(size_t)BATCH*NH*SL*64];     // Q head-major fp16
__device__ __half g_k16[(size_t)BATCH*NH*SL*64];     // K head-major fp16
__device__ __half g_vt [(size_t)BATCH*NH*64*SL];     // V^T [bh, d, s] fp16
__device__ __half g_p  [(size_t)BATCH*NH*SL*SL];     // softmax probs fp16

// ---------------- asm helpers -----------------------------------------------
__device__ __forceinline__ uint32_t smem_u32(const void* p){
    uint32_t a;
    asm("{ .reg .u64 t; cvta.to.shared.u64 t, %1; cvt.u32.u64 %0, t; }" : "=r"(a) : "l"(p));
    return a;
}
__device__ __forceinline__ void cpa16(uint32_t d, const void* s){
    asm volatile("cp.async.cg.shared.global [%0], [%1], 16;" :: "r"(d), "l"(s));
}
#define CP_COMMIT() asm volatile("cp.async.commit_group;" ::: "memory")
#define CP_WAIT(n)  asm volatile("cp.async.wait_group %0;" :: "n"(n) : "memory")

#define LDSM4(r0,r1,r2,r3,a) \
    asm volatile("ldmatrix.sync.aligned.m8n8.x4.shared.b16 {%0,%1,%2,%3}, [%4];" \
        : "=r"(r0),"=r"(r1),"=r"(r2),"=r"(r3) : "r"(a))

#define MMA16816(d, a, b0, b1) \
    asm volatile("mma.sync.aligned.m16n8k16.row.col.f32.bf16.bf16.f32 " \
        "{%0,%1,%2,%3},{%4,%5,%6,%7},{%8,%9},{%0,%1,%2,%3};" \
        : "+f"((d)[0]),"+f"((d)[1]),"+f"((d)[2]),"+f"((d)[3]) \
        : "r"((a)[0]),"r"((a)[1]),"r"((a)[2]),"r"((a)[3]),"r"(b0),"r"(b1))

#define MMA16816H(d, a, b0, b1) \
    asm volatile("mma.sync.aligned.m16n8k16.row.col.f32.f16.f16.f32 " \
        "{%0,%1,%2,%3},{%4,%5,%6,%7},{%8,%9},{%0,%1,%2,%3};" \
        : "+f"((d)[0]),"+f"((d)[1]),"+f"((d)[2]),"+f"((d)[3]) \
        : "r"((a)[0]),"r"((a)[1]),"r"((a)[2]),"r"((a)[3]),"r"(b0),"r"(b1))

// ---------------- small kernels ---------------------------------------------
__global__ void k_build_tok(const int* __restrict__ ctx, const int* __restrict__ qry,
                            const int* __restrict__ rsp, const int* __restrict__ c2,
                            const int* __restrict__ cl, const int* __restrict__ ql,
                            const int* __restrict__ rl, const int* __restrict__ c2l)
{
    int idx = blockIdx.x*blockDim.x + threadIdx.x;
    if (idx >= MT) return;
    int b = idx / SL, p = idx % SL;
    int l0 = cl[b], l1 = c2l[b], l2 = ql[b], l3 = rl[b];
    int tok = -1;
    if (p < l0)               tok = ctx[b*S_C + p];
    else if (p < l0+l1)       tok = c2 [b*S_C2 + (p-l0)];
    else if (p < l0+l1+l2)    tok = qry[b*S_Q + (p-l0-l1)];
    else if (p < l0+l1+l2+l3) tok = rsp[b*S_R + (p-l0-l1-l2)];
    g_tok[idx] = tok;
}

__global__ void k_gather(const float* __restrict__ wte)
{
    int idx = blockIdx.x*blockDim.x + threadIdx.x;
    if (idx >= MT*(DM/4)) return;
    int row = idx / (DM/4), c4 = idx % (DM/4);
    int tok = g_tok[row];
    float4 v = make_float4(0.f,0.f,0.f,0.f);
    if (tok >= 0) v = ((const float4*)(wte + (size_t)tok*DM))[c4];
    float vv[4] = {v.x, v.y, v.z, v.w};
    size_t o = (size_t)row*DM + c4*4;
    #pragma unroll
    for (int t=0;t<4;t++){
        bf16 h = __float2bfloat16(vv[t]);
        g_xh[o+t] = h;
        g_xl[o+t] = __float2bfloat16(vv[t] - __bfloat162float(h));
    }
}

__global__ void k_cvt_f16(const float* __restrict__ in, __half* __restrict__ o,
                          int nin, int ntot)
{
    int i = blockIdx.x*blockDim.x + threadIdx.x;
    if (i >= ntot) return;
    float v = (i < nin) ? in[i] : 0.f;
    o[i] = __float2half(v);
}

__global__ void k_cvt(const float* __restrict__ in, bf16* __restrict__ oh,
                      bf16* __restrict__ ol, int nin, int ntot)
{
    int i = blockIdx.x*blockDim.x + threadIdx.x;
    if (i >= ntot) return;
    float v = (i < nin) ? in[i] : 0.f;
    bf16 h = __float2bfloat16(v);
    oh[i] = h;
    ol[i] = __float2bfloat16(v - __bfloat162float(h));
}

// transpose fp32 [Kd, Nd] -> split bf16 [Nd, Kd]
__global__ void k_cvtT(const float* __restrict__ in, bf16* __restrict__ oh,
                       bf16* __restrict__ ol, int Kd, int Nd)
{
    __shared__ float t[32][33];
    int kb = blockIdx.y*32, nb = blockIdx.x*32;
    int tx = threadIdx.x, ty = threadIdx.y;
    #pragma unroll
    for (int i=0;i<32;i+=8)
        t[ty+i][tx] = in[(size_t)(kb+ty+i)*Nd + nb+tx];
    __syncthreads();
    #pragma unroll
    for (int i=0;i<32;i+=8){
        float v = t[tx][ty+i];
        bf16 h = __float2bfloat16(v);
        size_t o = (size_t)(nb+ty+i)*Kd + kb+tx;
        oh[o] = h;
        ol[o] = __float2bfloat16(v - __bfloat162float(h));
    }
}

__global__ void __launch_bounds__(256)
k_ln(const float* __restrict__ in, const float* __restrict__ gm,
     const float* __restrict__ bt, bf16* __restrict__ oh, bf16* __restrict__ ol)
{
    __shared__ float red[256];
    int row = blockIdx.x, tid = threadIdx.x;
    const float* x = in + (size_t)row*DM;
    float v0 = x[tid], v1 = x[tid+256], v2 = x[tid+512];
    red[tid] = v0+v1+v2; __syncthreads();
    for (int o=128;o>0;o>>=1){ if(tid<o) red[tid]+=red[tid+o]; __syncthreads(); }
    float mean = red[0] * (1.f/768.f); __syncthreads();
    float d0=v0-mean, d1=v1-mean, d2=v2-mean;
    red[tid] = d0*d0+d1*d1+d2*d2; __syncthreads();
    for (int o=128;o>0;o>>=1){ if(tid<o) red[tid]+=red[tid+o]; __syncthreads(); }
    float inv = rsqrtf(red[0]*(1.f/768.f) + 1e-5f);
    #pragma unroll
    for (int t=0;t<3;t++){
        int c = tid + t*256;
        float d = (t==0)?d0:((t==1)?d1:d2);
        float y = d*inv*gm[c] + bt[c];
        bf16 h = __float2bfloat16(y);
        size_t o = (size_t)row*DM + c;
        oh[o] = h;
        ol[o] = __float2bfloat16(y - __bfloat162float(h));
    }
}

// final LayerNorm -> fp16 (feeds LM head only)
__global__ void __launch_bounds__(256)
k_ln_f16(const float* __restrict__ in, const float* __restrict__ gm,
         const float* __restrict__ bt, __half* __restrict__ o16)
{
    __shared__ float red[256];
    int row = blockIdx.x, tid = threadIdx.x;
    const float* x = in + (size_t)row*DM;
    float v0 = x[tid], v1 = x[tid+256], v2 = x[tid+512];
    red[tid] = v0+v1+v2; __syncthreads();
    for (int o=128;o>0;o>>=1){ if(tid<o) red[tid]+=red[tid+o]; __syncthreads(); }
    float mean = red[0] * (1.f/768.f); __syncthreads();
    float d0=v0-mean, d1=v1-mean, d2=v2-mean;
    red[tid] = d0*d0+d1*d1+d2*d2; __syncthreads();
    for (int o=128;o>0;o>>=1){ if(tid<o) red[tid]+=red[tid+o]; __syncthreads(); }
    float inv = rsqrtf(red[0]*(1.f/768.f) + 1e-5f);
    #pragma unroll
    for (int t=0;t<3;t++){
        int c = tid + t*256;
        float d = (t==0)?d0:((t==1)?d1:d2);
        o16[(size_t)row*DM + c] = __float2half(d*inv*gm[c] + bt[c]);
    }
}

// ---------------- attention: HMMA scores ------------------------------------
// S[q,k] = Q.K^T / 8, masked; only lower-triangular 128x128 tiles computed.
__global__ void __launch_bounds__(256)
k_scores_h(const int* __restrict__ cl, const int* __restrict__ c2l,
           const int* __restrict__ ql, const int* __restrict__ rl)
{
    int bh = blockIdx.z;
    int q0 = blockIdx.x*128, k0 = blockIdx.y*128;
    if (k0 > q0) return;            // fully masked tile: never read by softmax
    int b = bh / NH;
    int total = cl[b] + c2l[b] + ql[b] + rl[b];

    __shared__ __align__(128) unsigned char smem_buf[32768];
    uint32_t sb = smem_u32(smem_buf);
    int tid = threadIdx.x, w = tid>>5, lane = tid&31;
    int wm = w>>2, wn = w&3;

    const __half* Qb = g_q16 + (size_t)bh*SL*64;
    const __half* Kb = g_k16 + (size_t)bh*SL*64;
    for (int u = tid; u < 1024; u += 256) {
        int r = u>>3, c = u&7;
        uint32_t d = r*128 + ((c ^ (r&7))*16);
        cpa16(sb + d,         Qb + (size_t)(q0+r)*64 + c*8);
        cpa16(sb + 16384 + d, Kb + (size_t)(k0+r)*64 + c*8);
    }
    CP_COMMIT(); CP_WAIT(0);
    __syncthreads();

    float acc[4][4][4];
    #pragma unroll
    for (int mt=0;mt<4;mt++)
        #pragma unroll
        for (int n8=0;n8<4;n8++)
            #pragma unroll
            for (int r=0;r<4;r++) acc[mt][n8][r]=0.f;

    int rr = lane & 15, hf = lane >> 4;
    #pragma unroll
    for (int ks = 0; ks < 4; ks++) {
        uint32_t ah[4][4], bh2[2][4];
        int ch = ks*2 + hf;
        #pragma unroll
        for (int mt=0;mt<4;mt++) {
            int r = wm*64 + mt*16 + rr;
            LDSM4(ah[mt][0],ah[mt][1],ah[mt][2],ah[mt][3], sb + r*128 + ((ch ^ (r&7))*16));
        }
        #pragma unroll
        for (int nt=0;nt<2;nt++) {
            int r = wn*32 + nt*16 + rr;
            LDSM4(bh2[nt][0],bh2[nt][1],bh2[nt][2],bh2[nt][3], sb + 16384 + r*128 + ((ch ^ (r&7))*16));
        }
        #pragma unroll
        for (int mt=0;mt<4;mt++)
            #pragma unroll
            for (int n8=0;n8<4;n8++) {
                int nt = n8 >> 1, p = n8 & 1;
                MMA16816H(acc[mt][n8], ah[mt], bh2[nt][p], bh2[nt][p+2]);
            }
    }

    float* Sb = g_sc + (size_t)bh*SL*SL;
    int qb = q0 + wm*64 + (lane >> 2);
    int kb = k0 + wn*32 + (lane & 3)*2;
    #pragma unroll
    for (int mt=0;mt<4;mt++)
        #pragma unroll
        for (int n8=0;n8<4;n8++)
            #pragma unroll
            for (int half=0; half<2; half++) {
                int qi = qb + mt*16 + half*8;
                int kj = kb + n8*8;
                float v0 = ((kj   <= qi) && (kj   < total)) ? acc[mt][n8][half*2+0]*0.125f : -1e9f;
                float v1 = ((kj+1 <= qi) && (kj+1 < total)) ? acc[mt][n8][half*2+1]*0.125f : -1e9f;
                *(float2*)(Sb + (size_t)qi*SL + kj) = make_float2(v0, v1);
            }
}

// ---------------- softmax: fp32 scores (variable length) -> fp16 probs -------
__global__ void __launch_bounds__(128) k_softmax_h()
{
    __shared__ float red[128];
    int rowid = blockIdx.x;
    int bh = rowid >> 10, q = rowid & 1023;
    const float* S = g_sc + ((size_t)bh*SL + q)*SL;
    __half2* P = (__half2*)(g_p + ((size_t)bh*SL + q)*SL);
    int tile_end = ((q >> 7) + 1) << 7;
    int nch = tile_end >> 2;              // 32..256 float4 chunks
    int tid = threadIdx.x;

    float4 v0 = make_float4(-1e9f,-1e9f,-1e9f,-1e9f), v1 = v0;
    if (tid < nch)      v0 = ((const float4*)S)[tid];
    if (tid+128 < nch)  v1 = ((const float4*)S)[tid+128];
    float m = fmaxf(fmaxf(fmaxf(v0.x,v0.y),fmaxf(v0.z,v0.w)),
                    fmaxf(fmaxf(v1.x,v1.y),fmaxf(v1.z,v1.w)));
    red[tid] = m; __syncthreads();
    for (int o=64;o>0;o>>=1){ if(tid<o) red[tid]=fmaxf(red[tid],red[tid+o]); __syncthreads(); }
    float mx = red[0]; __syncthreads();

    float e0=__expf(v0.x-mx), e1=__expf(v0.y-mx), e2=__expf(v0.z-mx), e3=__expf(v0.w-mx);
    float f0=__expf(v1.x-mx), f1=__expf(v1.y-mx), f2=__expf(v1.z-mx), f3=__expf(v1.w-mx);
    red[tid] = (e0+e1)+(e2+e3) + (f0+f1)+(f2+f3); __syncthreads();
    for (int o=64;o>0;o>>=1){ if(tid<o) red[tid]+=red[tid+o]; __syncthreads(); }
    float inv = 1.f / red[0];

    if (tid < nch) {
        P[tid*2  ] = __floats2half2_rn(e0*inv, e1*inv);
        P[tid*2+1] = __floats2half2_rn(e2*inv, e3*inv);
    }
    if (tid+128 < nch) {
        P[(tid+128)*2  ] = __floats2half2_rn(f0*inv, f1*inv);
        P[(tid+128)*2+1] = __floats2half2_rn(f2*inv, f3*inv);
    }
}

// ---------------- AV: O = P @ V (HMMA, causal chunks) ------------------------
#define AVA 16384            /* A stage: 128 x 64 halves */
#define AVB 8192             /* B stage: 64 x 64 halves */
#define AVST (AVA+AVB)

__global__ void __launch_bounds__(256) k_av_h()
{
    __shared__ __align__(128) unsigned char smem_buf[2*AVST];   // 49152
    uint32_t sb = smem_u32(smem_buf);
    int tid = threadIdx.x;
    int bh = blockIdx.y; int b = bh / NH, hh = bh % NH;
    int q0 = blockIdx.x*128;
    int w = tid>>5, lane = tid&31;
    int wm = w>>2, wn = w&3;

    float acc[4][2][4];
    #pragma unroll
    for (int mt=0;mt<4;mt++)
        #pragma unroll
        for (int n8=0;n8<2;n8++)
            #pragma unroll
            for (int r=0;r<4;r++) acc[mt][n8][r]=0.f;

    const __half* Pb = g_p  + (size_t)bh*SL*SL;
    const __half* Vb = g_vt + (size_t)bh*64*SL;
    int nk = (q0 >> 6) + 2;

    auto load_stage = [&](int s, int k0){
        uint32_t st = sb + s*AVST;
        #pragma unroll 4
        for (int u = tid; u < 1024; u += 256) {
            int r = u>>3, c = u&7;
            cpa16(st + r*128 + ((c ^ (r&7))*16), Pb + (size_t)(q0+r)*SL + k0 + c*8);
        }
        #pragma unroll 2
        for (int u = tid; u < 512; u += 256) {
            int r = u>>3, c = u&7;
            cpa16(st + AVA + r*128 + ((c ^ (r&7))*16), Vb + (size_t)r*SL + k0 + c*8);
        }
        CP_COMMIT();
    };

    load_stage(0, 0);
    int rr = lane & 15, hf = lane >> 4;
    for (int i = 0; i < nk; i++) {
        uint32_t st = sb + (i&1)*AVST;
        if (i + 1 < nk) { load_stage((i+1)&1, (i+1)*64); CP_WAIT(1); }
        else            { CP_WAIT(0); }
        __syncthreads();

        #pragma unroll
        for (int ks = 0; ks < 4; ks++) {
            uint32_t ah[4][4], bv[4];
            int ch = ks*2 + hf;
            #pragma unroll
            for (int mt=0;mt<4;mt++) {
                int r = wm*64 + mt*16 + rr;
                LDSM4(ah[mt][0],ah[mt][1],ah[mt][2],ah[mt][3], st + r*128 + ((ch ^ (r&7))*16));
            }
            {
                int r = wn*16 + rr;
                LDSM4(bv[0],bv[1],bv[2],bv[3], st + AVA + r*128 + ((ch ^ (r&7))*16));
            }
            #pragma unroll
            for (int mt=0;mt<4;mt++) {
                MMA16816H(acc[mt][0], ah[mt], bv[0], bv[2]);
                MMA16816H(acc[mt][1], ah[mt], bv[1], bv[3]);
            }
        }
        __syncthreads();
    }

    int sbase = q0 + wm*64 + (lane >> 2);
    int dbase = wn*16 + (lane & 3)*2;
    #pragma unroll
    for (int mt=0;mt<4;mt++)
        #pragma unroll
        for (int n8=0;n8<2;n8++)
            #pragma unroll
            for (int half=0; half<2; half++) {
                int s = sbase + mt*16 + half*8;
                int d = dbase + n8*8;
                float v0 = acc[mt][n8][half*2+0];
                float v1 = acc[mt][n8][half*2+1];
                size_t o = (size_t)(b*SL + s)*DM + hh*64 + d;
                bf16 h0 = __float2bfloat16(v0), h1 = __float2bfloat16(v1);
                g_ah[o] = h0; g_ah[o+1] = h1;
                g_al[o]   = __float2bfloat16(v0 - __bfloat162float(h0));
                g_al[o+1] = __float2bfloat16(v1 - __bfloat162float(h1));
            }
}

// ---------------- split-bf16 mma.sync GEMM (layer GEMMs) ---------------------
#define KC 64
#define AB (128*128)

template<int BN>
__global__ void __launch_bounds__(256,1)
k_tgemm(const bf16* __restrict__ aH, const bf16* __restrict__ aL,
        const bf16* __restrict__ bH, const bf16* __restrict__ bL,
        const float* __restrict__ bias, const float* __restrict__ wpe,
        float* __restrict__ C, bf16* __restrict__ cH, bf16* __restrict__ cL,
        int K, int Nvalid, int flags)
{
    constexpr int WN  = BN/4;
    constexpr int NT  = WN/16;
    constexpr int N8  = WN/8;
    constexpr int BB  = BN*128;
    constexpr int STG = 2*AB + 2*BB;

    extern __shared__ __align__(128) unsigned char smem_buf[];
    uint32_t sb = smem_u32(smem_buf);
    int tid = threadIdx.x;
    int bm = blockIdx.x * 128;
    int bn = blockIdx.y * BN;

    int w = tid >> 5, lane = tid & 31;
    int wm = w >> 2, wn = w & 3;

    float acc[4][N8][4];
    #pragma unroll
    for (int mt=0;mt<4;mt++)
        #pragma unroll
        for (int n8=0;n8<N8;n8++)
            #pragma unroll
            for (int r=0;r<4;r++) acc[mt][n8][r]=0.f;

    int nk = K / KC;

    auto load_stage = [&](int stage, int k0){
        uint32_t st = sb + stage*STG;
        #pragma unroll 4
        for (int u = tid; u < 128*8; u += 256) {
            int r = u >> 3, c = u & 7;
            uint32_t d = r*128 + ((c ^ (r&7))*16);
            size_t g = (size_t)(bm+r)*K + k0 + c*8;
            cpa16(st + d,      aH + g);
            cpa16(st + AB + d, aL + g);
        }
        #pragma unroll 4
        for (int u = tid; u < BN*8; u += 256) {
            int r = u >> 3, c = u & 7;
            uint32_t d = r*128 + ((c ^ (r&7))*16);
            size_t g = (size_t)(bn+r)*K + k0 + c*8;
            cpa16(st + 2*AB + d,      bH + g);
            cpa16(st + 2*AB + BB + d, bL + g);
        }
        CP_COMMIT();
    };

    load_stage(0, 0);

    int rr = lane & 15, hf = lane >> 4;
    for (int i = 0; i < nk; i++) {
        uint32_t st = sb + (i & 1)*STG;
        if (i + 1 < nk) { load_stage((i+1)&1, (i+1)*KC); CP_WAIT(1); }
        else            { CP_WAIT(0); }
        __syncthreads();

        #pragma unroll
        for (int ks = 0; ks < 4; ks++) {
            uint32_t ah[4][4], al[4][4], bh[NT][4], bl[NT][4];
            int ch = ks*2 + hf;
            #pragma unroll
            for (int mt=0;mt<4;mt++) {
                int r = wm*64 + mt*16 + rr;
                uint32_t ra = st + r*128 + ((ch ^ (r&7))*16);
                LDSM4(ah[mt][0],ah[mt][1],ah[mt][2],ah[mt][3], ra);
                LDSM4(al[mt][0],al[mt][1],al[mt][2],al[mt][3], ra + AB);
            }
            #pragma unroll
            for (int nt=0;nt<NT;nt++) {
                int r = wn*WN + nt*16 + rr;
                uint32_t rb = st + 2*AB + r*128 + ((ch ^ (r&7))*16);
                LDSM4(bh[nt][0],bh[nt][1],bh[nt][2],bh[nt][3], rb);
                LDSM4(bl[nt][0],bl[nt][1],bl[nt][2],bl[nt][3], rb + BB);
            }
            #pragma unroll
            for (int mt=0;mt<4;mt++) {
                #pragma unroll
                for (int n8=0;n8<N8;n8++) {
                    int nt = n8 >> 1, p = n8 & 1;
                    MMA16816(acc[mt][n8], ah[mt], bh[nt][p], bh[nt][p+2]);
                    MMA16816(acc[mt][n8], ah[mt], bl[nt][p], bl[nt][p+2]);
                    MMA16816(acc[mt][n8], al[mt], bh[nt][p], bh[nt][p+2]);
                }
            }
        }
        __syncthreads();
    }

    int r0b = bm + wm*64 + (lane >> 2);
    int c0b = bn + wn*WN + (lane & 3)*2;
    #pragma unroll
    for (int mt=0;mt<4;mt++) {
        #pragma unroll
        for (int n8=0;n8<N8;n8++) {
            #pragma unroll
            for (int half=0; half<2; half++) {
                int r = r0b + mt*16 + half*8;
                int c = c0b + n8*8;
                float v0 = acc[mt][n8][half*2+0];
                float v1 = acc[mt][n8][half*2+1];
                if (bias) { v0 += bias[c]; v1 += bias[c+1]; }
                if (flags & GF_WPE) {
                    const float* wp = wpe + (size_t)(r & (SL-1))*DM + c;
                    v0 += wp[0]; v1 += wp[1];
                }
                if (flags & GF_QKV) {
                    int sec = c / DM;
                    int cc = c - sec*DM;
                    int hh = cc >> 6, d = cc & 63;
                    int bb2 = r >> 10, s = r & (SL-1);
                    if (sec < 2) {
                        __half* dst = (sec == 0 ? g_q16 : g_k16)
                                      + (((size_t)(bb2*NH + hh)*SL + s) << 6) + d;
                        *(__half2*)dst = __floats2half2_rn(v0, v1);
                    } else {
                        __half* dst = g_vt + ((size_t)(bb2*NH + hh)*64 + d)*SL + s;
                        dst[0]  = __float2half(v0);
                        dst[SL] = __float2half(v1);
                    }
                    continue;
                }
                size_t o = (size_t)r*Nvalid + c;
                if (flags & GF_GELU) {
                    float u0=v0, u1=v1;
                    v0 = 0.5f*u0*(1.f + tanhf(0.7978845608028654f*(u0 + 0.044715f*u0*u0*u0)));
                    v1 = 0.5f*u1*(1.f + tanhf(0.7978845608028654f*(u1 + 0.044715f*u1*u1*u1)));
                    bf16 h0 = __float2bfloat16(v0), h1 = __float2bfloat16(v1);
                    cH[o] = h0; cH[o+1] = h1;
                    cL[o]   = __float2bfloat16(v0 - __bfloat162float(h0));
                    cL[o+1] = __float2bfloat16(v1 - __bfloat162float(h1));
                } else if (flags & GF_RESID) {
                    float2 old = *(float2*)(C + o);
                    old.x += v0; old.y += v1;
                    *(float2*)(C + o) = old;
                } else {
                    C[o] = v0; C[o+1] = v1;
                }
            }
        }
    }
}

#define SMEM256 (2*(2*AB + 2*256*128))   /* 196608 */
#define SMEM128 (2*(2*AB + 2*128*128))   /* 131072 */

// ---------------- fp16 single-pass GEMM (LM head) ----------------------------
#define HAB (128*128)
#define HBB (256*128)
#define HSTG (HAB+HBB)
#define SMEMH (3*HSTG)

__global__ void __launch_bounds__(256,1)
k_hgemm(const __half* __restrict__ Af, const __half* __restrict__ Bf,
        float* __restrict__ C, int K, int Nvalid)
{
    extern __shared__ __align__(128) unsigned char smem_buf[];
    uint32_t sb = smem_u32(smem_buf);
    int tid = threadIdx.x;
    int bm = blockIdx.x * 128;
    int bn = blockIdx.y * 256;

    int w = tid >> 5, lane = tid & 31;
    int wm = w >> 2, wn = w & 3;

    float acc[4][8][4];
    #pragma unroll
    for (int mt=0;mt<4;mt++)
        #pragma unroll
        for (int n8=0;n8<8;n8++)
            #pragma unroll
            for (int r=0;r<4;r++) acc[mt][n8][r]=0.f;

    int nk = K / KC;

    auto load_stage = [&](int stage, int k0){
        uint32_t st = sb + stage*HSTG;
        #pragma unroll 4
        for (int u = tid; u < 128*8; u += 256) {
            int r = u >> 3, c = u & 7;
            uint32_t d = r*128 + ((c ^ (r&7))*16);
            cpa16(st + d, Af + (size_t)(bm+r)*K + k0 + c*8);
        }
        #pragma unroll 8
        for (int u = tid; u < 256*8; u += 256) {
            int r = u >> 3, c = u & 7;
            uint32_t d = r*128 + ((c ^ (r&7))*16);
            cpa16(st + HAB + d, Bf + (size_t)(bn+r)*K + k0 + c*8);
        }
        CP_COMMIT();
    };

    load_stage(0, 0);
    if (nk > 1) load_stage(1, KC);

    int rr = lane & 15, hf = lane >> 4;
    int stage = 0;
    for (int i = 0; i < nk; i++) {
        if (i + 2 < nk) { load_stage((stage+2)%3, (i+2)*KC); CP_WAIT(2); }
        else if (i + 1 < nk) { CP_WAIT(1); }
        else { CP_WAIT(0); }
        __syncthreads();

        uint32_t st = sb + stage*HSTG;
        #pragma unroll
        for (int ks = 0; ks < 4; ks++) {
            uint32_t ah[4][4], bh[4][4];
            int ch = ks*2 + hf;
            #pragma unroll
            for (int mt=0;mt<4;mt++) {
                int r = wm*64 + mt*16 + rr;
                LDSM4(ah[mt][0],ah[mt][1],ah[mt][2],ah[mt][3], st + r*128 + ((ch ^ (r&7))*16));
            }
            #pragma unroll
            for (int nt=0;nt<4;nt++) {
                int r = wn*64 + nt*16 + rr;
                LDSM4(bh[nt][0],bh[nt][1],bh[nt][2],bh[nt][3], st + HAB + r*128 + ((ch ^ (r&7))*16));
            }
            #pragma unroll
            for (int mt=0;mt<4;mt++) {
                #pragma unroll
                for (int n8=0;n8<8;n8++) {
                    int nt = n8 >> 1, p = n8 & 1;
                    MMA16816H(acc[mt][n8], ah[mt], bh[nt][p], bh[nt][p+2]);
                }
            }
        }
        __syncthreads();
        stage = (stage + 1) % 3;
    }

    int r0b = bm + wm*64 + (lane >> 2);
    int c0b = bn + wn*64 + (lane & 3)*2;
    #pragma unroll
    for (int mt=0;mt<4;mt++) {
        #pragma unroll
        for (int n8=0;n8<8;n8++) {
            int c = c0b + n8*8;
            #pragma unroll
            for (int half=0; half<2; half++) {
                int r = r0b + mt*16 + half*8;
                size_t o = (size_t)r*Nvalid + c;
                if (c + 1 < Nvalid) {
                    C[o]   = acc[mt][n8][half*2+0];
                    C[o+1] = acc[mt][n8][half*2+1];
                } else if (c < Nvalid) {
                    C[o]   = acc[mt][n8][half*2+0];
                }
            }
        }
    }
}

// ---------------- launch ----------------------------------------------------
extern "C" void kernel_launch(void* const* d_in, const int* in_sizes, int n_in,
                              void* d_out, int out_size)
{
    const int*   ctx  = (const int*)  d_in[0];
    const int*   qry  = (const int*)  d_in[1];
    const int*   rsp  = (const int*)  d_in[2];
    const int*   c2   = (const int*)  d_in[3];
    const int*   cl   = (const int*)  d_in[4];
    const int*   ql   = (const int*)  d_in[5];
    const int*   rl   = (const int*)  d_in[6];
    const int*   c2l  = (const int*)  d_in[7];
    const float* wte  = (const float*)d_in[8];
    const float* wpe  = (const float*)d_in[9];
    const float* ln1g = (const float*)d_in[10];
    const float* ln1b = (const float*)d_in[11];
    const float* wqkv = (const float*)d_in[12];
    const float* bqkv = (const float*)d_in[13];
    const float* wo   = (const float*)d_in[14];
    const float* bo   = (const float*)d_in[15];
    const float* ln2g = (const float*)d_in[16];
    const float* ln2b = (const float*)d_in[17];
    const float* wfc  = (const float*)d_in[18];
    const float* bfc  = (const float*)d_in[19];
    const float* wpr  = (const float*)d_in[20];
    const float* bpr  = (const float*)d_in[21];
    const float* lnfg = (const float*)d_in[22];
    const float* lnfb = (const float*)d_in[23];
    const float* llw  = (const float*)d_in[24];
    const float* llb  = (const float*)d_in[25];
    float* out = (float*)d_out;

    cudaFuncSetAttribute(k_tgemm<256>, cudaFuncAttributeMaxDynamicSharedMemorySize, SMEM256);
    cudaFuncSetAttribute(k_tgemm<128>, cudaFuncAttributeMaxDynamicSharedMemorySize, SMEM128);
    cudaFuncSetAttribute(k_hgemm,      cudaFuncAttributeMaxDynamicSharedMemorySize, SMEMH);

    float *ph;
    bf16 *xh, *xl, *ah, *al, *fh, *fl;
    bf16 *qwh, *qwl, *owh, *owl, *fwh, *fwl, *pwh, *pwl, *lwh, *lwl;
    __half *xf, *wtf;
    cudaGetSymbolAddress((void**)&ph,   g_h);
    cudaGetSymbolAddress((void**)&xh,  g_xh);  cudaGetSymbolAddress((void**)&xl,  g_xl);
    cudaGetSymbolAddress((void**)&ah,  g_ah);  cudaGetSymbolAddress((void**)&al,  g_al);
    cudaGetSymbolAddress((void**)&fh,  g_fh);  cudaGetSymbolAddress((void**)&fl,  g_fl);
    cudaGetSymbolAddress((void**)&qwh, g_qwh); cudaGetSymbolAddress((void**)&qwl, g_qwl);
    cudaGetSymbolAddress((void**)&owh, g_owh); cudaGetSymbolAddress((void**)&owl, g_owl);
    cudaGetSymbolAddress((void**)&fwh, g_fwh); cudaGetSymbolAddress((void**)&fwl, g_fwl);
    cudaGetSymbolAddress((void**)&pwh, g_pwh); cudaGetSymbolAddress((void**)&pwl, g_pwl);
    cudaGetSymbolAddress((void**)&lwh, g_lwh); cudaGetSymbolAddress((void**)&lwl, g_lwl);
    cudaGetSymbolAddress((void**)&xf,  g_xf);  cudaGetSymbolAddress((void**)&wtf, g_wtf);

    // ---- weight conversions ----
    k_cvt_f16<<<(NVP*DM+255)/256, 256>>>(wte, wtf, NVOC*DM, NVP*DM);
    k_cvt<<<(DM*DM+255)/256, 256>>>(llw, lwh, lwl, DM*DM, DM*DM);
    for (int l = 0; l < NLAY; l++) {
        k_cvtT<<<dim3(3*DM/32, DM/32), dim3(32,8)>>>(wqkv + (size_t)l*DM*3*DM,
                                                     qwh + (size_t)l*3*DM*DM, qwl + (size_t)l*3*DM*DM, DM, 3*DM);
        k_cvtT<<<dim3(DM/32, DM/32), dim3(32,8)>>>(wo + (size_t)l*DM*DM,
                                                   owh + (size_t)l*DM*DM, owl + (size_t)l*DM*DM, DM, DM);
        k_cvtT<<<dim3(FF/32, DM/32), dim3(32,8)>>>(wfc + (size_t)l*DM*FF,
                                                   fwh + (size_t)l*FF*DM, fwl + (size_t)l*FF*DM, DM, FF);
        k_cvtT<<<dim3(DM/32, FF/32), dim3(32,8)>>>(wpr + (size_t)l*FF*DM,
                                                   pwh + (size_t)l*DM*FF, pwl + (size_t)l*DM*FF, FF, DM);
    }

    // ---- embeddings ----
    k_build_tok<<<(MT+255)/256, 256>>>(ctx, qry, rsp, c2, cl, ql, rl, c2l);
    k_gather<<<(MT*(DM/4)+255)/256, 256>>>(wte);

    // h = emb @ ll_w^T + ll_b + wpe
    k_tgemm<128><<<dim3(MT/128, DM/128), 256, SMEM128>>>(xh, xl, lwh, lwl, llb, wpe,
                                                         ph, nullptr, nullptr, DM, DM, GF_WPE);

    for (int l = 0; l < NLAY; l++) {
        k_ln<<<MT, 256>>>(ph, ln1g + l*DM, ln1b + l*DM, xh, xl);
        // qkv -> fp16 Q,K head-major + V^T directly (GF_QKV epilogue)
        k_tgemm<256><<<dim3(MT/128, 3*DM/256), 256, SMEM256>>>(xh, xl,
            qwh + (size_t)l*3*DM*DM, qwl + (size_t)l*3*DM*DM, bqkv + l*3*DM, nullptr,
            nullptr, nullptr, nullptr, DM, 3*DM, GF_QKV);
        k_scores_h<<<dim3(SL/128, SL/128, BATCH*NH), 256>>>(cl, c2l, ql, rl);
        k_softmax_h<<<BATCH*NH*SL, 128>>>();
        k_av_h<<<dim3(SL/128, BATCH*NH), 256>>>();
        k_tgemm<128><<<dim3(MT/128, DM/128), 256, SMEM128>>>(ah, al,
            owh + (size_t)l*DM*DM, owl + (size_t)l*DM*DM, bo + l*DM, nullptr,
            ph, nullptr, nullptr, DM, DM, GF_RESID);
        k_ln<<<MT, 256>>>(ph, ln2g + l*DM, ln2b + l*DM, xh, xl);
        k_tgemm<256><<<dim3(MT/128, FF/256), 256, SMEM256>>>(xh, xl,
            fwh + (size_t)l*FF*DM, fwl + (size_t)l*FF*DM, bfc + l*FF, nullptr,
            nullptr, fh, fl, DM, FF, GF_GELU);
        k_tgemm<128><<<dim3(MT/128, DM/128), 256, SMEM128>>>(fh, fl,
            pwh + (size_t)l*DM*FF, pwl + (size_t)l*DM*FF, bpr + l*DM, nullptr,
            ph, nullptr, nullptr, FF, DM, GF_RESID);
    }

    k_ln_f16<<<MT, 256>>>(ph, lnfg, lnfb, xf);

    // logits = x @ wte^T  (fp16 single-pass)
    k_hgemm<<<dim3(MT/128, NVP/256), 256, SMEMH>>>(xf, wtf, out, DM, NVOC);
}

// round 10
// speedup vs baseline: 5.2736x; 1.3508x over previous
#include <cuda_runtime.h>
#include <cuda_bf16.h>
#include <cuda_fp16.h>
#include <math.h>
#include <stdint.h>

#define BATCH 4
#define SL    1024
#define DM    768
#define NH    12
#define FF    3072
#define NVOC  50257
#define NVP   50432
#define MT    (BATCH*SL)
#define NLAY  2

#define S_C   512
#define S_C2  256
#define S_Q   128
#define S_R   128

#define GF_RESID 1
#define GF_GELU  2
#define GF_WPE   4
#define GF_QKV   8

typedef __nv_bfloat16 bf16;

// ---------------- scratch ---------------------------------------------------
__device__ float g_h[MT*DM];
__device__ float g_sc[(size_t)BATCH*NH*SL*SL];
__device__ int   g_tok[MT];

__device__ bf16 g_xh[MT*DM], g_xl[MT*DM];            // emb split (ll GEMM)
__device__ bf16 g_lwh[DM*DM], g_lwl[DM*DM];          // ll_w split

__device__ __half g_x16[MT*DM];                      // LN outputs fp16
__device__ __half g_a16[MT*DM];                      // attention out fp16
__device__ __half g_f16[(size_t)MT*FF];              // MLP hidden fp16
__device__ __half g_wtf[(size_t)NVP*DM];             // wte fp16 (padded)
__device__ __half g_qw16[NLAY*3*DM*DM];              // wqkv^T fp16
__device__ __half g_ow16[NLAY*DM*DM];                // wo^T fp16
__device__ __half g_fw16[NLAY*FF*DM];                // wfc^T fp16
__device__ __half g_pw16[NLAY*DM*FF];                // wpr^T fp16
__device__ __half g_q16[(size_t)BATCH*NH*SL*64];     // Q head-major fp16
__device__ __half g_k16[(size_t)BATCH*NH*SL*64];     // K head-major fp16
__device__ __half g_vt [(size_t)BATCH*NH*64*SL];     // V^T fp16
__device__ __half g_p  [(size_t)BATCH*NH*SL*SL];     // softmax probs fp16

// ---------------- asm helpers -----------------------------------------------
__device__ __forceinline__ uint32_t smem_u32(const void* p){
    uint32_t a;
    asm("{ .reg .u64 t; cvta.to.shared.u64 t, %1; cvt.u32.u64 %0, t; }" : "=r"(a) : "l"(p));
    return a;
}
__device__ __forceinline__ void cpa16(uint32_t d, const void* s){
    asm volatile("cp.async.cg.shared.global [%0], [%1], 16;" :: "r"(d), "l"(s));
}
#define CP_COMMIT() asm volatile("cp.async.commit_group;" ::: "memory")
#define CP_WAIT(n)  asm volatile("cp.async.wait_group %0;" :: "n"(n) : "memory")

#define LDSM4(r0,r1,r2,r3,a) \
    asm volatile("ldmatrix.sync.aligned.m8n8.x4.shared.b16 {%0,%1,%2,%3}, [%4];" \
        : "=r"(r0),"=r"(r1),"=r"(r2),"=r"(r3) : "r"(a))

#define MMA16816(d, a, b0, b1) \
    asm volatile("mma.sync.aligned.m16n8k16.row.col.f32.bf16.bf16.f32 " \
        "{%0,%1,%2,%3},{%4,%5,%6,%7},{%8,%9},{%0,%1,%2,%3};" \
        : "+f"((d)[0]),"+f"((d)[1]),"+f"((d)[2]),"+f"((d)[3]) \
        : "r"((a)[0]),"r"((a)[1]),"r"((a)[2]),"r"((a)[3]),"r"(b0),"r"(b1))

#define MMA16816H(d, a, b0, b1) \
    asm volatile("mma.sync.aligned.m16n8k16.row.col.f32.f16.f16.f32 " \
        "{%0,%1,%2,%3},{%4,%5,%6,%7},{%8,%9},{%0,%1,%2,%3};" \
        : "+f"((d)[0]),"+f"((d)[1]),"+f"((d)[2]),"+f"((d)[3]) \
        : "r"((a)[0]),"r"((a)[1]),"r"((a)[2]),"r"((a)[3]),"r"(b0),"r"(b1))

// ---------------- small kernels ---------------------------------------------
__global__ void k_build_tok(const int* __restrict__ ctx, const int* __restrict__ qry,
                            const int* __restrict__ rsp, const int* __restrict__ c2,
                            const int* __restrict__ cl, const int* __restrict__ ql,
                            const int* __restrict__ rl, const int* __restrict__ c2l)
{
    int idx = blockIdx.x*blockDim.x + threadIdx.x;
    if (idx >= MT) return;
    int b = idx / SL, p = idx % SL;
    int l0 = cl[b], l1 = c2l[b], l2 = ql[b], l3 = rl[b];
    int tok = -1;
    if (p < l0)               tok = ctx[b*S_C + p];
    else if (p < l0+l1)       tok = c2 [b*S_C2 + (p-l0)];
    else if (p < l0+l1+l2)    tok = qry[b*S_Q + (p-l0-l1)];
    else if (p < l0+l1+l2+l3) tok = rsp[b*S_R + (p-l0-l1-l2)];
    g_tok[idx] = tok;
}

__global__ void k_gather(const float* __restrict__ wte)
{
    int idx = blockIdx.x*blockDim.x + threadIdx.x;
    if (idx >= MT*(DM/4)) return;
    int row = idx / (DM/4), c4 = idx % (DM/4);
    int tok = g_tok[row];
    float4 v = make_float4(0.f,0.f,0.f,0.f);
    if (tok >= 0) v = ((const float4*)(wte + (size_t)tok*DM))[c4];
    float vv[4] = {v.x, v.y, v.z, v.w};
    size_t o = (size_t)row*DM + c4*4;
    #pragma unroll
    for (int t=0;t<4;t++){
        bf16 h = __float2bfloat16(vv[t]);
        g_xh[o+t] = h;
        g_xl[o+t] = __float2bfloat16(vv[t] - __bfloat162float(h));
    }
}

__global__ void k_cvt_f16(const float* __restrict__ in, __half* __restrict__ o,
                          int nin, int ntot)
{
    int i = blockIdx.x*blockDim.x + threadIdx.x;
    if (i >= ntot) return;
    float v = (i < nin) ? in[i] : 0.f;
    o[i] = __float2half(v);
}

__global__ void k_cvt(const float* __restrict__ in, bf16* __restrict__ oh,
                      bf16* __restrict__ ol, int nin, int ntot)
{
    int i = blockIdx.x*blockDim.x + threadIdx.x;
    if (i >= ntot) return;
    float v = (i < nin) ? in[i] : 0.f;
    bf16 h = __float2bfloat16(v);
    oh[i] = h;
    ol[i] = __float2bfloat16(v - __bfloat162float(h));
}

// transpose fp32 [Kd, Nd] -> fp16 [Nd, Kd]
__global__ void k_cvtT_f16(const float* __restrict__ in, __half* __restrict__ o,
                           int Kd, int Nd)
{
    __shared__ float t[32][33];
    int kb = blockIdx.y*32, nb = blockIdx.x*32;
    int tx = threadIdx.x, ty = threadIdx.y;
    #pragma unroll
    for (int i=0;i<32;i+=8)
        t[ty+i][tx] = in[(size_t)(kb+ty+i)*Nd + nb+tx];
    __syncthreads();
    #pragma unroll
    for (int i=0;i<32;i+=8)
        o[(size_t)(nb+ty+i)*Kd + kb+tx] = __float2half(t[tx][ty+i]);
}

// LayerNorm fp32 -> fp16
__global__ void __launch_bounds__(256)
k_ln_f16(const float* __restrict__ in, const float* __restrict__ gm,
         const float* __restrict__ bt, __half* __restrict__ o16)
{
    __shared__ float red[256];
    int row = blockIdx.x, tid = threadIdx.x;
    const float* x = in + (size_t)row*DM;
    float v0 = x[tid], v1 = x[tid+256], v2 = x[tid+512];
    red[tid] = v0+v1+v2; __syncthreads();
    for (int o=128;o>0;o>>=1){ if(tid<o) red[tid]+=red[tid+o]; __syncthreads(); }
    float mean = red[0] * (1.f/768.f); __syncthreads();
    float d0=v0-mean, d1=v1-mean, d2=v2-mean;
    red[tid] = d0*d0+d1*d1+d2*d2; __syncthreads();
    for (int o=128;o>0;o>>=1){ if(tid<o) red[tid]+=red[tid+o]; __syncthreads(); }
    float inv = rsqrtf(red[0]*(1.f/768.f) + 1e-5f);
    #pragma unroll
    for (int t=0;t<3;t++){
        int c = tid + t*256;
        float d = (t==0)?d0:((t==1)?d1:d2);
        o16[(size_t)row*DM + c] = __float2half(d*inv*gm[c] + bt[c]);
    }
}

// ---------------- attention: HMMA scores ------------------------------------
__global__ void __launch_bounds__(256)
k_scores_h(const int* __restrict__ cl, const int* __restrict__ c2l,
           const int* __restrict__ ql, const int* __restrict__ rl)
{
    int bh = blockIdx.z;
    int q0 = blockIdx.x*128, k0 = blockIdx.y*128;
    if (k0 > q0) return;
    int b = bh / NH;
    int total = cl[b] + c2l[b] + ql[b] + rl[b];

    __shared__ __align__(128) unsigned char smem_buf[32768];
    uint32_t sb = smem_u32(smem_buf);
    int tid = threadIdx.x, w = tid>>5, lane = tid&31;
    int wm = w>>2, wn = w&3;

    const __half* Qb = g_q16 + (size_t)bh*SL*64;
    const __half* Kb = g_k16 + (size_t)bh*SL*64;
    for (int u = tid; u < 1024; u += 256) {
        int r = u>>3, c = u&7;
        uint32_t d = r*128 + ((c ^ (r&7))*16);
        cpa16(sb + d,         Qb + (size_t)(q0+r)*64 + c*8);
        cpa16(sb + 16384 + d, Kb + (size_t)(k0+r)*64 + c*8);
    }
    CP_COMMIT(); CP_WAIT(0);
    __syncthreads();

    float acc[4][4][4];
    #pragma unroll
    for (int mt=0;mt<4;mt++)
        #pragma unroll
        for (int n8=0;n8<4;n8++)
            #pragma unroll
            for (int r=0;r<4;r++) acc[mt][n8][r]=0.f;

    int rr = lane & 15, hf = lane >> 4;
    #pragma unroll
    for (int ks = 0; ks < 4; ks++) {
        uint32_t ah[4][4], bh2[2][4];
        int ch = ks*2 + hf;
        #pragma unroll
        for (int mt=0;mt<4;mt++) {
            int r = wm*64 + mt*16 + rr;
            LDSM4(ah[mt][0],ah[mt][1],ah[mt][2],ah[mt][3], sb + r*128 + ((ch ^ (r&7))*16));
        }
        #pragma unroll
        for (int nt=0;nt<2;nt++) {
            int r = wn*32 + nt*16 + rr;
            LDSM4(bh2[nt][0],bh2[nt][1],bh2[nt][2],bh2[nt][3], sb + 16384 + r*128 + ((ch ^ (r&7))*16));
        }
        #pragma unroll
        for (int mt=0;mt<4;mt++)
            #pragma unroll
            for (int n8=0;n8<4;n8++) {
                int nt = n8 >> 1, p = n8 & 1;
                MMA16816H(acc[mt][n8], ah[mt], bh2[nt][p], bh2[nt][p+2]);
            }
    }

    float* Sb = g_sc + (size_t)bh*SL*SL;
    int qb = q0 + wm*64 + (lane >> 2);
    int kb = k0 + wn*32 + (lane & 3)*2;
    #pragma unroll
    for (int mt=0;mt<4;mt++)
        #pragma unroll
        for (int n8=0;n8<4;n8++)
            #pragma unroll
            for (int half=0; half<2; half++) {
                int qi = qb + mt*16 + half*8;
                int kj = kb + n8*8;
                float v0 = ((kj   <= qi) && (kj   < total)) ? acc[mt][n8][half*2+0]*0.125f : -1e9f;
                float v1 = ((kj+1 <= qi) && (kj+1 < total)) ? acc[mt][n8][half*2+1]*0.125f : -1e9f;
                *(float2*)(Sb + (size_t)qi*SL + kj) = make_float2(v0, v1);
            }
}

// ---------------- softmax ----------------------------------------------------
__global__ void __launch_bounds__(128) k_softmax_h()
{
    __shared__ float red[128];
    int rowid = blockIdx.x;
    int bh = rowid >> 10, q = rowid & 1023;
    const float* S = g_sc + ((size_t)bh*SL + q)*SL;
    __half2* P = (__half2*)(g_p + ((size_t)bh*SL + q)*SL);
    int tile_end = ((q >> 7) + 1) << 7;
    int nch = tile_end >> 2;
    int tid = threadIdx.x;

    float4 v0 = make_float4(-1e9f,-1e9f,-1e9f,-1e9f), v1 = v0;
    if (tid < nch)      v0 = ((const float4*)S)[tid];
    if (tid+128 < nch)  v1 = ((const float4*)S)[tid+128];
    float m = fmaxf(fmaxf(fmaxf(v0.x,v0.y),fmaxf(v0.z,v0.w)),
                    fmaxf(fmaxf(v1.x,v1.y),fmaxf(v1.z,v1.w)));
    red[tid] = m; __syncthreads();
    for (int o=64;o>0;o>>=1){ if(tid<o) red[tid]=fmaxf(red[tid],red[tid+o]); __syncthreads(); }
    float mx = red[0]; __syncthreads();

    float e0=__expf(v0.x-mx), e1=__expf(v0.y-mx), e2=__expf(v0.z-mx), e3=__expf(v0.w-mx);
    float f0=__expf(v1.x-mx), f1=__expf(v1.y-mx), f2=__expf(v1.z-mx), f3=__expf(v1.w-mx);
    red[tid] = (e0+e1)+(e2+e3) + (f0+f1)+(f2+f3); __syncthreads();
    for (int o=64;o>0;o>>=1){ if(tid<o) red[tid]+=red[tid+o]; __syncthreads(); }
    float inv = 1.f / red[0];

    if (tid < nch) {
        P[tid*2  ] = __floats2half2_rn(e0*inv, e1*inv);
        P[tid*2+1] = __floats2half2_rn(e2*inv, e3*inv);
    }
    if (tid+128 < nch) {
        P[(tid+128)*2  ] = __floats2half2_rn(f0*inv, f1*inv);
        P[(tid+128)*2+1] = __floats2half2_rn(f2*inv, f3*inv);
    }
}

// ---------------- AV ----------------------------------------------------------
#define AVA 16384
#define AVB 8192
#define AVST (AVA+AVB)

__global__ void __launch_bounds__(256) k_av_h()
{
    __shared__ __align__(128) unsigned char smem_buf[2*AVST];
    uint32_t sb = smem_u32(smem_buf);
    int tid = threadIdx.x;
    int bh = blockIdx.y; int b = bh / NH, hh = bh % NH;
    int q0 = blockIdx.x*128;
    int w = tid>>5, lane = tid&31;
    int wm = w>>2, wn = w&3;

    float acc[4][2][4];
    #pragma unroll
    for (int mt=0;mt<4;mt++)
        #pragma unroll
        for (int n8=0;n8<2;n8++)
            #pragma unroll
            for (int r=0;r<4;r++) acc[mt][n8][r]=0.f;

    const __half* Pb = g_p  + (size_t)bh*SL*SL;
    const __half* Vb = g_vt + (size_t)bh*64*SL;
    int nk = (q0 >> 6) + 2;

    auto load_stage = [&](int s, int k0){
        uint32_t st = sb + s*AVST;
        #pragma unroll 4
        for (int u = tid; u < 1024; u += 256) {
            int r = u>>3, c = u&7;
            cpa16(st + r*128 + ((c ^ (r&7))*16), Pb + (size_t)(q0+r)*SL + k0 + c*8);
        }
        #pragma unroll 2
        for (int u = tid; u < 512; u += 256) {
            int r = u>>3, c = u&7;
            cpa16(st + AVA + r*128 + ((c ^ (r&7))*16), Vb + (size_t)r*SL + k0 + c*8);
        }
        CP_COMMIT();
    };

    load_stage(0, 0);
    int rr = lane & 15, hf = lane >> 4;
    for (int i = 0; i < nk; i++) {
        uint32_t st = sb + (i&1)*AVST;
        if (i + 1 < nk) { load_stage((i+1)&1, (i+1)*64); CP_WAIT(1); }
        else            { CP_WAIT(0); }
        __syncthreads();

        #pragma unroll
        for (int ks = 0; ks < 4; ks++) {
            uint32_t ah[4][4], bv[4];
            int ch = ks*2 + hf;
            #pragma unroll
            for (int mt=0;mt<4;mt++) {
                int r = wm*64 + mt*16 + rr;
                LDSM4(ah[mt][0],ah[mt][1],ah[mt][2],ah[mt][3], st + r*128 + ((ch ^ (r&7))*16));
            }
            {
                int r = wn*16 + rr;
                LDSM4(bv[0],bv[1],bv[2],bv[3], st + AVA + r*128 + ((ch ^ (r&7))*16));
            }
            #pragma unroll
            for (int mt=0;mt<4;mt++) {
                MMA16816H(acc[mt][0], ah[mt], bv[0], bv[2]);
                MMA16816H(acc[mt][1], ah[mt], bv[1], bv[3]);
            }
        }
        __syncthreads();
    }

    int sbase = q0 + wm*64 + (lane >> 2);
    int dbase = wn*16 + (lane & 3)*2;
    #pragma unroll
    for (int mt=0;mt<4;mt++)
        #pragma unroll
        for (int n8=0;n8<2;n8++)
            #pragma unroll
            for (int half=0; half<2; half++) {
                int s = sbase + mt*16 + half*8;
                int d = dbase + n8*8;
                size_t o = (size_t)(b*SL + s)*DM + hh*64 + d;
                *(__half2*)(g_a16 + o) =
                    __floats2half2_rn(acc[mt][n8][half*2+0], acc[mt][n8][half*2+1]);
            }
}

// ---------------- split-bf16 GEMM (ll only) ----------------------------------
#define KC 64
#define AB (128*128)

template<int BN>
__global__ void __launch_bounds__(256,1)
k_tgemm(const bf16* __restrict__ aH, const bf16* __restrict__ aL,
        const bf16* __restrict__ bH, const bf16* __restrict__ bL,
        const float* __restrict__ bias, const float* __restrict__ wpe,
        float* __restrict__ C, int K, int Nvalid, int flags)
{
    constexpr int WN  = BN/4;
    constexpr int NT  = WN/16;
    constexpr int N8  = WN/8;
    constexpr int BB  = BN*128;
    constexpr int STG = 2*AB + 2*BB;

    extern __shared__ __align__(128) unsigned char smem_buf[];
    uint32_t sb = smem_u32(smem_buf);
    int tid = threadIdx.x;
    int bm = blockIdx.x * 128;
    int bn = blockIdx.y * BN;

    int w = tid >> 5, lane = tid & 31;
    int wm = w >> 2, wn = w & 3;

    float acc[4][N8][4];
    #pragma unroll
    for (int mt=0;mt<4;mt++)
        #pragma unroll
        for (int n8=0;n8<N8;n8++)
            #pragma unroll
            for (int r=0;r<4;r++) acc[mt][n8][r]=0.f;

    int nk = K / KC;

    auto load_stage = [&](int stage, int k0){
        uint32_t st = sb + stage*STG;
        #pragma unroll 4
        for (int u = tid; u < 128*8; u += 256) {
            int r = u >> 3, c = u & 7;
            uint32_t d = r*128 + ((c ^ (r&7))*16);
            size_t g = (size_t)(bm+r)*K + k0 + c*8;
            cpa16(st + d,      aH + g);
            cpa16(st + AB + d, aL + g);
        }
        #pragma unroll 4
        for (int u = tid; u < BN*8; u += 256) {
            int r = u >> 3, c = u & 7;
            uint32_t d = r*128 + ((c ^ (r&7))*16);
            size_t g = (size_t)(bn+r)*K + k0 + c*8;
            cpa16(st + 2*AB + d,      bH + g);
            cpa16(st + 2*AB + BB + d, bL + g);
        }
        CP_COMMIT();
    };

    load_stage(0, 0);

    int rr = lane & 15, hf = lane >> 4;
    for (int i = 0; i < nk; i++) {
        uint32_t st = sb + (i & 1)*STG;
        if (i + 1 < nk) { load_stage((i+1)&1, (i+1)*KC); CP_WAIT(1); }
        else            { CP_WAIT(0); }
        __syncthreads();

        #pragma unroll
        for (int ks = 0; ks < 4; ks++) {
            uint32_t ah[4][4], al[4][4], bh[NT][4], bl[NT][4];
            int ch = ks*2 + hf;
            #pragma unroll
            for (int mt=0;mt<4;mt++) {
                int r = wm*64 + mt*16 + rr;
                uint32_t ra = st + r*128 + ((ch ^ (r&7))*16);
                LDSM4(ah[mt][0],ah[mt][1],ah[mt][2],ah[mt][3], ra);
                LDSM4(al[mt][0],al[mt][1],al[mt][2],al[mt][3], ra + AB);
            }
            #pragma unroll
            for (int nt=0;nt<NT;nt++) {
                int r = wn*WN + nt*16 + rr;
                uint32_t rb = st + 2*AB + r*128 + ((ch ^ (r&7))*16);
                LDSM4(bh[nt][0],bh[nt][1],bh[nt][2],bh[nt][3], rb);
                LDSM4(bl[nt][0],bl[nt][1],bl[nt][2],bl[nt][3], rb + BB);
            }
            #pragma unroll
            for (int mt=0;mt<4;mt++) {
                #pragma unroll
                for (int n8=0;n8<N8;n8++) {
                    int nt = n8 >> 1, p = n8 & 1;
                    MMA16816(acc[mt][n8], ah[mt], bh[nt][p], bh[nt][p+2]);
                    MMA16816(acc[mt][n8], ah[mt], bl[nt][p], bl[nt][p+2]);
                    MMA16816(acc[mt][n8], al[mt], bh[nt][p], bh[nt][p+2]);
                }
            }
        }
        __syncthreads();
    }

    int r0b = bm + wm*64 + (lane >> 2);
    int c0b = bn + wn*WN + (lane & 3)*2;
    #pragma unroll
    for (int mt=0;mt<4;mt++) {
        #pragma unroll
        for (int n8=0;n8<N8;n8++) {
            #pragma unroll
            for (int half=0; half<2; half++) {
                int r = r0b + mt*16 + half*8;
                int c = c0b + n8*8;
                float v0 = acc[mt][n8][half*2+0];
                float v1 = acc[mt][n8][half*2+1];
                if (bias) { v0 += bias[c]; v1 += bias[c+1]; }
                if (flags & GF_WPE) {
                    const float* wp = wpe + (size_t)(r & (SL-1))*DM + c;
                    v0 += wp[0]; v1 += wp[1];
                }
                size_t o = (size_t)r*Nvalid + c;
                if (flags & GF_RESID) {
                    float2 old = *(float2*)(C + o);
                    old.x += v0; old.y += v1;
                    *(float2*)(C + o) = old;
                } else {
                    C[o] = v0; C[o+1] = v1;
                }
            }
        }
    }
}

#define SMEM128 (2*(2*AB + 2*128*128))   /* 131072 */

// ---------------- fp16 single-pass GEMM (layer GEMMs + LM head) --------------
template<int BN>
__global__ void __launch_bounds__(256,1)
k_hgemm(const __half* __restrict__ Af, const __half* __restrict__ Bf,
        const float* __restrict__ bias,
        float* __restrict__ C, __half* __restrict__ C16,
        int K, int Nvalid, int flags)
{
    constexpr int WN = BN/4;
    constexpr int NT = WN/16;
    constexpr int N8 = WN/8;
    constexpr int HA = 16384;
    constexpr int HB = BN*128;
    constexpr int ST = HA+HB;

    extern __shared__ __align__(128) unsigned char smem_buf[];
    uint32_t sb = smem_u32(smem_buf);
    int tid = threadIdx.x;
    int bm = blockIdx.x * 128;
    int bn = blockIdx.y * BN;

    int w = tid >> 5, lane = tid & 31;
    int wm = w >> 2, wn = w & 3;

    float acc[4][N8][4];
    #pragma unroll
    for (int mt=0;mt<4;mt++)
        #pragma unroll
        for (int n8=0;n8<N8;n8++)
            #pragma unroll
            for (int r=0;r<4;r++) acc[mt][n8][r]=0.f;

    int nk = K / KC;

    auto load_stage = [&](int stage, int k0){
        uint32_t st = sb + stage*ST;
        #pragma unroll 4
        for (int u = tid; u < 128*8; u += 256) {
            int r = u >> 3, c = u & 7;
            uint32_t d = r*128 + ((c ^ (r&7))*16);
            cpa16(st + d, Af + (size_t)(bm+r)*K + k0 + c*8);
        }
        #pragma unroll 8
        for (int u = tid; u < BN*8; u += 256) {
            int r = u >> 3, c = u & 7;
            uint32_t d = r*128 + ((c ^ (r&7))*16);
            cpa16(st + HA + d, Bf + (size_t)(bn+r)*K + k0 + c*8);
        }
        CP_COMMIT();
    };

    load_stage(0, 0);
    if (nk > 1) load_stage(1, KC);

    int rr = lane & 15, hf = lane >> 4;
    int stage = 0;
    for (int i = 0; i < nk; i++) {
        if (i + 2 < nk) { load_stage((stage+2)%3, (i+2)*KC); CP_WAIT(2); }
        else if (i + 1 < nk) { CP_WAIT(1); }
        else { CP_WAIT(0); }
        __syncthreads();

        uint32_t st = sb + stage*ST;
        #pragma unroll
        for (int ks = 0; ks < 4; ks++) {
            uint32_t ah[4][4], bh[NT][4];
            int ch = ks*2 + hf;
            #pragma unroll
            for (int mt=0;mt<4;mt++) {
                int r = wm*64 + mt*16 + rr;
                LDSM4(ah[mt][0],ah[mt][1],ah[mt][2],ah[mt][3], st + r*128 + ((ch ^ (r&7))*16));
            }
            #pragma unroll
            for (int nt=0;nt<NT;nt++) {
                int r = wn*WN + nt*16 + rr;
                LDSM4(bh[nt][0],bh[nt][1],bh[nt][2],bh[nt][3], st + HA + r*128 + ((ch ^ (r&7))*16));
            }
            #pragma unroll
            for (int mt=0;mt<4;mt++) {
                #pragma unroll
                for (int n8=0;n8<N8;n8++) {
                    int nt = n8 >> 1, p = n8 & 1;
                    MMA16816H(acc[mt][n8], ah[mt], bh[nt][p], bh[nt][p+2]);
                }
            }
        }
        __syncthreads();
        stage = (stage + 1) % 3;
    }

    int r0b = bm + wm*64 + (lane >> 2);
    int c0b = bn + wn*WN + (lane & 3)*2;
    #pragma unroll
    for (int mt=0;mt<4;mt++) {
        #pragma unroll
        for (int n8=0;n8<N8;n8++) {
            #pragma unroll
            for (int half=0; half<2; half++) {
                int r = r0b + mt*16 + half*8;
                int c = c0b + n8*8;
                float v0 = acc[mt][n8][half*2+0];
                float v1 = acc[mt][n8][half*2+1];
                if (bias) { v0 += bias[c]; v1 += bias[c+1]; }
                if (flags & GF_QKV) {
                    int sec = c / DM;
                    int cc = c - sec*DM;
                    int hh = cc >> 6, d = cc & 63;
                    int bb2 = r >> 10, s = r & (SL-1);
                    if (sec < 2) {
                        __half* dst = (sec == 0 ? g_q16 : g_k16)
                                      + (((size_t)(bb2*NH + hh)*SL + s) << 6) + d;
                        *(__half2*)dst = __floats2half2_rn(v0, v1);
                    } else {
                        __half* dst = g_vt + ((size_t)(bb2*NH + hh)*64 + d)*SL + s;
                        dst[0]  = __float2half(v0);
                        dst[SL] = __float2half(v1);
                    }
                    continue;
                }
                if (flags & GF_GELU) {
                    float u0=v0, u1=v1;
                    v0 = 0.5f*u0*(1.f + tanhf(0.7978845608028654f*(u0 + 0.044715f*u0*u0*u0)));
                    v1 = 0.5f*u1*(1.f + tanhf(0.7978845608028654f*(u1 + 0.044715f*u1*u1*u1)));
                    *(__half2*)(C16 + (size_t)r*Nvalid + c) = __floats2half2_rn(v0, v1);
                    continue;
                }
                size_t o = (size_t)r*Nvalid + c;
                if (flags & GF_RESID) {
                    float2 old = *(float2*)(C + o);
                    old.x += v0; old.y += v1;
                    *(float2*)(C + o) = old;
                } else {
                    if (c < Nvalid)   C[o]   = v0;
                    if (c+1 < Nvalid) C[o+1] = v1;
                }
            }
        }
    }
}

#define SMEMH256 (3*(16384 + 256*128))   /* 147456 */
#define SMEMH128 (3*(16384 + 128*128))   /* 98304 */

// ---------------- launch ----------------------------------------------------
extern "C" void kernel_launch(void* const* d_in, const int* in_sizes, int n_in,
                              void* d_out, int out_size)
{
    const int*   ctx  = (const int*)  d_in[0];
    const int*   qry  = (const int*)  d_in[1];
    const int*   rsp  = (const int*)  d_in[2];
    const int*   c2   = (const int*)  d_in[3];
    const int*   cl   = (const int*)  d_in[4];
    const int*   ql   = (const int*)  d_in[5];
    const int*   rl   = (const int*)  d_in[6];
    const int*   c2l  = (const int*)  d_in[7];
    const float* wte  = (const float*)d_in[8];
    const float* wpe  = (const float*)d_in[9];
    const float* ln1g = (const float*)d_in[10];
    const float* ln1b = (const float*)d_in[11];
    const float* wqkv = (const float*)d_in[12];
    const float* bqkv = (const float*)d_in[13];
    const float* wo   = (const float*)d_in[14];
    const float* bo   = (const float*)d_in[15];
    const float* ln2g = (const float*)d_in[16];
    const float* ln2b = (const float*)d_in[17];
    const float* wfc  = (const float*)d_in[18];
    const float* bfc  = (const float*)d_in[19];
    const float* wpr  = (const float*)d_in[20];
    const float* bpr  = (const float*)d_in[21];
    const float* lnfg = (const float*)d_in[22];
    const float* lnfb = (const float*)d_in[23];
    const float* llw  = (const float*)d_in[24];
    const float* llb  = (const float*)d_in[25];
    float* out = (float*)d_out;

    cudaFuncSetAttribute(k_tgemm<128>, cudaFuncAttributeMaxDynamicSharedMemorySize, SMEM128);
    cudaFuncSetAttribute(k_hgemm<256>, cudaFuncAttributeMaxDynamicSharedMemorySize, SMEMH256);
    cudaFuncSetAttribute(k_hgemm<128>, cudaFuncAttributeMaxDynamicSharedMemorySize, SMEMH128);

    float *ph;
    bf16 *xh, *xl, *lwh, *lwl;
    __half *x16, *a16, *f16b, *wtf, *qw16, *ow16, *fw16, *pw16;
    cudaGetSymbolAddress((void**)&ph,   g_h);
    cudaGetSymbolAddress((void**)&xh,   g_xh);   cudaGetSymbolAddress((void**)&xl,   g_xl);
    cudaGetSymbolAddress((void**)&lwh,  g_lwh);  cudaGetSymbolAddress((void**)&lwl,  g_lwl);
    cudaGetSymbolAddress((void**)&x16,  g_x16);  cudaGetSymbolAddress((void**)&a16,  g_a16);
    cudaGetSymbolAddress((void**)&f16b, g_f16);  cudaGetSymbolAddress((void**)&wtf,  g_wtf);
    cudaGetSymbolAddress((void**)&qw16, g_qw16); cudaGetSymbolAddress((void**)&ow16, g_ow16);
    cudaGetSymbolAddress((void**)&fw16, g_fw16); cudaGetSymbolAddress((void**)&pw16, g_pw16);

    // ---- weight conversions ----
    k_cvt_f16<<<(NVP*DM+255)/256, 256>>>(wte, wtf, NVOC*DM, NVP*DM);
    k_cvt<<<(DM*DM+255)/256, 256>>>(llw, lwh, lwl, DM*DM, DM*DM);
    for (int l = 0; l < NLAY; l++) {
        k_cvtT_f16<<<dim3(3*DM/32, DM/32), dim3(32,8)>>>(wqkv + (size_t)l*DM*3*DM,
                                                         qw16 + (size_t)l*3*DM*DM, DM, 3*DM);
        k_cvtT_f16<<<dim3(DM/32, DM/32), dim3(32,8)>>>(wo + (size_t)l*DM*DM,
                                                       ow16 + (size_t)l*DM*DM, DM, DM);
        k_cvtT_f16<<<dim3(FF/32, DM/32), dim3(32,8)>>>(wfc + (size_t)l*DM*FF,
                                                       fw16 + (size_t)l*FF*DM, DM, FF);
        k_cvtT_f16<<<dim3(DM/32, FF/32), dim3(32,8)>>>(wpr + (size_t)l*FF*DM,
                                                       pw16 + (size_t)l*DM*FF, FF, DM);
    }

    // ---- embeddings ----
    k_build_tok<<<(MT+255)/256, 256>>>(ctx, qry, rsp, c2, cl, ql, rl, c2l);
    k_gather<<<(MT*(DM/4)+255)/256, 256>>>(wte);

    // h = emb @ ll_w^T + ll_b + wpe  (bf16x3 — first op, highest amplification)
    k_tgemm<128><<<dim3(MT/128, DM/128), 256, SMEM128>>>(xh, xl, lwh, lwl, llb, wpe,
                                                         ph, DM, DM, GF_WPE);

    for (int l = 0; l < NLAY; l++) {
        k_ln_f16<<<MT, 256>>>(ph, ln1g + l*DM, ln1b + l*DM, x16);
        k_hgemm<256><<<dim3(MT/128, 3*DM/256), 256, SMEMH256>>>(x16,
            qw16 + (size_t)l*3*DM*DM, bqkv + l*3*DM,
            nullptr, nullptr, DM, 3*DM, GF_QKV);
        k_scores_h<<<dim3(SL/128, SL/128, BATCH*NH), 256>>>(cl, c2l, ql, rl);
        k_softmax_h<<<BATCH*NH*SL, 128>>>();
        k_av_h<<<dim3(SL/128, BATCH*NH), 256>>>();
        k_hgemm<128><<<dim3(MT/128, DM/128), 256, SMEMH128>>>(a16,
            ow16 + (size_t)l*DM*DM, bo + l*DM,
            ph, nullptr, DM, DM, GF_RESID);
        k_ln_f16<<<MT, 256>>>(ph, ln2g + l*DM, ln2b + l*DM, x16);
        k_hgemm<256><<<dim3(MT/128, FF/256), 256, SMEMH256>>>(x16,
            fw16 + (size_t)l*FF*DM, bfc + l*FF,
            nullptr, f16b, DM, FF, GF_GELU);
        k_hgemm<128><<<dim3(MT/128, DM/128), 256, SMEMH128>>>(f16b,
            pw16 + (size_t)l*DM*FF, bpr + l*DM,
            ph, nullptr, FF, DM, GF_RESID);
    }

    k_ln_f16<<<MT, 256>>>(ph, lnfg, lnfb, x16);

    // logits = x @ wte^T (fp16 single-pass)
    k_hgemm<256><<<dim3(MT/128, NVP/256), 256, SMEMH256>>>(x16, wtf, nullptr,
                                                           out, nullptr, DM, NVOC, 0);
}

// round 12
// speedup vs baseline: 5.6978x; 1.0804x over previous
#include <cuda_runtime.h>
#include <cuda_bf16.h>
#include <cuda_fp16.h>
#include <math.h>
#include <stdint.h>

#define BATCH 4
#define SL    1024
#define DM    768
#define NH    12
#define FF    3072
#define NVOC  50257
#define NVP   50432
#define MT    (BATCH*SL)
#define NLAY  2

#define S_C   512
#define S_C2  256
#define S_Q   128
#define S_R   128

#define GF_RESID 1
#define GF_GELU  2
#define GF_WPE   4
#define GF_QKV   8

typedef __nv_bfloat16 bf16;

// ---------------- scratch ---------------------------------------------------
__device__ float g_h[MT*DM];
__device__ int   g_tok[MT];

__device__ bf16 g_xh[MT*DM], g_xl[MT*DM];            // emb split (ll GEMM)
__device__ bf16 g_lwh[DM*DM], g_lwl[DM*DM];          // ll_w split

__device__ __half g_x16[MT*DM];                      // LN outputs fp16
__device__ __half g_a16[MT*DM];                      // attention out fp16
__device__ __half g_f16[(size_t)MT*FF];              // MLP hidden fp16
__device__ __half g_wtf[(size_t)NVP*DM];             // wte fp16 (padded)
__device__ __half g_qw16[NLAY*3*DM*DM];              // wqkv^T fp16
__device__ __half g_ow16[NLAY*DM*DM];                // wo^T fp16
__device__ __half g_fw16[NLAY*FF*DM];                // wfc^T fp16
__device__ __half g_pw16[NLAY*DM*FF];                // wpr^T fp16
__device__ __half g_q16[(size_t)BATCH*NH*SL*64];     // Q head-major fp16
__device__ __half g_k16[(size_t)BATCH*NH*SL*64];     // K head-major fp16
__device__ __half g_vt [(size_t)BATCH*NH*64*SL];     // V^T fp16

// ---------------- asm helpers -----------------------------------------------
__device__ __forceinline__ uint32_t smem_u32(const void* p){
    uint32_t a;
    asm("{ .reg .u64 t; cvta.to.shared.u64 t, %1; cvt.u32.u64 %0, t; }" : "=r"(a) : "l"(p));
    return a;
}
__device__ __forceinline__ void cpa16(uint32_t d, const void* s){
    asm volatile("cp.async.cg.shared.global [%0], [%1], 16;" :: "r"(d), "l"(s));
}
#define CP_COMMIT() asm volatile("cp.async.commit_group;" ::: "memory")
#define CP_WAIT(n)  asm volatile("cp.async.wait_group %0;" :: "n"(n) : "memory")

#define LDSM4(r0,r1,r2,r3,a) \
    asm volatile("ldmatrix.sync.aligned.m8n8.x4.shared.b16 {%0,%1,%2,%3}, [%4];" \
        : "=r"(r0),"=r"(r1),"=r"(r2),"=r"(r3) : "r"(a))

#define MMA16816(d, a, b0, b1) \
    asm volatile("mma.sync.aligned.m16n8k16.row.col.f32.bf16.bf16.f32 " \
        "{%0,%1,%2,%3},{%4,%5,%6,%7},{%8,%9},{%0,%1,%2,%3};" \
        : "+f"((d)[0]),"+f"((d)[1]),"+f"((d)[2]),"+f"((d)[3]) \
        : "r"((a)[0]),"r"((a)[1]),"r"((a)[2]),"r"((a)[3]),"r"(b0),"r"(b1))

#define MMA16816H(d, a, b0, b1) \
    asm volatile("mma.sync.aligned.m16n8k16.row.col.f32.f16.f16.f32 " \
        "{%0,%1,%2,%3},{%4,%5,%6,%7},{%8,%9},{%0,%1,%2,%3};" \
        : "+f"((d)[0]),"+f"((d)[1]),"+f"((d)[2]),"+f"((d)[3]) \
        : "r"((a)[0]),"r"((a)[1]),"r"((a)[2]),"r"((a)[3]),"r"(b0),"r"(b1))

__device__ __forceinline__ uint32_t pack_h2(float a, float b){
    __half2 h = __floats2half2_rn(a, b);
    return *(uint32_t*)&h;
}

// ---------------- small kernels ---------------------------------------------
__global__ void k_build_tok(const int* __restrict__ ctx, const int* __restrict__ qry,
                            const int* __restrict__ rsp, const int* __restrict__ c2,
                            const int* __restrict__ cl, const int* __restrict__ ql,
                            const int* __restrict__ rl, const int* __restrict__ c2l)
{
    int idx = blockIdx.x*blockDim.x + threadIdx.x;
    if (idx >= MT) return;
    int b = idx / SL, p = idx % SL;
    int l0 = cl[b], l1 = c2l[b], l2 = ql[b], l3 = rl[b];
    int tok = -1;
    if (p < l0)               tok = ctx[b*S_C + p];
    else if (p < l0+l1)       tok = c2 [b*S_C2 + (p-l0)];
    else if (p < l0+l1+l2)    tok = qry[b*S_Q + (p-l0-l1)];
    else if (p < l0+l1+l2+l3) tok = rsp[b*S_R + (p-l0-l1-l2)];
    g_tok[idx] = tok;
}

__global__ void k_gather(const float* __restrict__ wte)
{
    int idx = blockIdx.x*blockDim.x + threadIdx.x;
    if (idx >= MT*(DM/4)) return;
    int row = idx / (DM/4), c4 = idx % (DM/4);
    int tok = g_tok[row];
    float4 v = make_float4(0.f,0.f,0.f,0.f);
    if (tok >= 0) v = ((const float4*)(wte + (size_t)tok*DM))[c4];
    float vv[4] = {v.x, v.y, v.z, v.w};
    size_t o = (size_t)row*DM + c4*4;
    #pragma unroll
    for (int t=0;t<4;t++){
        bf16 h = __float2bfloat16(vv[t]);
        g_xh[o+t] = h;
        g_xl[o+t] = __float2bfloat16(vv[t] - __bfloat162float(h));
    }
}

__global__ void k_cvt_f16(const float* __restrict__ in, __half* __restrict__ o,
                          int nin, int ntot)
{
    int i = blockIdx.x*blockDim.x + threadIdx.x;
    if (i >= ntot) return;
    float v = (i < nin) ? in[i] : 0.f;
    o[i] = __float2half(v);
}

__global__ void k_cvt(const float* __restrict__ in, bf16* __restrict__ oh,
                      bf16* __restrict__ ol, int nin, int ntot)
{
    int i = blockIdx.x*blockDim.x + threadIdx.x;
    if (i >= ntot) return;
    float v = (i < nin) ? in[i] : 0.f;
    bf16 h = __float2bfloat16(v);
    oh[i] = h;
    ol[i] = __float2bfloat16(v - __bfloat162float(h));
}

// transpose fp32 [Kd, Nd] -> fp16 [Nd, Kd]
__global__ void k_cvtT_f16(const float* __restrict__ in, __half* __restrict__ o,
                           int Kd, int Nd)
{
    __shared__ float t[32][33];
    int kb = blockIdx.y*32, nb = blockIdx.x*32;
    int tx = threadIdx.x, ty = threadIdx.y;
    #pragma unroll
    for (int i=0;i<32;i+=8)
        t[ty+i][tx] = in[(size_t)(kb+ty+i)*Nd + nb+tx];
    __syncthreads();
    #pragma unroll
    for (int i=0;i<32;i+=8)
        o[(size_t)(nb+ty+i)*Kd + kb+tx] = __float2half(t[tx][ty+i]);
}

// LayerNorm fp32 -> fp16
__global__ void __launch_bounds__(256)
k_ln_f16(const float* __restrict__ in, const float* __restrict__ gm,
         const float* __restrict__ bt, __half* __restrict__ o16)
{
    __shared__ float red[256];
    int row = blockIdx.x, tid = threadIdx.x;
    const float* x = in + (size_t)row*DM;
    float v0 = x[tid], v1 = x[tid+256], v2 = x[tid+512];
    red[tid] = v0+v1+v2; __syncthreads();
    for (int o=128;o>0;o>>=1){ if(tid<o) red[tid]+=red[tid+o]; __syncthreads(); }
    float mean = red[0] * (1.f/768.f); __syncthreads();
    float d0=v0-mean, d1=v1-mean, d2=v2-mean;
    red[tid] = d0*d0+d1*d1+d2*d2; __syncthreads();
    for (int o=128;o>0;o>>=1){ if(tid<o) red[tid]+=red[tid+o]; __syncthreads(); }
    float inv = rsqrtf(red[0]*(1.f/768.f) + 1e-5f);
    #pragma unroll
    for (int t=0;t<3;t++){
        int c = tid + t*256;
        float d = (t==0)?d0:((t==1)?d1:d2);
        o16[(size_t)row*DM + c] = __float2half(d*inv*gm[c] + bt[c]);
    }
}

// ---------------- fused flash attention --------------------------------------
// One CTA per (bh, 128-row q tile). Online softmax, K/V chunks of 64,
// double-buffered cp.async. Q/K/V/P fp16 HMMA, fp32 softmax state.
__global__ void __launch_bounds__(256,1)
k_flash(const int* __restrict__ cl, const int* __restrict__ c2l,
        const int* __restrict__ ql, const int* __restrict__ rl)
{
    __shared__ __align__(128) unsigned char smem_buf[49152]; // Q 16K + 2x(K 8K + V 8K)
    uint32_t sb = smem_u32(smem_buf);
    int tid = threadIdx.x, w = tid>>5, lane = tid&31;
    int bh = blockIdx.y, b = bh / NH, hh = bh % NH;
    int q0 = blockIdx.x * 128;
    int total = cl[b] + c2l[b] + ql[b] + rl[b];

    const __half* Qb = g_q16 + (size_t)bh*SL*64;
    const __half* Kb = g_k16 + (size_t)bh*SL*64;
    const __half* Vb = g_vt  + (size_t)bh*64*SL;

    // prologue: Q (128x64) + KV chunk 0
    for (int u = tid; u < 1024; u += 256) {
        int r = u>>3, c = u&7;
        cpa16(sb + r*128 + ((c^(r&7))*16), Qb + (size_t)(q0+r)*64 + c*8);
    }
    for (int u = tid; u < 512; u += 256) {
        int r = u>>3, c = u&7;
        uint32_t d = r*128 + ((c^(r&7))*16);
        cpa16(sb + 16384 + d,        Kb + (size_t)r*64 + c*8);
        cpa16(sb + 16384 + 8192 + d, Vb + (size_t)r*SL + c*8);
    }
    CP_COMMIT();
    CP_WAIT(0);
    __syncthreads();

    int rr = lane & 15, hf = lane >> 4;

    // preload Q frags: warp w owns rows w*16..+15
    uint32_t qf[4][4];
    #pragma unroll
    for (int ks=0; ks<4; ks++) {
        int r = w*16 + rr;
        int ch = ks*2 + hf;
        LDSM4(qf[ks][0],qf[ks][1],qf[ks][2],qf[ks][3], sb + r*128 + ((ch^(r&7))*16));
    }

    float Oacc[8][4];
    #pragma unroll
    for (int nd=0;nd<8;nd++)
        #pragma unroll
        for (int j=0;j<4;j++) Oacc[nd][j]=0.f;
    float mrow[2] = {-1e30f,-1e30f}, lrow[2] = {0.f,0.f};
    int qi0 = q0 + w*16 + (lane>>2);

    int nk = q0/64 + 2;
    int nkt = (total + 63) >> 6;
    if (nkt < nk) nk = nkt;

    for (int i = 0; i < nk; i++) {
        uint32_t st = sb + 16384 + (i&1)*16384;
        if (i+1 < nk) {
            uint32_t st2 = sb + 16384 + ((i+1)&1)*16384;
            int k0n = (i+1)*64;
            for (int u = tid; u < 512; u += 256) {
                int r = u>>3, c = u&7;
                uint32_t d = r*128 + ((c^(r&7))*16);
                cpa16(st2 + d,        Kb + (size_t)(k0n+r)*64 + c*8);
                cpa16(st2 + 8192 + d, Vb + (size_t)r*SL + k0n + c*8);
            }
            CP_COMMIT();
            CP_WAIT(1);
        } else {
            CP_WAIT(0);
        }
        __syncthreads();

        int k0 = i*64;
        // ---- S = Q K^T ----
        float Sacc[8][4];
        #pragma unroll
        for (int n8=0;n8<8;n8++)
            #pragma unroll
            for (int j=0;j<4;j++) Sacc[n8][j]=0.f;
        #pragma unroll
        for (int ks=0; ks<4; ks++) {
            uint32_t bf[4][4];
            int ch = ks*2 + hf;
            #pragma unroll
            for (int nt=0; nt<4; nt++) {
                int r = nt*16 + rr;
                LDSM4(bf[nt][0],bf[nt][1],bf[nt][2],bf[nt][3], st + r*128 + ((ch^(r&7))*16));
            }
            #pragma unroll
            for (int nt=0; nt<4; nt++) {
                MMA16816H(Sacc[nt*2+0], qf[ks], bf[nt][0], bf[nt][2]);
                MMA16816H(Sacc[nt*2+1], qf[ks], bf[nt][1], bf[nt][3]);
            }
        }
        // ---- scale + mask ----
        #pragma unroll
        for (int n8=0;n8<8;n8++)
            #pragma unroll
            for (int j=0;j<4;j++) {
                int kk = k0 + n8*8 + (lane&3)*2 + (j&1);
                int qi = qi0 + (j>>1)*8;
                float v = Sacc[n8][j]*0.125f;
                Sacc[n8][j] = (kk<=qi && kk<total) ? v : -1e30f;
            }
        // ---- online softmax ----
        float cm[2] = {-1e30f,-1e30f};
        #pragma unroll
        for (int n8=0;n8<8;n8++) {
            cm[0] = fmaxf(cm[0], fmaxf(Sacc[n8][0], Sacc[n8][1]));
            cm[1] = fmaxf(cm[1], fmaxf(Sacc[n8][2], Sacc[n8][3]));
        }
        #pragma unroll
        for (int o=1;o<4;o<<=1) {
            cm[0] = fmaxf(cm[0], __shfl_xor_sync(0xffffffffu, cm[0], o));
            cm[1] = fmaxf(cm[1], __shfl_xor_sync(0xffffffffu, cm[1], o));
        }
        float mnew[2], corr[2];
        #pragma unroll
        for (int h=0;h<2;h++) {
            mnew[h] = fmaxf(mrow[h], cm[h]);
            corr[h] = __expf(mrow[h] - mnew[h]);
        }
        float ls[2] = {0.f,0.f};
        #pragma unroll
        for (int n8=0;n8<8;n8++)
            #pragma unroll
            for (int j=0;j<4;j++) {
                float p = __expf(Sacc[n8][j] - mnew[j>>1]);
                Sacc[n8][j] = p;
                ls[j>>1] += p;
            }
        #pragma unroll
        for (int o=1;o<4;o<<=1) {
            ls[0] += __shfl_xor_sync(0xffffffffu, ls[0], o);
            ls[1] += __shfl_xor_sync(0xffffffffu, ls[1], o);
        }
        #pragma unroll
        for (int h=0;h<2;h++) {
            lrow[h] = lrow[h]*corr[h] + ls[h];
            mrow[h] = mnew[h];
        }
        // rescale O
        #pragma unroll
        for (int nd=0;nd<8;nd++) {
            Oacc[nd][0] *= corr[0]; Oacc[nd][1] *= corr[0];
            Oacc[nd][2] *= corr[1]; Oacc[nd][3] *= corr[1];
        }
        // ---- O += P V ----
        #pragma unroll
        for (int kf=0; kf<4; kf++) {
            uint32_t ph[4];
            ph[0] = pack_h2(Sacc[2*kf  ][0], Sacc[2*kf  ][1]);
            ph[1] = pack_h2(Sacc[2*kf  ][2], Sacc[2*kf  ][3]);
            ph[2] = pack_h2(Sacc[2*kf+1][0], Sacc[2*kf+1][1]);
            ph[3] = pack_h2(Sacc[2*kf+1][2], Sacc[2*kf+1][3]);
            uint32_t bv[4][4];
            int ch = kf*2 + hf;
            #pragma unroll
            for (int nt=0; nt<4; nt++) {
                int r = nt*16 + rr;
                LDSM4(bv[nt][0],bv[nt][1],bv[nt][2],bv[nt][3], st + 8192 + r*128 + ((ch^(r&7))*16));
            }
            #pragma unroll
            for (int nt=0; nt<4; nt++) {
                MMA16816H(Oacc[nt*2+0], ph, bv[nt][0], bv[nt][2]);
                MMA16816H(Oacc[nt*2+1], ph, bv[nt][1], bv[nt][3]);
            }
        }
        __syncthreads();
    }

    float inv0 = 1.f/lrow[0], inv1 = 1.f/lrow[1];
    #pragma unroll
    for (int nd=0; nd<8; nd++)
        #pragma unroll
        for (int h=0; h<2; h++) {
            int s = qi0 + h*8;
            int d = nd*8 + (lane&3)*2;
            float inv = h ? inv1 : inv0;
            size_t o = (size_t)(b*SL + s)*DM + hh*64 + d;
            *(__half2*)(g_a16 + o) =
                __floats2half2_rn(Oacc[nd][h*2+0]*inv, Oacc[nd][h*2+1]*inv);
        }
}

// ---------------- split-bf16 GEMM (ll only) ----------------------------------
#define KC 64
#define AB (128*128)

template<int BN>
__global__ void __launch_bounds__(256,1)
k_tgemm(const bf16* __restrict__ aH, const bf16* __restrict__ aL,
        const bf16* __restrict__ bH, const bf16* __restrict__ bL,
        const float* __restrict__ bias, const float* __restrict__ wpe,
        float* __restrict__ C, int K, int Nvalid, int flags)
{
    constexpr int WN  = BN/4;
    constexpr int NT  = WN/16;
    constexpr int N8  = WN/8;
    constexpr int BB  = BN*128;
    constexpr int STG = 2*AB + 2*BB;

    extern __shared__ __align__(128) unsigned char smem_buf[];
    uint32_t sb = smem_u32(smem_buf);
    int tid = threadIdx.x;
    int bm = blockIdx.x * 128;
    int bn = blockIdx.y * BN;

    int w = tid >> 5, lane = tid & 31;
    int wm = w >> 2, wn = w & 3;

    float acc[4][N8][4];
    #pragma unroll
    for (int mt=0;mt<4;mt++)
        #pragma unroll
        for (int n8=0;n8<N8;n8++)
            #pragma unroll
            for (int r=0;r<4;r++) acc[mt][n8][r]=0.f;

    int nk = K / KC;

    auto load_stage = [&](int stage, int k0){
        uint32_t st = sb + stage*STG;
        #pragma unroll 4
        for (int u = tid; u < 128*8; u += 256) {
            int r = u >> 3, c = u & 7;
            uint32_t d = r*128 + ((c ^ (r&7))*16);
            size_t g = (size_t)(bm+r)*K + k0 + c*8;
            cpa16(st + d,      aH + g);
            cpa16(st + AB + d, aL + g);
        }
        #pragma unroll 4
        for (int u = tid; u < BN*8; u += 256) {
            int r = u >> 3, c = u & 7;
            uint32_t d = r*128 + ((c ^ (r&7))*16);
            size_t g = (size_t)(bn+r)*K + k0 + c*8;
            cpa16(st + 2*AB + d,      bH + g);
            cpa16(st + 2*AB + BB + d, bL + g);
        }
        CP_COMMIT();
    };

    load_stage(0, 0);

    int rr = lane & 15, hf = lane >> 4;
    for (int i = 0; i < nk; i++) {
        uint32_t st = sb + (i & 1)*STG;
        if (i + 1 < nk) { load_stage((i+1)&1, (i+1)*KC); CP_WAIT(1); }
        else            { CP_WAIT(0); }
        __syncthreads();

        #pragma unroll
        for (int ks = 0; ks < 4; ks++) {
            uint32_t ah[4][4], al[4][4], bh[NT][4], bl[NT][4];
            int ch = ks*2 + hf;
            #pragma unroll
            for (int mt=0;mt<4;mt++) {
                int r = wm*64 + mt*16 + rr;
                uint32_t ra = st + r*128 + ((ch ^ (r&7))*16);
                LDSM4(ah[mt][0],ah[mt][1],ah[mt][2],ah[mt][3], ra);
                LDSM4(al[mt][0],al[mt][1],al[mt][2],al[mt][3], ra + AB);
            }
            #pragma unroll
            for (int nt=0;nt<NT;nt++) {
                int r = wn*WN + nt*16 + rr;
                uint32_t rb = st + 2*AB + r*128 + ((ch ^ (r&7))*16);
                LDSM4(bh[nt][0],bh[nt][1],bh[nt][2],bh[nt][3], rb);
                LDSM4(bl[nt][0],bl[nt][1],bl[nt][2],bl[nt][3], rb + BB);
            }
            #pragma unroll
            for (int mt=0;mt<4;mt++) {
                #pragma unroll
                for (int n8=0;n8<N8;n8++) {
                    int nt = n8 >> 1, p = n8 & 1;
                    MMA16816(acc[mt][n8], ah[mt], bh[nt][p], bh[nt][p+2]);
                    MMA16816(acc[mt][n8], ah[mt], bl[nt][p], bl[nt][p+2]);
                    MMA16816(acc[mt][n8], al[mt], bh[nt][p], bh[nt][p+2]);
                }
            }
        }
        __syncthreads();
    }

    int r0b = bm + wm*64 + (lane >> 2);
    int c0b = bn + wn*WN + (lane & 3)*2;
    #pragma unroll
    for (int mt=0;mt<4;mt++) {
        #pragma unroll
        for (int n8=0;n8<N8;n8++) {
            #pragma unroll
            for (int half=0; half<2; half++) {
                int r = r0b + mt*16 + half*8;
                int c = c0b + n8*8;
                float v0 = acc[mt][n8][half*2+0];
                float v1 = acc[mt][n8][half*2+1];
                if (bias) { v0 += bias[c]; v1 += bias[c+1]; }
                if (flags & GF_WPE) {
                    const float* wp = wpe + (size_t)(r & (SL-1))*DM + c;
                    v0 += wp[0]; v1 += wp[1];
                }
                size_t o = (size_t)r*Nvalid + c;
                if (flags & GF_RESID) {
                    float2 old = *(float2*)(C + o);
                    old.x += v0; old.y += v1;
                    *(float2*)(C + o) = old;
                } else {
                    C[o] = v0; C[o+1] = v1;
                }
            }
        }
    }
}

#define SMEM128 (2*(2*AB + 2*128*128))   /* 131072 */

// ---------------- fp16 single-pass GEMM (layer GEMMs + LM head) --------------
template<int BN>
__global__ void __launch_bounds__(256,1)
k_hgemm(const __half* __restrict__ Af, const __half* __restrict__ Bf,
        const float* __restrict__ bias,
        float* __restrict__ C, __half* __restrict__ C16,
        int K, int Nvalid, int flags)
{
    constexpr int WN = BN/4;
    constexpr int NT = WN/16;
    constexpr int N8 = WN/8;
    constexpr int HA = 16384;
    constexpr int HB = BN*128;
    constexpr int ST = HA+HB;

    extern __shared__ __align__(128) unsigned char smem_buf[];
    uint32_t sb = smem_u32(smem_buf);
    int tid = threadIdx.x;
    int bm = blockIdx.x * 128;
    int bn = blockIdx.y * BN;

    int w = tid >> 5, lane = tid & 31;
    int wm = w >> 2, wn = w & 3;

    float acc[4][N8][4];
    #pragma unroll
    for (int mt=0;mt<4;mt++)
        #pragma unroll
        for (int n8=0;n8<N8;n8++)
            #pragma unroll
            for (int r=0;r<4;r++) acc[mt][n8][r]=0.f;

    int nk = K / KC;

    auto load_stage = [&](int stage, int k0){
        uint32_t st = sb + stage*ST;
        #pragma unroll 4
        for (int u = tid; u < 128*8; u += 256) {
            int r = u >> 3, c = u & 7;
            uint32_t d = r*128 + ((c ^ (r&7))*16);
            cpa16(st + d, Af + (size_t)(bm+r)*K + k0 + c*8);
        }
        #pragma unroll 8
        for (int u = tid; u < BN*8; u += 256) {
            int r = u >> 3, c = u & 7;
            uint32_t d = r*128 + ((c ^ (r&7))*16);
            cpa16(st + HA + d, Bf + (size_t)(bn+r)*K + k0 + c*8);
        }
        CP_COMMIT();
    };

    load_stage(0, 0);
    if (nk > 1) load_stage(1, KC);

    int rr = lane & 15, hf = lane >> 4;
    int stage = 0;
    for (int i = 0; i < nk; i++) {
        if (i + 2 < nk) { load_stage((stage+2)%3, (i+2)*KC); CP_WAIT(2); }
        else if (i + 1 < nk) { CP_WAIT(1); }
        else { CP_WAIT(0); }
        __syncthreads();

        uint32_t st = sb + stage*ST;
        #pragma unroll
        for (int ks = 0; ks < 4; ks++) {
            uint32_t ah[4][4], bh[NT][4];
            int ch = ks*2 + hf;
            #pragma unroll
            for (int mt=0;mt<4;mt++) {
                int r = wm*64 + mt*16 + rr;
                LDSM4(ah[mt][0],ah[mt][1],ah[mt][2],ah[mt][3], st + r*128 + ((ch ^ (r&7))*16));
            }
            #pragma unroll
            for (int nt=0;nt<NT;nt++) {
                int r = wn*WN + nt*16 + rr;
                LDSM4(bh[nt][0],bh[nt][1],bh[nt][2],bh[nt][3], st + HA + r*128 + ((ch ^ (r&7))*16));
            }
            #pragma unroll
            for (int mt=0;mt<4;mt++) {
                #pragma unroll
                for (int n8=0;n8<N8;n8++) {
                    int nt = n8 >> 1, p = n8 & 1;
                    MMA16816H(acc[mt][n8], ah[mt], bh[nt][p], bh[nt][p+2]);
                }
            }
        }
        __syncthreads();
        stage = (stage + 1) % 3;
    }

    int r0b = bm + wm*64 + (lane >> 2);
    int c0b = bn + wn*WN + (lane & 3)*2;
    #pragma unroll
    for (int mt=0;mt<4;mt++) {
        #pragma unroll
        for (int n8=0;n8<N8;n8++) {
            #pragma unroll
            for (int half=0; half<2; half++) {
                int r = r0b + mt*16 + half*8;
                int c = c0b + n8*8;
                float v0 = acc[mt][n8][half*2+0];
                float v1 = acc[mt][n8][half*2+1];
                if (bias) { v0 += bias[c]; v1 += bias[c+1]; }
                if (flags & GF_QKV) {
                    int sec = c / DM;
                    int cc = c - sec*DM;
                    int hh = cc >> 6, d = cc & 63;
                    int bb2 = r >> 10, s = r & (SL-1);
                    if (sec < 2) {
                        __half* dst = (sec == 0 ? g_q16 : g_k16)
                                      + (((size_t)(bb2*NH + hh)*SL + s) << 6) + d;
                        *(__half2*)dst = __floats2half2_rn(v0, v1);
                    } else {
                        __half* dst = g_vt + ((size_t)(bb2*NH + hh)*64 + d)*SL + s;
                        dst[0]  = __float2half(v0);
                        dst[SL] = __float2half(v1);
                    }
                    continue;
                }
                if (flags & GF_GELU) {
                    float u0=v0, u1=v1;
                    v0 = 0.5f*u0*(1.f + tanhf(0.7978845608028654f*(u0 + 0.044715f*u0*u0*u0)));
                    v1 = 0.5f*u1*(1.f + tanhf(0.7978845608028654f*(u1 + 0.044715f*u1*u1*u1)));
                    *(__half2*)(C16 + (size_t)r*Nvalid + c) = __floats2half2_rn(v0, v1);
                    continue;
                }
                size_t o = (size_t)r*Nvalid + c;
                if (flags & GF_RESID) {
                    float2 old = *(float2*)(C + o);
                    old.x += v0; old.y += v1;
                    *(float2*)(C + o) = old;
                } else {
                    if (c < Nvalid)   C[o]   = v0;
                    if (c+1 < Nvalid) C[o+1] = v1;
                }
            }
        }
    }
}

#define SMEMH256 (3*(16384 + 256*128))   /* 147456 */
#define SMEMH128 (3*(16384 + 128*128))   /* 98304 */

// ---------------- launch ----------------------------------------------------
extern "C" void kernel_launch(void* const* d_in, const int* in_sizes, int n_in,
                              void* d_out, int out_size)
{
    const int*   ctx  = (const int*)  d_in[0];
    const int*   qry  = (const int*)  d_in[1];
    const int*   rsp  = (const int*)  d_in[2];
    const int*   c2   = (const int*)  d_in[3];
    const int*   cl   = (const int*)  d_in[4];
    const int*   ql   = (const int*)  d_in[5];
    const int*   rl   = (const int*)  d_in[6];
    const int*   c2l  = (const int*)  d_in[7];
    const float* wte  = (const float*)d_in[8];
    const float* wpe  = (const float*)d_in[9];
    const float* ln1g = (const float*)d_in[10];
    const float* ln1b = (const float*)d_in[11];
    const float* wqkv = (const float*)d_in[12];
    const float* bqkv = (const float*)d_in[13];
    const float* wo   = (const float*)d_in[14];
    const float* bo   = (const float*)d_in[15];
    const float* ln2g = (const float*)d_in[16];
    const float* ln2b = (const float*)d_in[17];
    const float* wfc  = (const float*)d_in[18];
    const float* bfc  = (const float*)d_in[19];
    const float* wpr  = (const float*)d_in[20];
    const float* bpr  = (const float*)d_in[21];
    const float* lnfg = (const float*)d_in[22];
    const float* lnfb = (const float*)d_in[23];
    const float* llw  = (const float*)d_in[24];
    const float* llb  = (const float*)d_in[25];
    float* out = (float*)d_out;

    cudaFuncSetAttribute(k_tgemm<128>, cudaFuncAttributeMaxDynamicSharedMemorySize, SMEM128);
    cudaFuncSetAttribute(k_hgemm<256>, cudaFuncAttributeMaxDynamicSharedMemorySize, SMEMH256);
    cudaFuncSetAttribute(k_hgemm<128>, cudaFuncAttributeMaxDynamicSharedMemorySize, SMEMH128);

    float *ph;
    bf16 *xh, *xl, *lwh, *lwl;
    __half *x16, *a16, *f16b, *wtf, *qw16, *ow16, *fw16, *pw16;
    cudaGetSymbolAddress((void**)&ph,   g_h);
    cudaGetSymbolAddress((void**)&xh,   g_xh);   cudaGetSymbolAddress((void**)&xl,   g_xl);
    cudaGetSymbolAddress((void**)&lwh,  g_lwh);  cudaGetSymbolAddress((void**)&lwl,  g_lwl);
    cudaGetSymbolAddress((void**)&x16,  g_x16);  cudaGetSymbolAddress((void**)&a16,  g_a16);
    cudaGetSymbolAddress((void**)&f16b, g_f16);  cudaGetSymbolAddress((void**)&wtf,  g_wtf);
    cudaGetSymbolAddress((void**)&qw16, g_qw16); cudaGetSymbolAddress((void**)&ow16, g_ow16);
    cudaGetSymbolAddress((void**)&fw16, g_fw16); cudaGetSymbolAddress((void**)&pw16, g_pw16);

    // ---- weight conversions ----
    k_cvt_f16<<<(NVP*DM+255)/256, 256>>>(wte, wtf, NVOC*DM, NVP*DM);
    k_cvt<<<(DM*DM+255)/256, 256>>>(llw, lwh, lwl, DM*DM, DM*DM);
    for (int l = 0; l < NLAY; l++) {
        k_cvtT_f16<<<dim3(3*DM/32, DM/32), dim3(32,8)>>>(wqkv + (size_t)l*DM*3*DM,
                                                         qw16 + (size_t)l*3*DM*DM, DM, 3*DM);
        k_cvtT_f16<<<dim3(DM/32, DM/32), dim3(32,8)>>>(wo + (size_t)l*DM*DM,
                                                       ow16 + (size_t)l*DM*DM, DM, DM);
        k_cvtT_f16<<<dim3(FF/32, DM/32), dim3(32,8)>>>(wfc + (size_t)l*DM*FF,
                                                       fw16 + (size_t)l*FF*DM, DM, FF);
        k_cvtT_f16<<<dim3(DM/32, FF/32), dim3(32,8)>>>(wpr + (size_t)l*FF*DM,
                                                       pw16 + (size_t)l*DM*FF, FF, DM);
    }

    // ---- embeddings ----
    k_build_tok<<<(MT+255)/256, 256>>>(ctx, qry, rsp, c2, cl, ql, rl, c2l);
    k_gather<<<(MT*(DM/4)+255)/256, 256>>>(wte);

    // h = emb @ ll_w^T + ll_b + wpe  (bf16x3 — first op, highest amplification)
    k_tgemm<128><<<dim3(MT/128, DM/128), 256, SMEM128>>>(xh, xl, lwh, lwl, llb, wpe,
                                                         ph, DM, DM, GF_WPE);

    for (int l = 0; l < NLAY; l++) {
        k_ln_f16<<<MT, 256>>>(ph, ln1g + l*DM, ln1b + l*DM, x16);
        k_hgemm<256><<<dim3(MT/128, 3*DM/256), 256, SMEMH256>>>(x16,
            qw16 + (size_t)l*3*DM*DM, bqkv + l*3*DM,
            nullptr, nullptr, DM, 3*DM, GF_QKV);
        k_flash<<<dim3(SL/128, BATCH*NH), 256>>>(cl, c2l, ql, rl);
        k_hgemm<128><<<dim3(MT/128, DM/128), 256, SMEMH128>>>(a16,
            ow16 + (size_t)l*DM*DM, bo + l*DM,
            ph, nullptr, DM, DM, GF_RESID);
        k_ln_f16<<<MT, 256>>>(ph, ln2g + l*DM, ln2b + l*DM, x16);
        k_hgemm<256><<<dim3(MT/128, FF/256), 256, SMEMH256>>>(x16,
            fw16 + (size_t)l*FF*DM, bfc + l*FF,
            nullptr, f16b, DM, FF, GF_GELU);
        k_hgemm<128><<<dim3(MT/128, DM/128), 256, SMEMH128>>>(f16b,
            pw16 + (size_t)l*DM*FF, bpr + l*DM,
            ph, nullptr, FF, DM, GF_RESID);
    }

    k_ln_f16<<<MT, 256>>>(ph, lnfg, lnfb, x16);

    // logits = x @ wte^T (fp16 single-pass)
    k_hgemm<256><<<dim3(MT/128, NVP/256), 256, SMEMH256>>>(x16, wtf, nullptr,
                                                           out, nullptr, DM, NVOC, 0);
}

// round 15
// speedup vs baseline: 5.8705x; 1.0303x over previous
#include <cuda_runtime.h>
#include <cuda_bf16.h>
#include <cuda_fp16.h>
#include <math.h>
#include <stdint.h>

#define BATCH 4
#define SL    1024
#define DM    768
#define NH    12
#define FF    3072
#define NVOC  50257
#define NVP   50432
#define MT    (BATCH*SL)
#define NLAY  2

#define S_C   512
#define S_C2  256
#define S_Q   128
#define S_R   128

#define GF_RESID 1
#define GF_GELU  2
#define GF_WPE   4
#define GF_QKV   8

typedef __nv_bfloat16 bf16;

// ---------------- scratch ---------------------------------------------------
__device__ float g_h[MT*DM];
__device__ int   g_tok[MT];

__device__ bf16 g_xh[MT*DM], g_xl[MT*DM];
__device__ bf16 g_lwh[DM*DM], g_lwl[DM*DM];

__device__ __half g_x16[MT*DM];
__device__ __half g_a16[MT*DM];
__device__ __half g_f16[(size_t)MT*FF];
__device__ __half g_wtf[(size_t)NVP*DM];
__device__ __half g_qw16[NLAY*3*DM*DM];
__device__ __half g_ow16[NLAY*DM*DM];
__device__ __half g_fw16[NLAY*FF*DM];
__device__ __half g_pw16[NLAY*DM*FF];
__device__ __half g_q16[(size_t)BATCH*NH*SL*64];
__device__ __half g_k16[(size_t)BATCH*NH*SL*64];
__device__ __half g_vt [(size_t)BATCH*NH*64*SL];

// ---------------- asm helpers -----------------------------------------------
__device__ __forceinline__ uint32_t smem_u32(const void* p){
    uint32_t a;
    asm("{ .reg .u64 t; cvta.to.shared.u64 t, %1; cvt.u32.u64 %0, t; }" : "=r"(a) : "l"(p));
    return a;
}
__device__ __forceinline__ void cpa16(uint32_t d, const void* s){
    asm volatile("cp.async.cg.shared.global [%0], [%1], 16;" :: "r"(d), "l"(s));
}
#define CP_COMMIT() asm volatile("cp.async.commit_group;" ::: "memory")
#define CP_WAIT(n)  asm volatile("cp.async.wait_group %0;" :: "n"(n) : "memory")

#define LDSM4(r0,r1,r2,r3,a) \
    asm volatile("ldmatrix.sync.aligned.m8n8.x4.shared.b16 {%0,%1,%2,%3}, [%4];" \
        : "=r"(r0),"=r"(r1),"=r"(r2),"=r"(r3) : "r"(a))

#define MMA16816(d, a, b0, b1) \
    asm volatile("mma.sync.aligned.m16n8k16.row.col.f32.bf16.bf16.f32 " \
        "{%0,%1,%2,%3},{%4,%5,%6,%7},{%8,%9},{%0,%1,%2,%3};" \
        : "+f"((d)[0]),"+f"((d)[1]),"+f"((d)[2]),"+f"((d)[3]) \
        : "r"((a)[0]),"r"((a)[1]),"r"((a)[2]),"r"((a)[3]),"r"(b0),"r"(b1))

#define MMA16816H(d, a, b0, b1) \
    asm volatile("mma.sync.aligned.m16n8k16.row.col.f32.f16.f16.f32 " \
        "{%0,%1,%2,%3},{%4,%5,%6,%7},{%8,%9},{%0,%1,%2,%3};" \
        : "+f"((d)[0]),"+f"((d)[1]),"+f"((d)[2]),"+f"((d)[3]) \
        : "r"((a)[0]),"r"((a)[1]),"r"((a)[2]),"r"((a)[3]),"r"(b0),"r"(b1))

__device__ __forceinline__ uint32_t pack_h2(float a, float b){
    __half2 h = __floats2half2_rn(a, b);
    return *(uint32_t*)&h;
}

// ---------------- small kernels ---------------------------------------------
__global__ void k_build_tok(const int* __restrict__ ctx, const int* __restrict__ qry,
                            const int* __restrict__ rsp, const int* __restrict__ c2,
                            const int* __restrict__ cl, const int* __restrict__ ql,
                            const int* __restrict__ rl, const int* __restrict__ c2l)
{
    int idx = blockIdx.x*blockDim.x + threadIdx.x;
    if (idx >= MT) return;
    int b = idx / SL, p = idx % SL;
    int l0 = cl[b], l1 = c2l[b], l2 = ql[b], l3 = rl[b];
    int tok = -1;
    if (p < l0)               tok = ctx[b*S_C + p];
    else if (p < l0+l1)       tok = c2 [b*S_C2 + (p-l0)];
    else if (p < l0+l1+l2)    tok = qry[b*S_Q + (p-l0-l1)];
    else if (p < l0+l1+l2+l3) tok = rsp[b*S_R + (p-l0-l1-l2)];
    g_tok[idx] = tok;
}

__global__ void k_gather(const float* __restrict__ wte)
{
    int idx = blockIdx.x*blockDim.x + threadIdx.x;
    if (idx >= MT*(DM/4)) return;
    int row = idx / (DM/4), c4 = idx % (DM/4);
    int tok = g_tok[row];
    float4 v = make_float4(0.f,0.f,0.f,0.f);
    if (tok >= 0) v = ((const float4*)(wte + (size_t)tok*DM))[c4];
    float vv[4] = {v.x, v.y, v.z, v.w};
    size_t o = (size_t)row*DM + c4*4;
    #pragma unroll
    for (int t=0;t<4;t++){
        bf16 h = __float2bfloat16(vv[t]);
        g_xh[o+t] = h;
        g_xl[o+t] = __float2bfloat16(vv[t] - __bfloat162float(h));
    }
}

__global__ void k_cvt_f16(const float* __restrict__ in, __half* __restrict__ o,
                          int nin, int ntot)
{
    int i = blockIdx.x*blockDim.x + threadIdx.x;
    if (i >= ntot) return;
    float v = (i < nin) ? in[i] : 0.f;
    o[i] = __float2half(v);
}

__global__ void k_cvt(const float* __restrict__ in, bf16* __restrict__ oh,
                      bf16* __restrict__ ol, int nin, int ntot)
{
    int i = blockIdx.x*blockDim.x + threadIdx.x;
    if (i >= ntot) return;
    float v = (i < nin) ? in[i] : 0.f;
    bf16 h = __float2bfloat16(v);
    oh[i] = h;
    ol[i] = __float2bfloat16(v - __bfloat162float(h));
}

// fused transpose+fp16 conversion for all 8 layer weight matrices.
// Cumulative tile offsets (fixed segment scan):
//   layer0: qkv[0,1728) wo[1728,2304) wfc[2304,4608) wpr[4608,6912)
//   layer1: qkv[6912,8640) wo[8640,9216) wfc[9216,11520) wpr[11520,13824)
__global__ void k_cvtT_all(const float* __restrict__ wqkv, const float* __restrict__ wo,
                           const float* __restrict__ wfc,  const float* __restrict__ wpr)
{
    __shared__ float t[32][33];
    const int off[9] = {0,1728,2304,4608,6912,8640,9216,11520,13824};
    int bid = blockIdx.x;
    int s = 0;
    #pragma unroll
    for (int i = 1; i < 8; i++)
        if (bid >= off[i]) s = i;
    int start = off[s];
    int l = s >> 2, m = s & 3;
    int Kd, Nd;
    const float* src;
    __half* dst;
    if (m == 0)      { Kd = DM;  Nd = 3*DM; src = wqkv + (size_t)l*DM*3*DM; dst = g_qw16 + (size_t)l*3*DM*DM; }
    else if (m == 1) { Kd = DM;  Nd = DM;   src = wo   + (size_t)l*DM*DM;   dst = g_ow16 + (size_t)l*DM*DM; }
    else if (m == 2) { Kd = DM;  Nd = FF;   src = wfc  + (size_t)l*DM*FF;   dst = g_fw16 + (size_t)l*FF*DM; }
    else             { Kd = FF;  Nd = DM;   src = wpr  + (size_t)l*FF*DM;   dst = g_pw16 + (size_t)l*DM*FF; }
    int tloc = bid - start;
    int tilesX = Nd >> 5;
    int nb = (tloc % tilesX) * 32;
    int kb = (tloc / tilesX) * 32;
    int tx = threadIdx.x, ty = threadIdx.y;
    #pragma unroll
    for (int i=0;i<32;i+=8)
        t[ty+i][tx] = src[(size_t)(kb+ty+i)*Nd + nb+tx];
    __syncthreads();
    #pragma unroll
    for (int i=0;i<32;i+=8)
        dst[(size_t)(nb+ty+i)*Kd + kb+tx] = __float2half(t[tx][ty+i]);
}

// LayerNorm fp32 -> fp16
__global__ void __launch_bounds__(256)
k_ln_f16(const float* __restrict__ in, const float* __restrict__ gm,
         const float* __restrict__ bt, __half* __restrict__ o16)
{
    __shared__ float red[256];
    int row = blockIdx.x, tid = threadIdx.x;
    const float* x = in + (size_t)row*DM;
    float v0 = x[tid], v1 = x[tid+256], v2 = x[tid+512];
    red[tid] = v0+v1+v2; __syncthreads();
    for (int o=128;o>0;o>>=1){ if(tid<o) red[tid]+=red[tid+o]; __syncthreads(); }
    float mean = red[0] * (1.f/768.f); __syncthreads();
    float d0=v0-mean, d1=v1-mean, d2=v2-mean;
    red[tid] = d0*d0+d1*d1+d2*d2; __syncthreads();
    for (int o=128;o>0;o>>=1){ if(tid<o) red[tid]+=red[tid+o]; __syncthreads(); }
    float inv = rsqrtf(red[0]*(1.f/768.f) + 1e-5f);
    #pragma unroll
    for (int t=0;t<3;t++){
        int c = tid + t*256;
        float d = (t==0)?d0:((t==1)?d1:d2);
        o16[(size_t)row*DM + c] = __float2half(d*inv*gm[c] + bt[c]);
    }
}

// ---------------- fused flash attention --------------------------------------
__global__ void __launch_bounds__(256,1)
k_flash(const int* __restrict__ cl, const int* __restrict__ c2l,
        const int* __restrict__ ql, const int* __restrict__ rl)
{
    __shared__ __align__(128) unsigned char smem_buf[49152];
    uint32_t sb = smem_u32(smem_buf);
    int tid = threadIdx.x, w = tid>>5, lane = tid&31;
    int bh = blockIdx.y, b = bh / NH, hh = bh % NH;
    int q0 = blockIdx.x * 128;
    int total = cl[b] + c2l[b] + ql[b] + rl[b];

    const __half* Qb = g_q16 + (size_t)bh*SL*64;
    const __half* Kb = g_k16 + (size_t)bh*SL*64;
    const __half* Vb = g_vt  + (size_t)bh*64*SL;

    for (int u = tid; u < 1024; u += 256) {
        int r = u>>3, c = u&7;
        cpa16(sb + r*128 + ((c^(r&7))*16), Qb + (size_t)(q0+r)*64 + c*8);
    }
    for (int u = tid; u < 512; u += 256) {
        int r = u>>3, c = u&7;
        uint32_t d = r*128 + ((c^(r&7))*16);
        cpa16(sb + 16384 + d,        Kb + (size_t)r*64 + c*8);
        cpa16(sb + 16384 + 8192 + d, Vb + (size_t)r*SL + c*8);
    }
    CP_COMMIT();
    CP_WAIT(0);
    __syncthreads();

    int rr = lane & 15, hf = lane >> 4;

    uint32_t qf[4][4];
    #pragma unroll
    for (int ks=0; ks<4; ks++) {
        int r = w*16 + rr;
        int ch = ks*2 + hf;
        LDSM4(qf[ks][0],qf[ks][1],qf[ks][2],qf[ks][3], sb + r*128 + ((ch^(r&7))*16));
    }

    float Oacc[8][4];
    #pragma unroll
    for (int nd=0;nd<8;nd++)
        #pragma unroll
        for (int j=0;j<4;j++) Oacc[nd][j]=0.f;
    float mrow[2] = {-1e30f,-1e30f}, lrow[2] = {0.f,0.f};
    int qi0 = q0 + w*16 + (lane>>2);

    int nk = q0/64 + 2;
    int nkt = (total + 63) >> 6;
    if (nkt < nk) nk = nkt;

    for (int i = 0; i < nk; i++) {
        uint32_t st = sb + 16384 + (i&1)*16384;
        if (i+1 < nk) {
            uint32_t st2 = sb + 16384 + ((i+1)&1)*16384;
            int k0n = (i+1)*64;
            for (int u = tid; u < 512; u += 256) {
                int r = u>>3, c = u&7;
                uint32_t d = r*128 + ((c^(r&7))*16);
                cpa16(st2 + d,        Kb + (size_t)(k0n+r)*64 + c*8);
                cpa16(st2 + 8192 + d, Vb + (size_t)r*SL + k0n + c*8);
            }
            CP_COMMIT();
            CP_WAIT(1);
        } else {
            CP_WAIT(0);
        }
        __syncthreads();

        int k0 = i*64;
        float Sacc[8][4];
        #pragma unroll
        for (int n8=0;n8<8;n8++)
            #pragma unroll
            for (int j=0;j<4;j++) Sacc[n8][j]=0.f;
        #pragma unroll
        for (int ks=0; ks<4; ks++) {
            uint32_t bf[4][4];
            int ch = ks*2 + hf;
            #pragma unroll
            for (int nt=0; nt<4; nt++) {
                int r = nt*16 + rr;
                LDSM4(bf[nt][0],bf[nt][1],bf[nt][2],bf[nt][3], st + r*128 + ((ch^(r&7))*16));
            }
            #pragma unroll
            for (int nt=0; nt<4; nt++) {
                MMA16816H(Sacc[nt*2+0], qf[ks], bf[nt][0], bf[nt][2]);
                MMA16816H(Sacc[nt*2+1], qf[ks], bf[nt][1], bf[nt][3]);
            }
        }
        #pragma unroll
        for (int n8=0;n8<8;n8++)
            #pragma unroll
            for (int j=0;j<4;j++) {
                int kk = k0 + n8*8 + (lane&3)*2 + (j&1);
                int qi = qi0 + (j>>1)*8;
                float v = Sacc[n8][j]*0.125f;
                Sacc[n8][j] = (kk<=qi && kk<total) ? v : -1e30f;
            }
        float cm[2] = {-1e30f,-1e30f};
        #pragma unroll
        for (int n8=0;n8<8;n8++) {
            cm[0] = fmaxf(cm[0], fmaxf(Sacc[n8][0], Sacc[n8][1]));
            cm[1] = fmaxf(cm[1], fmaxf(Sacc[n8][2], Sacc[n8][3]));
        }
        #pragma unroll
        for (int o=1;o<4;o<<=1) {
            cm[0] = fmaxf(cm[0], __shfl_xor_sync(0xffffffffu, cm[0], o));
            cm[1] = fmaxf(cm[1], __shfl_xor_sync(0xffffffffu, cm[1], o));
        }
        float mnew[2], corr[2];
        #pragma unroll
        for (int h=0;h<2;h++) {
            mnew[h] = fmaxf(mrow[h], cm[h]);
            corr[h] = __expf(mrow[h] - mnew[h]);
        }
        float ls[2] = {0.f,0.f};
        #pragma unroll
        for (int n8=0;n8<8;n8++)
            #pragma unroll
            for (int j=0;j<4;j++) {
                float p = __expf(Sacc[n8][j] - mnew[j>>1]);
                Sacc[n8][j] = p;
                ls[j>>1] += p;
            }
        #pragma unroll
        for (int o=1;o<4;o<<=1) {
            ls[0] += __shfl_xor_sync(0xffffffffu, ls[0], o);
            ls[1] += __shfl_xor_sync(0xffffffffu, ls[1], o);
        }
        #pragma unroll
        for (int h=0;h<2;h++) {
            lrow[h] = lrow[h]*corr[h] + ls[h];
            mrow[h] = mnew[h];
        }
        #pragma unroll
        for (int nd=0;nd<8;nd++) {
            Oacc[nd][0] *= corr[0]; Oacc[nd][1] *= corr[0];
            Oacc[nd][2] *= corr[1]; Oacc[nd][3] *= corr[1];
        }
        #pragma unroll
        for (int kf=0; kf<4; kf++) {
            uint32_t ph[4];
            ph[0] = pack_h2(Sacc[2*kf  ][0], Sacc[2*kf  ][1]);
            ph[1] = pack_h2(Sacc[2*kf  ][2], Sacc[2*kf  ][3]);
            ph[2] = pack_h2(Sacc[2*kf+1][0], Sacc[2*kf+1][1]);
            ph[3] = pack_h2(Sacc[2*kf+1][2], Sacc[2*kf+1][3]);
            uint32_t bv[4][4];
            int ch = kf*2 + hf;
            #pragma unroll
            for (int nt=0; nt<4; nt++) {
                int r = nt*16 + rr;
                LDSM4(bv[nt][0],bv[nt][1],bv[nt][2],bv[nt][3], st + 8192 + r*128 + ((ch^(r&7))*16));
            }
            #pragma unroll
            for (int nt=0; nt<4; nt++) {
                MMA16816H(Oacc[nt*2+0], ph, bv[nt][0], bv[nt][2]);
                MMA16816H(Oacc[nt*2+1], ph, bv[nt][1], bv[nt][3]);
            }
        }
        __syncthreads();
    }

    float inv0 = 1.f/lrow[0], inv1 = 1.f/lrow[1];
    #pragma unroll
    for (int nd=0; nd<8; nd++)
        #pragma unroll
        for (int h=0; h<2; h++) {
            int s = qi0 + h*8;
            int d = nd*8 + (lane&3)*2;
            float inv = h ? inv1 : inv0;
            size_t o = (size_t)(b*SL + s)*DM + hh*64 + d;
            *(__half2*)(g_a16 + o) =
                __floats2half2_rn(Oacc[nd][h*2+0]*inv, Oacc[nd][h*2+1]*inv);
        }
}

// ---------------- split-bf16 GEMM (ll only) ----------------------------------
#define KC 64
#define AB (128*128)

template<int BN>
__global__ void __launch_bounds__(256,1)
k_tgemm(const bf16* __restrict__ aH, const bf16* __restrict__ aL,
        const bf16* __restrict__ bH, const bf16* __restrict__ bL,
        const float* __restrict__ bias, const float* __restrict__ wpe,
        float* __restrict__ C, int K, int Nvalid, int flags)
{
    constexpr int WN  = BN/4;
    constexpr int NT  = WN/16;
    constexpr int N8  = WN/8;
    constexpr int BB  = BN*128;
    constexpr int STG = 2*AB + 2*BB;

    extern __shared__ __align__(128) unsigned char smem_buf[];
    uint32_t sb = smem_u32(smem_buf);
    int tid = threadIdx.x;
    int bm = blockIdx.x * 128;
    int bn = blockIdx.y * BN;

    int w = tid >> 5, lane = tid & 31;
    int wm = w >> 2, wn = w & 3;

    float acc[4][N8][4];
    #pragma unroll
    for (int mt=0;mt<4;mt++)
        #pragma unroll
        for (int n8=0;n8<N8;n8++)
            #pragma unroll
            for (int r=0;r<4;r++) acc[mt][n8][r]=0.f;

    int nk = K / KC;

    auto load_stage = [&](int stage, int k0){
        uint32_t st = sb + stage*STG;
        #pragma unroll 4
        for (int u = tid; u < 128*8; u += 256) {
            int r = u >> 3, c = u & 7;
            uint32_t d = r*128 + ((c ^ (r&7))*16);
            size_t g = (size_t)(bm+r)*K + k0 + c*8;
            cpa16(st + d,      aH + g);
            cpa16(st + AB + d, aL + g);
        }
        #pragma unroll 4
        for (int u = tid; u < BN*8; u += 256) {
            int r = u >> 3, c = u & 7;
            uint32_t d = r*128 + ((c ^ (r&7))*16);
            size_t g = (size_t)(bn+r)*K + k0 + c*8;
            cpa16(st + 2*AB + d,      bH + g);
            cpa16(st + 2*AB + BB + d, bL + g);
        }
        CP_COMMIT();
    };

    load_stage(0, 0);

    int rr = lane & 15, hf = lane >> 4;
    for (int i = 0; i < nk; i++) {
        uint32_t st = sb + (i & 1)*STG;
        if (i + 1 < nk) { load_stage((i+1)&1, (i+1)*KC); CP_WAIT(1); }
        else            { CP_WAIT(0); }
        __syncthreads();

        #pragma unroll
        for (int ks = 0; ks < 4; ks++) {
            uint32_t ah[4][4], al[4][4], bh[NT][4], bl[NT][4];
            int ch = ks*2 + hf;
            #pragma unroll
            for (int mt=0;mt<4;mt++) {
                int r = wm*64 + mt*16 + rr;
                uint32_t ra = st + r*128 + ((ch ^ (r&7))*16);
                LDSM4(ah[mt][0],ah[mt][1],ah[mt][2],ah[mt][3], ra);
                LDSM4(al[mt][0],al[mt][1],al[mt][2],al[mt][3], ra + AB);
            }
            #pragma unroll
            for (int nt=0;nt<NT;nt++) {
                int r = wn*WN + nt*16 + rr;
                uint32_t rb = st + 2*AB + r*128 + ((ch ^ (r&7))*16);
                LDSM4(bh[nt][0],bh[nt][1],bh[nt][2],bh[nt][3], rb);
                LDSM4(bl[nt][0],bl[nt][1],bl[nt][2],bl[nt][3], rb + BB);
            }
            #pragma unroll
            for (int mt=0;mt<4;mt++) {
                #pragma unroll
                for (int n8=0;n8<N8;n8++) {
                    int nt = n8 >> 1, p = n8 & 1;
                    MMA16816(acc[mt][n8], ah[mt], bh[nt][p], bh[nt][p+2]);
                    MMA16816(acc[mt][n8], ah[mt], bl[nt][p], bl[nt][p+2]);
                    MMA16816(acc[mt][n8], al[mt], bh[nt][p], bh[nt][p+2]);
                }
            }
        }
        __syncthreads();
    }

    int r0b = bm + wm*64 + (lane >> 2);
    int c0b = bn + wn*WN + (lane & 3)*2;
    #pragma unroll
    for (int mt=0;mt<4;mt++) {
        #pragma unroll
        for (int n8=0;n8<N8;n8++) {
            #pragma unroll
            for (int half=0; half<2; half++) {
                int r = r0b + mt*16 + half*8;
                int c = c0b + n8*8;
                float v0 = acc[mt][n8][half*2+0];
                float v1 = acc[mt][n8][half*2+1];
                if (bias) { v0 += bias[c]; v1 += bias[c+1]; }
                if (flags & GF_WPE) {
                    const float* wp = wpe + (size_t)(r & (SL-1))*DM + c;
                    v0 += wp[0]; v1 += wp[1];
                }
                size_t o = (size_t)r*Nvalid + c;
                if (flags & GF_RESID) {
                    float2 old = *(float2*)(C + o);
                    old.x += v0; old.y += v1;
                    *(float2*)(C + o) = old;
                } else {
                    C[o] = v0; C[o+1] = v1;
                }
            }
        }
    }
}

#define SMEM128 (2*(2*AB + 2*128*128))   /* 131072 */

// ---------------- fp16 single-pass GEMM, 512 threads -------------------------
// 16 warps in 4x4; warp tile 32 x (BN/4). 3-stage cp.async pipeline.
template<int BN>
__global__ void __launch_bounds__(512,1)
k_hgemm(const __half* __restrict__ Af, const __half* __restrict__ Bf,
        const float* __restrict__ bias,
        float* __restrict__ C, __half* __restrict__ C16,
        int K, int Nvalid, int flags)
{
    constexpr int WN = BN/4;
    constexpr int NT = WN/16;
    constexpr int N8 = WN/8;
    constexpr int HA = 16384;
    constexpr int HB = BN*128;
    constexpr int ST = HA+HB;

    extern __shared__ __align__(128) unsigned char smem_buf[];
    uint32_t sb = smem_u32(smem_buf);
    int tid = threadIdx.x;
    int bm = blockIdx.x * 128;
    int bn = blockIdx.y * BN;

    int w = tid >> 5, lane = tid & 31;
    int wm = w >> 2, wn = w & 3;        // 4 x 4 warp grid; warp rows = wm*32

    float acc[2][N8][4];
    #pragma unroll
    for (int mt=0;mt<2;mt++)
        #pragma unroll
        for (int n8=0;n8<N8;n8++)
            #pragma unroll
            for (int r=0;r<4;r++) acc[mt][n8][r]=0.f;

    int nk = K / KC;

    auto load_stage = [&](int stage, int k0){
        uint32_t st = sb + stage*ST;
        #pragma unroll 2
        for (int u = tid; u < 128*8; u += 512) {
            int r = u >> 3, c = u & 7;
            uint32_t d = r*128 + ((c ^ (r&7))*16);
            cpa16(st + d, Af + (size_t)(bm+r)*K + k0 + c*8);
        }
        #pragma unroll 4
        for (int u = tid; u < BN*8; u += 512) {
            int r = u >> 3, c = u & 7;
            uint32_t d = r*128 + ((c ^ (r&7))*16);
            cpa16(st + HA + d, Bf + (size_t)(bn+r)*K + k0 + c*8);
        }
        CP_COMMIT();
    };

    load_stage(0, 0);
    if (nk > 1) load_stage(1, KC);

    int rr = lane & 15, hf = lane >> 4;
    int stage = 0;
    for (int i = 0; i < nk; i++) {
        if (i + 2 < nk) { load_stage((stage+2)%3, (i+2)*KC); CP_WAIT(2); }
        else if (i + 1 < nk) { CP_WAIT(1); }
        else { CP_WAIT(0); }
        __syncthreads();

        uint32_t st = sb + stage*ST;
        #pragma unroll
        for (int ks = 0; ks < 4; ks++) {
            uint32_t ah[2][4], bh[NT][4];
            int ch = ks*2 + hf;
            #pragma unroll
            for (int mt=0;mt<2;mt++) {
                int r = wm*32 + mt*16 + rr;
                LDSM4(ah[mt][0],ah[mt][1],ah[mt][2],ah[mt][3], st + r*128 + ((ch ^ (r&7))*16));
            }
            #pragma unroll
            for (int nt=0;nt<NT;nt++) {
                int r = wn*WN + nt*16 + rr;
                LDSM4(bh[nt][0],bh[nt][1],bh[nt][2],bh[nt][3], st + HA + r*128 + ((ch ^ (r&7))*16));
            }
            #pragma unroll
            for (int mt=0;mt<2;mt++) {
                #pragma unroll
                for (int n8=0;n8<N8;n8++) {
                    int nt = n8 >> 1, p = n8 & 1;
                    MMA16816H(acc[mt][n8], ah[mt], bh[nt][p], bh[nt][p+2]);
                }
            }
        }
        __syncthreads();
        stage = (stage + 1) % 3;
    }

    int r0b = bm + wm*32 + (lane >> 2);
    int c0b = bn + wn*WN + (lane & 3)*2;
    #pragma unroll
    for (int mt=0;mt<2;mt++) {
        #pragma unroll
        for (int n8=0;n8<N8;n8++) {
            #pragma unroll
            for (int half=0; half<2; half++) {
                int r = r0b + mt*16 + half*8;
                int c = c0b + n8*8;
                float v0 = acc[mt][n8][half*2+0];
                float v1 = acc[mt][n8][half*2+1];
                if (bias) { v0 += bias[c]; v1 += bias[c+1]; }
                if (flags & GF_QKV) {
                    int sec = c / DM;
                    int cc = c - sec*DM;
                    int hh = cc >> 6, d = cc & 63;
                    int bb2 = r >> 10, s = r & (SL-1);
                    if (sec < 2) {
                        __half* dst = (sec == 0 ? g_q16 : g_k16)
                                      + (((size_t)(bb2*NH + hh)*SL + s) << 6) + d;
                        *(__half2*)dst = __floats2half2_rn(v0, v1);
                    } else {
                        __half* dst = g_vt + ((size_t)(bb2*NH + hh)*64 + d)*SL + s;
                        dst[0]  = __float2half(v0);
                        dst[SL] = __float2half(v1);
                    }
                    continue;
                }
                if (flags & GF_GELU) {
                    float u0=v0, u1=v1;
                    v0 = 0.5f*u0*(1.f + tanhf(0.7978845608028654f*(u0 + 0.044715f*u0*u0*u0)));
                    v1 = 0.5f*u1*(1.f + tanhf(0.7978845608028654f*(u1 + 0.044715f*u1*u1*u1)));
                    *(__half2*)(C16 + (size_t)r*Nvalid + c) = __floats2half2_rn(v0, v1);
                    continue;
                }
                size_t o = (size_t)r*Nvalid + c;
                if (flags & GF_RESID) {
                    float2 old = *(float2*)(C + o);
                    old.x += v0; old.y += v1;
                    *(float2*)(C + o) = old;
                } else {
                    if (c < Nvalid)   C[o]   = v0;
                    if (c+1 < Nvalid) C[o+1] = v1;
                }
            }
        }
    }
}

#define SMEMH256 (3*(16384 + 256*128))   /* 147456 */
#define SMEMH128 (3*(16384 + 128*128))   /* 98304 */

// ---------------- launch ----------------------------------------------------
extern "C" void kernel_launch(void* const* d_in, const int* in_sizes, int n_in,
                              void* d_out, int out_size)
{
    const int*   ctx  = (const int*)  d_in[0];
    const int*   qry  = (const int*)  d_in[1];
    const int*   rsp  = (const int*)  d_in[2];
    const int*   c2   = (const int*)  d_in[3];
    const int*   cl   = (const int*)  d_in[4];
    const int*   ql   = (const int*)  d_in[5];
    const int*   rl   = (const int*)  d_in[6];
    const int*   c2l  = (const int*)  d_in[7];
    const float* wte  = (const float*)d_in[8];
    const float* wpe  = (const float*)d_in[9];
    const float* ln1g = (const float*)d_in[10];
    const float* ln1b = (const float*)d_in[11];
    const float* wqkv = (const float*)d_in[12];
    const float* bqkv = (const float*)d_in[13];
    const float* wo   = (const float*)d_in[14];
    const float* bo   = (const float*)d_in[15];
    const float* ln2g = (const float*)d_in[16];
    const float* ln2b = (const float*)d_in[17];
    const float* wfc  = (const float*)d_in[18];
    const float* bfc  = (const float*)d_in[19];
    const float* wpr  = (const float*)d_in[20];
    const float* bpr  = (const float*)d_in[21];
    const float* lnfg = (const float*)d_in[22];
    const float* lnfb = (const float*)d_in[23];
    const float* llw  = (const float*)d_in[24];
    const float* llb  = (const float*)d_in[25];
    float* out = (float*)d_out;

    cudaFuncSetAttribute(k_tgemm<128>, cudaFuncAttributeMaxDynamicSharedMemorySize, SMEM128);
    cudaFuncSetAttribute(k_hgemm<256>, cudaFuncAttributeMaxDynamicSharedMemorySize, SMEMH256);
    cudaFuncSetAttribute(k_hgemm<128>, cudaFuncAttributeMaxDynamicSharedMemorySize, SMEMH128);

    float *ph;
    bf16 *xh, *xl, *lwh, *lwl;
    __half *x16, *a16, *f16b, *wtf, *qw16, *ow16, *fw16, *pw16;
    cudaGetSymbolAddress((void**)&ph,   g_h);
    cudaGetSymbolAddress((void**)&xh,   g_xh);   cudaGetSymbolAddress((void**)&xl,   g_xl);
    cudaGetSymbolAddress((void**)&lwh,  g_lwh);  cudaGetSymbolAddress((void**)&lwl,  g_lwl);
    cudaGetSymbolAddress((void**)&x16,  g_x16);  cudaGetSymbolAddress((void**)&a16,  g_a16);
    cudaGetSymbolAddress((void**)&f16b, g_f16);  cudaGetSymbolAddress((void**)&wtf,  g_wtf);
    cudaGetSymbolAddress((void**)&qw16, g_qw16); cudaGetSymbolAddress((void**)&ow16, g_ow16);
    cudaGetSymbolAddress((void**)&fw16, g_fw16); cudaGetSymbolAddress((void**)&pw16, g_pw16);

    // ---- weight conversions (fused) ----
    k_cvt_f16<<<(NVP*DM+255)/256, 256>>>(wte, wtf, NVOC*DM, NVP*DM);
    k_cvt<<<(DM*DM+255)/256, 256>>>(llw, lwh, lwl, DM*DM, DM*DM);
    k_cvtT_all<<<13824, dim3(32,8)>>>(wqkv, wo, wfc, wpr);

    // ---- embeddings ----
    k_build_tok<<<(MT+255)/256, 256>>>(ctx, qry, rsp, c2, cl, ql, rl, c2l);
    k_gather<<<(MT*(DM/4)+255)/256, 256>>>(wte);

    // h = emb @ ll_w^T + ll_b + wpe  (bf16x3)
    k_tgemm<128><<<dim3(MT/128, DM/128), 256, SMEM128>>>(xh, xl, lwh, lwl, llb, wpe,
                                                         ph, DM, DM, GF_WPE);

    for (int l = 0; l < NLAY; l++) {
        k_ln_f16<<<MT, 256>>>(ph, ln1g + l*DM, ln1b + l*DM, x16);
        k_hgemm<256><<<dim3(MT/128, 3*DM/256), 512, SMEMH256>>>(x16,
            qw16 + (size_t)l*3*DM*DM, bqkv + l*3*DM,
            nullptr, nullptr, DM, 3*DM, GF_QKV);
        k_flash<<<dim3(SL/128, BATCH*NH), 256>>>(cl, c2l, ql, rl);
        k_hgemm<128><<<dim3(MT/128, DM/128), 512, SMEMH128>>>(a16,
            ow16 + (size_t)l*DM*DM, bo + l*DM,
            ph, nullptr, DM, DM, GF_RESID);
        k_ln_f16<<<MT, 256>>>(ph, ln2g + l*DM, ln2b + l*DM, x16);
        k_hgemm<256><<<dim3(MT/128, FF/256), 512, SMEMH256>>>(x16,
            fw16 + (size_t)l*FF*DM, bfc + l*FF,
            nullptr, f16b, DM, FF, GF_GELU);
        k_hgemm<128><<<dim3(MT/128, DM/128), 512, SMEMH128>>>(f16b,
            pw16 + (size_t)l*DM*FF, bpr + l*DM,
            ph, nullptr, FF, DM, GF_RESID);
    }

    k_ln_f16<<<MT, 256>>>(ph, lnfg, lnfb, x16);

    // logits = x @ wte^T (fp16 single-pass)
    k_hgemm<256><<<dim3(MT/128, NVP/256), 512, SMEMH256>>>(x16, wtf, nullptr,
                                                           out, nullptr, DM, NVOC, 0);
}